// round 3
// baseline (speedup 1.0000x reference)
#include <cuda_runtime.h>
#include <math.h>

#define B_SZ 32
#define C_SZ 64
#define T_SZ 8192
#define NSPLIT 8
#define TSEG (T_SZ / NSPLIT)   // 1024

// ---------------- scratch (static device globals; no allocation) ----------------
__device__ float2 g_Z[(size_t)B_SZ * C_SZ * T_SZ];                    // 128 MB phasors
__device__ float  g_Gpart[(size_t)NSPLIT * B_SZ * 10 * 256 * 2];      // tri-tile partials
__device__ float2 g_tw[T_SZ / 2];                                     // exp(-2pi i k/N)

__constant__ int c_TI[10] = {0,0,0,0,1,1,1,2,2,3};
__constant__ int c_TJ[10] = {0,1,2,3,1,2,3,2,3,3};

typedef unsigned long long ull;
union F2U { float2 f; ull u; };

__device__ __forceinline__ ull pack2(float lo, float hi) {
    F2U r; r.f = make_float2(lo, hi); return r.u;
}
__device__ __forceinline__ float2 cmul(float2 a, float2 b) {
    return make_float2(a.x * b.x - a.y * b.y, a.x * b.y + a.y * b.x);
}
__device__ __forceinline__ float2 cadd(float2 a, float2 b) {
    F2U A, Bv, R; A.f = a; Bv.f = b;
    asm("add.rn.f32x2 %0, %1, %2;" : "=l"(R.u) : "l"(A.u), "l"(Bv.u));
    return R.f;
}
__device__ __forceinline__ float2 csub(float2 a, float2 b) {
    F2U A, Bv, R; A.f = a; Bv.f = b;
    asm("sub.rn.f32x2 %0, %1, %2;" : "=l"(R.u) : "l"(A.u), "l"(Bv.u));
    return R.f;
}
__device__ __forceinline__ void fma2(ull& acc, ull a, ull b) {
    asm("fma.rn.f32x2 %0, %1, %2, %0;" : "+l"(acc) : "l"(a), "l"(b));
}

// ---------------- twiddle init ----------------
__global__ void twiddle_init_kernel() {
    int i = blockIdx.x * blockDim.x + threadIdx.x;
    if (i < T_SZ / 2) {
        double ang = -2.0 * 3.14159265358979323846 * (double)i / (double)T_SZ;
        g_tw[i] = make_float2((float)cos(ang), (float)sin(ang));
    }
}

// ---------------- FFT -> Hilbert -> IFFT -> normalize (2 stages / round trip) ---
__global__ __launch_bounds__(512) void fft_hilbert_kernel(const float* __restrict__ x) {
    extern __shared__ float2 s[];   // 64 KB
    const int row = blockIdx.x;
    const float* xr = x + (size_t)row * T_SZ;
    const int tid = threadIdx.x;

    // fused: load x + forward stage pair (st=0,1)
    #pragma unroll
    for (int rr = 0; rr < 4; rr++) {
        int g = tid + rr * 512;
        float u0 = xr[g], u1 = xr[g + 2048], u2 = xr[g + 4096], u3 = xr[g + 6144];
        float2 w1 = g_tw[g];
        float2 w2 = g_tw[2 * g];
        float ap = u0 + u2, cd = u0 - u2;
        float bp = u1 + u3, dd = u1 - u3;
        float2 cp = make_float2(cd * w1.x, cd * w1.y);
        float2 dp = make_float2(dd * w1.y, -dd * w1.x);
        s[g]        = make_float2(ap + bp, 0.f);
        s[g + 2048] = make_float2((ap - bp) * w2.x, (ap - bp) * w2.y);
        s[g + 4096] = cadd(cp, dp);
        s[g + 6144] = cmul(csub(cp, dp), w2);
    }
    __syncthreads();

    // forward stage pairs st = 2,4,6,8,10
    #pragma unroll
    for (int st = 2; st < 12; st += 2) {
        const int shift = 12 - st;
        const int h = 1 << shift, h2 = h >> 1;
        #pragma unroll
        for (int rr = 0; rr < 4; rr++) {
            int g = tid + rr * 512;
            int j = g & (h2 - 1);
            int i = ((g >> (shift - 1)) << (shift + 1)) + j;
            int m = j << st;
            float2 u0 = s[i], u1 = s[i + h2], u2 = s[i + h], u3 = s[i + h + h2];
            float2 w1 = g_tw[m];
            float2 w2 = g_tw[2 * m];
            float2 ap = cadd(u0, u2);
            float2 cp = cmul(csub(u0, u2), w1);
            float2 bp = cadd(u1, u3);
            float2 w1b = make_float2(w1.y, -w1.x);
            float2 dp = cmul(csub(u1, u3), w1b);
            s[i]          = cadd(ap, bp);
            s[i + h2]     = cmul(csub(ap, bp), w2);
            s[i + h]      = cadd(cp, dp);
            s[i + h + h2] = cmul(csub(cp, dp), w2);
        }
        __syncthreads();
    }

    // fused: final forward stage + Hilbert mask (bit-reversed domain)
    #pragma unroll
    for (int rr = 0; rr < 8; rr++) {
        int t = tid + rr * 512;
        float2 u = s[2 * t], v = s[2 * t + 1];
        float2 a = cadd(u, v), d = csub(u, v);
        if (t == 0) { s[0] = a; s[1] = d; }
        else {
            s[2 * t]     = make_float2(2.f * a.x, 2.f * a.y);
            s[2 * t + 1] = make_float2(0.f, 0.f);
        }
    }
    __syncthreads();

    // inverse stage pairs st = 0,2,4,6,8,10 (conjugate twiddles)
    #pragma unroll
    for (int st = 0; st < 12; st += 2) {
        const int g1 = 1 << st;
        #pragma unroll
        for (int rr = 0; rr < 4; rr++) {
            int q = tid + rr * 512;
            int j = q & (g1 - 1);
            int i = ((q >> st) << (st + 2)) + j;
            int m = j << (12 - st);
            float2 tm = g_tw[m];
            float2 w  = make_float2(tm.x, -tm.y);
            float2 t2 = g_tw[m >> 1];
            float2 w2 = make_float2(t2.x, -t2.y);
            float2 w2b = make_float2(-w2.y, w2.x);
            float2 u0 = s[i], u1 = s[i + g1], u2 = s[i + 2 * g1], u3 = s[i + 3 * g1];
            float2 v1 = cmul(u1, w), v3 = cmul(u3, w);
            float2 p0 = cadd(u0, v1), p1 = csub(u0, v1);
            float2 p2 = cadd(u2, v3), p3 = csub(u2, v3);
            float2 q2 = cmul(p2, w2), q3 = cmul(p3, w2b);
            s[i]           = cadd(p0, q2);
            s[i + 2 * g1]  = csub(p0, q2);
            s[i + g1]      = cadd(p1, q3);
            s[i + 3 * g1]  = csub(p1, q3);
        }
        __syncthreads();
    }

    // fused: final inverse stage + normalize + store
    float2* Zr = g_Z + (size_t)row * T_SZ;
    #pragma unroll
    for (int rr = 0; rr < 8; rr++) {
        int t = tid + rr * 512;
        float2 tm = g_tw[t];
        float2 w = make_float2(tm.x, -tm.y);
        float2 u = s[t];
        float2 v = cmul(s[t + 4096], w);
        float2 z0 = cadd(u, v), z1 = csub(u, v);
        float i0 = rsqrtf(z0.x * z0.x + z0.y * z0.y);
        float i1 = rsqrtf(z1.x * z1.x + z1.y * z1.y);
        Zr[t]        = make_float2(z0.x * i0, z0.y * i0);
        Zr[t + 4096] = make_float2(z1.x * i1, z1.y * i1);
    }
}

// ---------------- PLV gram partials via packed f32x2 FMAs -----------------------
// 10 upper-triangular 16x16 tiles, grid (10, NSPLIT, B). 256 threads =
// 32 spatial (8 r2 x 4 c2; thread tile rows {r2, r2+8}, cols 4c2..4c2+3)
// x 8 t-groups. Smem planes: Ap=(re,im), Aq=(im,-re), Bx=(re,re), By=(im,im);
// each complex MAC = 2 x fma.rn.f32x2.
#define GTC 64
__global__ __launch_bounds__(256) void gram_kernel() {
    __shared__ ull gsm[4][16][GTC + 1];   // Ap, Aq, Bx, By (4160 ull = 33.3 KB)
    const int z = blockIdx.x, split = blockIdx.y, b = blockIdx.z;
    const int ti = c_TI[z], tj = c_TJ[z];
    const int tid = threadIdx.x;
    const int sid = tid & 31, grp = tid >> 5;     // 8 t-groups
    const int r2 = sid >> 2, c2 = sid & 3;

    ull acc[2][4] = {};   // (re,im) packed, rows {r2, r2+8} x cols 4c2+cc

    const float2* ZA = g_Z + ((size_t)b * C_SZ + ti * 16) * T_SZ;
    const float2* ZB = g_Z + ((size_t)b * C_SZ + tj * 16) * T_SZ;
    const int tstart = split * TSEG;

    for (int ch = 0; ch < TSEG / GTC; ch++) {
        const int tb = tstart + ch * GTC;
        #pragma unroll
        for (int k = 0; k < 4; k++) {
            int idx = tid + k * 256;               // 0..1023
            int rw = idx >> 6, t = idx & 63;
            float2 a = ZA[(size_t)rw * T_SZ + tb + t];
            gsm[0][rw][t] = pack2(a.x, a.y);
            gsm[1][rw][t] = pack2(a.y, -a.x);
            float2 bb = ZB[(size_t)rw * T_SZ + tb + t];
            gsm[2][rw][t] = pack2(bb.x, bb.x);
            gsm[3][rw][t] = pack2(bb.y, bb.y);
        }
        __syncthreads();
        const int t0 = grp * 8;
        #pragma unroll
        for (int tt = 0; tt < 8; tt++) {
            int t = t0 + tt;
            ull pa0 = gsm[0][r2][t],     qa0 = gsm[1][r2][t];
            ull pa1 = gsm[0][r2 + 8][t], qa1 = gsm[1][r2 + 8][t];
            #pragma unroll
            for (int cc = 0; cc < 4; cc++) {
                ull bx = gsm[2][4 * c2 + cc][t];
                ull by = gsm[3][4 * c2 + cc][t];
                fma2(acc[0][cc], pa0, bx); fma2(acc[0][cc], qa0, by);
                fma2(acc[1][cc], pa1, bx); fma2(acc[1][cc], qa1, by);
            }
        }
        __syncthreads();
    }

    // reduce 8 t-groups through smem (reuse gsm: need 2048 ull)
    ull* red = &gsm[0][0][0];
    #pragma unroll
    for (int j = 0; j < 8; j++) red[tid * 8 + j] = acc[j >> 2][j & 3];
    __syncthreads();
    if (tid < 32) {
        float* Gp = g_Gpart + (((size_t)(split * B_SZ + b)) * 10 + z) * 512;
        #pragma unroll
        for (int j = 0; j < 8; j++) {
            float re = 0.f, im = 0.f;
            #pragma unroll
            for (int g = 0; g < 8; g++) {
                F2U v; v.u = red[(g * 32 + sid) * 8 + j];
                re += v.f.x; im += v.f.y;
            }
            int R = (j >> 2) ? (r2 + 8) : r2;
            int C = 4 * c2 + (j & 3);
            Gp[(R * 16 + C) * 2]     = re;
            Gp[(R * 16 + C) * 2 + 1] = im;
        }
    }
}

// ---------------- tail: conn finalize + GCN + MHA. One block/batch, 1024 thr ----
#define OFF_EE   4160                 // s_conn [64][65]
#define OFF_F1   8320                 // s_EE   [64][65]
#define OFF_H1   16768                // s_F1   [64][132]
#define OFF_T2   25216                // s_h1   [64][132]
#define OFF_H2   29568                // s_t2   [64][68]
#define OFF_Q    33728                // s_h2   [64][65]
#define OFF_K    38080                // s_q    [64][68]
#define OFF_V    42432                // s_k    [64][68]
#define TAIL_FLOATS 46784             // s_v    [64][68]  -> 187136 B

__global__ __launch_bounds__(1024) void tail_kernel(
    const float* __restrict__ EE,  const float* __restrict__ w1, const float* __restrict__ b1,
    const float* __restrict__ w2,  const float* __restrict__ b2,
    const float* __restrict__ Wip, const float* __restrict__ bip,
    const float* __restrict__ Wop, const float* __restrict__ bop,
    float* __restrict__ out)
{
    extern __shared__ float sm[];
    float* s_conn = sm;
    float* s_EE  = sm + OFF_EE;
    float* s_F1  = sm + OFF_F1;
    float* s_h1  = sm + OFF_H1;
    float* s_t2  = sm + OFF_T2;
    float* s_h2  = sm + OFF_H2;     // stride 65 (scalar reads in qkv)
    float* s_q   = sm + OFF_Q;
    float* s_k   = sm + OFF_K;
    float* s_v   = sm + OFF_V;
    float* s_WT  = s_F1;            // WipT [64][192], after F1/h1 dead
    float* s_WT2 = s_t2;            // WopT [64][64],  after t2 dead
    float* s_ao  = s_conn;          // conn dead after h2
    const int b = blockIdx.x;
    const int tid = threadIdx.x;

    // EE -> smem
    #pragma unroll
    for (int i = tid; i < 4096; i += 1024)
        s_EE[(i >> 6) * 65 + (i & 63)] = EE[i];

    // connectivity: reduce splits, Hermitian fill, |.|/T, zero diag; output #1
    #pragma unroll
    for (int i = tid; i < 4096; i += 1024) {
        int r = i >> 6, c = i & 63;
        int bi = r >> 4, bj = c >> 4, rr = r & 15, cc = c & 15;
        int ii = bi, jj = bj, o1 = rr, o2 = cc;
        if (bi > bj) { ii = bj; jj = bi; o1 = cc; o2 = rr; }
        int til = 4 * ii - ((ii * (ii - 1)) >> 1) + (jj - ii);
        int off = (til * 256 + o1 * 16 + o2);
        float re = 0.f, im = 0.f;
        #pragma unroll
        for (int sp = 0; sp < 8; sp++) {
            const float2* Gp = (const float2*)(g_Gpart + ((size_t)(sp * B_SZ + b)) * (10 * 512));
            float2 v = Gp[off];
            re += v.x; im += v.y;
        }
        float v = (r == c) ? 0.f : sqrtf(re * re + im * im) * (1.f / (float)T_SZ);
        s_conn[r * 65 + c] = v;
        out[(size_t)b * 4096 + i] = v;
    }
    __syncthreads();

    // F1 = EE @ w1   (64x128 as 64x32 float4 slots)
    const float4* w1v = (const float4*)w1;
    const float4* b1v = (const float4*)b1;
    #pragma unroll
    for (int it = 0; it < 2; it++) {
        int slot = tid + it * 1024;
        int r = slot >> 5, f4 = slot & 31;
        float4 acc = make_float4(0.f, 0.f, 0.f, 0.f);
        #pragma unroll 8
        for (int e = 0; e < 64; e++) {
            float4 w = w1v[e * 32 + f4];
            float sc = s_EE[r * 65 + e];
            acc.x += sc * w.x; acc.y += sc * w.y; acc.z += sc * w.z; acc.w += sc * w.w;
        }
        ((float4*)&s_F1[r * 132])[f4] = acc;
    }
    __syncthreads();

    // h1 = relu(conn @ F1 + b1)
    #pragma unroll
    for (int it = 0; it < 2; it++) {
        int slot = tid + it * 1024;
        int r = slot >> 5, f4 = slot & 31;
        float4 acc = b1v[f4];
        #pragma unroll 8
        for (int j = 0; j < 64; j++) {
            float4 fv = ((const float4*)&s_F1[j * 132])[f4];
            float cn = s_conn[r * 65 + j];
            acc.x += cn * fv.x; acc.y += cn * fv.y; acc.z += cn * fv.z; acc.w += cn * fv.w;
        }
        acc.x = fmaxf(acc.x, 0.f); acc.y = fmaxf(acc.y, 0.f);
        acc.z = fmaxf(acc.z, 0.f); acc.w = fmaxf(acc.w, 0.f);
        ((float4*)&s_h1[r * 132])[f4] = acc;
    }
    __syncthreads();

    // t2 = h1 @ w2   (64x16 float4 slots)
    {
        const float4* w2v = (const float4*)w2;
        int r = tid >> 4, e4 = tid & 15;
        float4 acc = make_float4(0.f, 0.f, 0.f, 0.f);
        #pragma unroll 8
        for (int f = 0; f < 128; f++) {
            float4 w = w2v[f * 16 + e4];
            float h = s_h1[r * 132 + f];
            acc.x += h * w.x; acc.y += h * w.y; acc.z += h * w.z; acc.w += h * w.w;
        }
        ((float4*)&s_t2[r * 68])[e4] = acc;
    }
    __syncthreads();

    // h2 = conn @ t2 + b2 ; output #3
    {
        const float4* b2v = (const float4*)b2;
        int r = tid >> 4, e4 = tid & 15;
        float4 acc = b2v[e4];
        #pragma unroll 8
        for (int j = 0; j < 64; j++) {
            float4 t4 = ((const float4*)&s_t2[j * 68])[e4];
            float cn = s_conn[r * 65 + j];
            acc.x += cn * t4.x; acc.y += cn * t4.y; acc.z += cn * t4.z; acc.w += cn * t4.w;
        }
        s_h2[r * 65 + 4 * e4]     = acc.x;
        s_h2[r * 65 + 4 * e4 + 1] = acc.y;
        s_h2[r * 65 + 4 * e4 + 2] = acc.z;
        s_h2[r * 65 + 4 * e4 + 3] = acc.w;
        ((float4*)(out + (size_t)(2 * B_SZ * 4096) + (size_t)b * 4096 + r * 64))[e4] = acc;
    }
    __syncthreads();

    // transposes: WipT[e][m] (F1/h1 region), WopT[f][e] (t2 region)
    #pragma unroll
    for (int i = tid; i < 192 * 64; i += 1024) {
        int m = i >> 6, e = i & 63;
        s_WT[e * 192 + m] = Wip[i];
    }
    #pragma unroll
    for (int i = tid; i < 4096; i += 1024) {
        int eo = i >> 6, f = i & 63;
        s_WT2[f * 64 + eo] = Wop[i];
    }
    __syncthreads();

    // qkv = h2 @ WipT + bip   (48 m4-slots x 64 n)
    {
        const float4* bipv = (const float4*)bip;
        #pragma unroll
        for (int it = 0; it < 3; it++) {
            int slot = tid + it * 1024;
            int n = slot & 63, m4 = slot >> 6;    // m4 in [0,48)
            float4 acc = bipv[m4];
            #pragma unroll 8
            for (int e = 0; e < 64; e++) {
                float4 w = ((const float4*)&s_WT[e * 192])[m4];
                float h = s_h2[n * 65 + e];
                acc.x += h * w.x; acc.y += h * w.y; acc.z += h * w.z; acc.w += h * w.w;
            }
            float* dst = (m4 < 16) ? s_q : (m4 < 32 ? s_k : s_v);
            int c4 = m4 & 15;
            ((float4*)&dst[n * 68])[c4] = acc;
        }
    }
    __syncthreads();

    // attention: 512 tasks = (head, row); two-pass softmax with __expf
    if (tid < 512) {
        int h = tid >> 6, qi = tid & 63;
        const float inv_sqrt_d = 0.35355339059327373f;
        float qv[8];
        #pragma unroll
        for (int d = 0; d < 8; d++) qv[d] = s_q[qi * 68 + h * 8 + d];
        float mx = -1e30f;
        for (int k = 0; k < 64; k++) {
            float sc = 0.f;
            #pragma unroll
            for (int d = 0; d < 8; d++) sc += qv[d] * s_k[k * 68 + h * 8 + d];
            mx = fmaxf(mx, sc * inv_sqrt_d);
        }
        float denom = 0.f, acc[8] = {};
        for (int k = 0; k < 64; k++) {
            float sc = 0.f;
            #pragma unroll
            for (int d = 0; d < 8; d++) sc += qv[d] * s_k[k * 68 + h * 8 + d];
            float p = __expf(sc * inv_sqrt_d - mx);
            denom += p;
            #pragma unroll
            for (int d = 0; d < 8; d++) acc[d] += p * s_v[k * 68 + h * 8 + d];
        }
        float rinv = 1.f / denom;
        __syncthreads();               // all conn reads complete; safe to overwrite
        #pragma unroll
        for (int d = 0; d < 8; d++) s_ao[qi * 65 + h * 8 + d] = acc[d] * rinv;
    } else {
        __syncthreads();
    }
    __syncthreads();

    // graph_features = ao @ WopT + bop ; output #2
    {
        const float4* bopv = (const float4*)bop;
        int n = tid >> 4, e4 = tid & 15;
        float4 acc = bopv[e4];
        #pragma unroll 8
        for (int f = 0; f < 64; f++) {
            float4 w = ((const float4*)&s_WT2[f * 64])[e4];
            float av = s_ao[n * 65 + f];
            acc.x += av * w.x; acc.y += av * w.y; acc.z += av * w.z; acc.w += av * w.w;
        }
        ((float4*)(out + (size_t)(B_SZ * 4096) + (size_t)b * 4096 + n * 64))[e4] = acc;
    }
}

// ---------------- launch ----------------
extern "C" void kernel_launch(void* const* d_in, const int* in_sizes, int n_in,
                              void* d_out, int out_size) {
    const float* x   = (const float*)d_in[0];
    const float* EE  = (const float*)d_in[1];
    const float* w1  = (const float*)d_in[2];
    const float* b1  = (const float*)d_in[3];
    const float* w2  = (const float*)d_in[4];
    const float* b2  = (const float*)d_in[5];
    const float* Wip = (const float*)d_in[6];
    const float* bip = (const float*)d_in[7];
    const float* Wop = (const float*)d_in[8];
    const float* bop = (const float*)d_in[9];
    float* out = (float*)d_out;

    cudaFuncSetAttribute(fft_hilbert_kernel,
                         cudaFuncAttributeMaxDynamicSharedMemorySize, 65536);
    cudaFuncSetAttribute(tail_kernel,
                         cudaFuncAttributeMaxDynamicSharedMemorySize, TAIL_FLOATS * 4);

    twiddle_init_kernel<<<16, 256>>>();
    fft_hilbert_kernel<<<B_SZ * C_SZ, 512, 65536>>>(x);
    gram_kernel<<<dim3(10, NSPLIT, B_SZ), 256>>>();
    tail_kernel<<<B_SZ, 1024, TAIL_FLOATS * 4>>>(EE, w1, b1, w2, b2,
                                                 Wip, bip, Wop, bop, out);
}

// round 4
// speedup vs baseline: 1.1042x; 1.1042x over previous
#include <cuda_runtime.h>
#include <math.h>

#define B_SZ 32
#define C_SZ 64
#define T_SZ 8192
#define NSPLIT 8
#define TSEG (T_SZ / NSPLIT)   // 1024

// ---------------- scratch (static device globals; no allocation) ----------------
__device__ float2 g_Z[(size_t)B_SZ * C_SZ * T_SZ];                    // 128 MB phasors
__device__ float  g_Gpart[(size_t)NSPLIT * B_SZ * 10 * 256 * 2];      // tri-tile partials
__device__ float2 g_tw[T_SZ / 2];                                     // exp(-2pi i k/N)

__constant__ int c_TI[10] = {0,0,0,0,1,1,1,2,2,3};
__constant__ int c_TJ[10] = {0,1,2,3,1,2,3,2,3,3};

__device__ __forceinline__ float2 cmul(float2 a, float2 b) {
    return make_float2(a.x * b.x - a.y * b.y, a.x * b.y + a.y * b.x);
}
__device__ __forceinline__ float2 cadd(float2 a, float2 b) { return make_float2(a.x + b.x, a.y + b.y); }
__device__ __forceinline__ float2 csub(float2 a, float2 b) { return make_float2(a.x - b.x, a.y - b.y); }

// XOR bank swizzle on logical float2 index: bijective, spreads stride-32-word
// access patterns across banks. s[] is only ever addressed through SW().
__device__ __forceinline__ int SW(int i) { return i ^ ((i >> 5) & 31); }

// ---------------- twiddle init ----------------
__global__ void twiddle_init_kernel() {
    int i = blockIdx.x * blockDim.x + threadIdx.x;
    if (i < T_SZ / 2) {
        double ang = -2.0 * 3.14159265358979323846 * (double)i / (double)T_SZ;
        g_tw[i] = make_float2((float)cos(ang), (float)sin(ang));
    }
}

// ---------------- FFT -> Hilbert -> IFFT -> normalize (2 stages / round trip) ---
// Radix-2 DIF forward (natural -> bit-reversed), Hilbert in bit-reversed domain
// (p==0:1, p==1:1, even:2, odd:0), radix-2 DIT inverse. 1/N scale cancels in z/|z|.
__global__ __launch_bounds__(512) void fft_hilbert_kernel(const float* __restrict__ x) {
    extern __shared__ float2 s[];   // 64 KB
    const int row = blockIdx.x;
    const float* xr = x + (size_t)row * T_SZ;
    const int tid = threadIdx.x;

    // fused: load x + forward stage pair (st=0,1)
    #pragma unroll
    for (int rr = 0; rr < 4; rr++) {
        int g = tid + rr * 512;
        float u0 = xr[g], u1 = xr[g + 2048], u2 = xr[g + 4096], u3 = xr[g + 6144];
        float2 w1 = g_tw[g];
        float2 w2 = g_tw[2 * g];
        float ap = u0 + u2, cd = u0 - u2;
        float bp = u1 + u3, dd = u1 - u3;
        float2 cp = make_float2(cd * w1.x, cd * w1.y);
        float2 dp = make_float2(dd * w1.y, -dd * w1.x);
        s[SW(g)]        = make_float2(ap + bp, 0.f);
        s[SW(g + 2048)] = make_float2((ap - bp) * w2.x, (ap - bp) * w2.y);
        s[SW(g + 4096)] = cadd(cp, dp);
        s[SW(g + 6144)] = cmul(csub(cp, dp), w2);
    }
    __syncthreads();

    // forward stage pairs st = 2,4,6,8,10
    #pragma unroll
    for (int st = 2; st < 12; st += 2) {
        const int shift = 12 - st;
        const int h = 1 << shift, h2 = h >> 1;
        #pragma unroll
        for (int rr = 0; rr < 4; rr++) {
            int g = tid + rr * 512;
            int j = g & (h2 - 1);
            int i = ((g >> (shift - 1)) << (shift + 1)) + j;
            int m = j << st;
            float2 u0 = s[SW(i)], u1 = s[SW(i + h2)];
            float2 u2 = s[SW(i + h)], u3 = s[SW(i + h + h2)];
            float2 w1 = g_tw[m];
            float2 w2 = g_tw[2 * m];
            float2 ap = cadd(u0, u2);
            float2 cp = cmul(csub(u0, u2), w1);
            float2 bp = cadd(u1, u3);
            float2 w1b = make_float2(w1.y, -w1.x);
            float2 dp = cmul(csub(u1, u3), w1b);
            s[SW(i)]          = cadd(ap, bp);
            s[SW(i + h2)]     = cmul(csub(ap, bp), w2);
            s[SW(i + h)]      = cadd(cp, dp);
            s[SW(i + h + h2)] = cmul(csub(cp, dp), w2);
        }
        __syncthreads();
    }

    // fused: final forward stage + Hilbert mask (bit-reversed domain)
    #pragma unroll
    for (int rr = 0; rr < 8; rr++) {
        int t = tid + rr * 512;
        int i0 = SW(2 * t), i1 = SW(2 * t + 1);
        float2 u = s[i0], v = s[i1];
        float2 a = cadd(u, v), d = csub(u, v);
        if (t == 0) { s[i0] = a; s[i1] = d; }
        else {
            s[i0] = make_float2(2.f * a.x, 2.f * a.y);
            s[i1] = make_float2(0.f, 0.f);
        }
    }
    __syncthreads();

    // inverse stage pairs st = 0,2,4,6,8,10 (conjugate twiddles)
    #pragma unroll
    for (int st = 0; st < 12; st += 2) {
        const int g1 = 1 << st;
        #pragma unroll
        for (int rr = 0; rr < 4; rr++) {
            int q = tid + rr * 512;
            int j = q & (g1 - 1);
            int i = ((q >> st) << (st + 2)) + j;
            int m = j << (12 - st);
            float2 tm = g_tw[m];
            float2 w  = make_float2(tm.x, -tm.y);
            float2 t2 = g_tw[m >> 1];
            float2 w2 = make_float2(t2.x, -t2.y);
            float2 w2b = make_float2(-w2.y, w2.x);
            float2 u0 = s[SW(i)], u1 = s[SW(i + g1)];
            float2 u2 = s[SW(i + 2 * g1)], u3 = s[SW(i + 3 * g1)];
            float2 v1 = cmul(u1, w), v3 = cmul(u3, w);
            float2 p0 = cadd(u0, v1), p1 = csub(u0, v1);
            float2 p2 = cadd(u2, v3), p3 = csub(u2, v3);
            float2 q2 = cmul(p2, w2), q3 = cmul(p3, w2b);
            s[SW(i)]          = cadd(p0, q2);
            s[SW(i + 2 * g1)] = csub(p0, q2);
            s[SW(i + g1)]     = cadd(p1, q3);
            s[SW(i + 3 * g1)] = csub(p1, q3);
        }
        __syncthreads();
    }

    // fused: final inverse stage + normalize + store
    float2* Zr = g_Z + (size_t)row * T_SZ;
    #pragma unroll
    for (int rr = 0; rr < 8; rr++) {
        int t = tid + rr * 512;
        float2 tm = g_tw[t];
        float2 w = make_float2(tm.x, -tm.y);
        float2 u = s[SW(t)];
        float2 v = cmul(s[SW(t + 4096)], w);
        float2 z0 = cadd(u, v), z1 = csub(u, v);
        float i0 = rsqrtf(z0.x * z0.x + z0.y * z0.y);
        float i1 = rsqrtf(z1.x * z1.x + z1.y * z1.y);
        Zr[t]        = make_float2(z0.x * i0, z0.y * i0);
        Zr[t + 4096] = make_float2(z1.x * i1, z1.y * i1);
    }
}

// ---------------- PLV gram partials, Hermitian: 10 upper 16x16 tiles ------------
// grid (10, NSPLIT, B). 256 threads = 4 t-groups x 64; 64-group computes the
// 16x16 tile with 2x2 complex register blocks; groups reduced in smem at the end.
__global__ __launch_bounds__(256) void gram_kernel() {
    __shared__ float2 As[16][129];
    __shared__ float2 Bs[16][129];
    const int z = blockIdx.x, split = blockIdx.y, b = blockIdx.z;
    const int ti = c_TI[z], tj = c_TJ[z];
    const int tid = threadIdx.x;
    const int grp = tid >> 6;
    const int sid = tid & 63;
    const int r2 = sid >> 3, c2 = sid & 7;

    float ar00 = 0, ar01 = 0, ar10 = 0, ar11 = 0;
    float ai00 = 0, ai01 = 0, ai10 = 0, ai11 = 0;

    const float2* ZA = g_Z + ((size_t)b * C_SZ + ti * 16) * T_SZ;
    const float2* ZB = g_Z + ((size_t)b * C_SZ + tj * 16) * T_SZ;
    const int tstart = split * TSEG;

    for (int ch = 0; ch < 8; ch++) {
        const int tb = tstart + ch * 128;
        #pragma unroll
        for (int l = tid; l < 2048; l += 256) {
            int rw = l >> 7, t = l & 127;
            As[rw][t] = ZA[(size_t)rw * T_SZ + tb + t];
            Bs[rw][t] = ZB[(size_t)rw * T_SZ + tb + t];
        }
        __syncthreads();
        const int t0 = grp * 32;
        #pragma unroll 8
        for (int t = 0; t < 32; t++) {
            float2 a0 = As[2 * r2][t0 + t],  a1 = As[2 * r2 + 1][t0 + t];
            float2 b0 = Bs[2 * c2][t0 + t],  b1 = Bs[2 * c2 + 1][t0 + t];
            ar00 += a0.x * b0.x + a0.y * b0.y;  ai00 += a0.y * b0.x - a0.x * b0.y;
            ar01 += a0.x * b1.x + a0.y * b1.y;  ai01 += a0.y * b1.x - a0.x * b1.y;
            ar10 += a1.x * b0.x + a1.y * b0.y;  ai10 += a1.y * b0.x - a1.x * b0.y;
            ar11 += a1.x * b1.x + a1.y * b1.y;  ai11 += a1.y * b1.x - a1.x * b1.y;
        }
        __syncthreads();
    }

    // reduce the 4 t-groups via smem (reuse As)
    float* red = (float*)As;
    float* my = red + (sid * 4 + grp) * 8;
    my[0] = ar00; my[1] = ai00; my[2] = ar01; my[3] = ai01;
    my[4] = ar10; my[5] = ai10; my[6] = ar11; my[7] = ai11;
    __syncthreads();
    if (grp == 0) {
        float v[8];
        #pragma unroll
        for (int k = 0; k < 8; k++)
            v[k] = red[(sid * 4 + 0) * 8 + k] + red[(sid * 4 + 1) * 8 + k]
                 + red[(sid * 4 + 2) * 8 + k] + red[(sid * 4 + 3) * 8 + k];
        float* Gp = g_Gpart + (((size_t)(split * B_SZ + b)) * 10 + z) * 512;
        #pragma unroll
        for (int rr = 0; rr < 2; rr++)
            #pragma unroll
            for (int cc = 0; cc < 2; cc++) {
                int R = 2 * r2 + rr, C = 2 * c2 + cc;
                Gp[(R * 16 + C) * 2]     = v[(rr * 2 + cc) * 2];
                Gp[(R * 16 + C) * 2 + 1] = v[(rr * 2 + cc) * 2 + 1];
            }
    }
}

// ---------------- tail: conn finalize + GCN + MHA. One block/batch, 1024 thr ----
#define OFF_EE   4160                 // s_conn [64][65]
#define OFF_F1   8320                 // s_EE   [64][65]
#define OFF_H1   16768                // s_F1   [64][132]
#define OFF_T2   25216                // s_h1   [64][132]
#define OFF_H2   29568                // s_t2   [64][68]
#define OFF_Q    33728                // s_h2   [64][65]
#define OFF_K    38080                // s_q    [64][68]
#define OFF_V    42432                // s_k    [64][68]
#define TAIL_FLOATS 46784             // s_v    [64][68]  -> 187136 B

__global__ __launch_bounds__(1024) void tail_kernel(
    const float* __restrict__ EE,  const float* __restrict__ w1, const float* __restrict__ b1,
    const float* __restrict__ w2,  const float* __restrict__ b2,
    const float* __restrict__ Wip, const float* __restrict__ bip,
    const float* __restrict__ Wop, const float* __restrict__ bop,
    float* __restrict__ out)
{
    extern __shared__ float sm[];
    float* s_conn = sm;
    float* s_EE  = sm + OFF_EE;
    float* s_F1  = sm + OFF_F1;
    float* s_h1  = sm + OFF_H1;
    float* s_t2  = sm + OFF_T2;
    float* s_h2  = sm + OFF_H2;
    float* s_q   = sm + OFF_Q;
    float* s_k   = sm + OFF_K;
    float* s_v   = sm + OFF_V;
    float* s_WT  = s_F1;            // WipT [64][192], after F1/h1 dead
    float* s_WT2 = s_t2;            // WopT [64][64],  after t2 dead
    float* s_ao  = s_conn;          // conn dead after h2
    const int b = blockIdx.x;
    const int tid = threadIdx.x;

    #pragma unroll
    for (int i = tid; i < 4096; i += 1024)
        s_EE[(i >> 6) * 65 + (i & 63)] = EE[i];

    // connectivity: reduce splits, Hermitian fill, |.|/T, zero diag; output #1
    #pragma unroll
    for (int i = tid; i < 4096; i += 1024) {
        int r = i >> 6, c = i & 63;
        int bi = r >> 4, bj = c >> 4, rr = r & 15, cc = c & 15;
        int ii = bi, jj = bj, o1 = rr, o2 = cc;
        if (bi > bj) { ii = bj; jj = bi; o1 = cc; o2 = rr; }
        int til = 4 * ii - ((ii * (ii - 1)) >> 1) + (jj - ii);
        int off = (til * 256 + o1 * 16 + o2);
        float re = 0.f, im = 0.f;
        #pragma unroll
        for (int sp = 0; sp < 8; sp++) {
            const float2* Gp = (const float2*)(g_Gpart + ((size_t)(sp * B_SZ + b)) * (10 * 512));
            float2 v = Gp[off];
            re += v.x; im += v.y;
        }
        float v = (r == c) ? 0.f : sqrtf(re * re + im * im) * (1.f / (float)T_SZ);
        s_conn[r * 65 + c] = v;
        out[(size_t)b * 4096 + i] = v;
    }
    __syncthreads();

    // F1 = EE @ w1
    const float4* w1v = (const float4*)w1;
    const float4* b1v = (const float4*)b1;
    #pragma unroll
    for (int it = 0; it < 2; it++) {
        int slot = tid + it * 1024;
        int r = slot >> 5, f4 = slot & 31;
        float4 acc = make_float4(0.f, 0.f, 0.f, 0.f);
        #pragma unroll 8
        for (int e = 0; e < 64; e++) {
            float4 w = w1v[e * 32 + f4];
            float sc = s_EE[r * 65 + e];
            acc.x += sc * w.x; acc.y += sc * w.y; acc.z += sc * w.z; acc.w += sc * w.w;
        }
        ((float4*)&s_F1[r * 132])[f4] = acc;
    }
    __syncthreads();

    // h1 = relu(conn @ F1 + b1)
    #pragma unroll
    for (int it = 0; it < 2; it++) {
        int slot = tid + it * 1024;
        int r = slot >> 5, f4 = slot & 31;
        float4 acc = b1v[f4];
        #pragma unroll 8
        for (int j = 0; j < 64; j++) {
            float4 fv = ((const float4*)&s_F1[j * 132])[f4];
            float cn = s_conn[r * 65 + j];
            acc.x += cn * fv.x; acc.y += cn * fv.y; acc.z += cn * fv.z; acc.w += cn * fv.w;
        }
        acc.x = fmaxf(acc.x, 0.f); acc.y = fmaxf(acc.y, 0.f);
        acc.z = fmaxf(acc.z, 0.f); acc.w = fmaxf(acc.w, 0.f);
        ((float4*)&s_h1[r * 132])[f4] = acc;
    }
    __syncthreads();

    // t2 = h1 @ w2
    {
        const float4* w2v = (const float4*)w2;
        int r = tid >> 4, e4 = tid & 15;
        float4 acc = make_float4(0.f, 0.f, 0.f, 0.f);
        #pragma unroll 8
        for (int f = 0; f < 128; f++) {
            float4 w = w2v[f * 16 + e4];
            float h = s_h1[r * 132 + f];
            acc.x += h * w.x; acc.y += h * w.y; acc.z += h * w.z; acc.w += h * w.w;
        }
        ((float4*)&s_t2[r * 68])[e4] = acc;
    }
    __syncthreads();

    // h2 = conn @ t2 + b2 ; output #3
    {
        const float4* b2v = (const float4*)b2;
        int r = tid >> 4, e4 = tid & 15;
        float4 acc = b2v[e4];
        #pragma unroll 8
        for (int j = 0; j < 64; j++) {
            float4 t4 = ((const float4*)&s_t2[j * 68])[e4];
            float cn = s_conn[r * 65 + j];
            acc.x += cn * t4.x; acc.y += cn * t4.y; acc.z += cn * t4.z; acc.w += cn * t4.w;
        }
        s_h2[r * 65 + 4 * e4]     = acc.x;
        s_h2[r * 65 + 4 * e4 + 1] = acc.y;
        s_h2[r * 65 + 4 * e4 + 2] = acc.z;
        s_h2[r * 65 + 4 * e4 + 3] = acc.w;
        ((float4*)(out + (size_t)(2 * B_SZ * 4096) + (size_t)b * 4096 + r * 64))[e4] = acc;
    }
    __syncthreads();

    // transposes: WipT[e][m], WopT[f][e]
    #pragma unroll
    for (int i = tid; i < 192 * 64; i += 1024) {
        int m = i >> 6, e = i & 63;
        s_WT[e * 192 + m] = Wip[i];
    }
    #pragma unroll
    for (int i = tid; i < 4096; i += 1024) {
        int eo = i >> 6, f = i & 63;
        s_WT2[f * 64 + eo] = Wop[i];
    }
    __syncthreads();

    // qkv = h2 @ WipT + bip
    {
        const float4* bipv = (const float4*)bip;
        #pragma unroll
        for (int it = 0; it < 3; it++) {
            int slot = tid + it * 1024;
            int n = slot & 63, m4 = slot >> 6;
            float4 acc = bipv[m4];
            #pragma unroll 8
            for (int e = 0; e < 64; e++) {
                float4 w = ((const float4*)&s_WT[e * 192])[m4];
                float h = s_h2[n * 65 + e];
                acc.x += h * w.x; acc.y += h * w.y; acc.z += h * w.z; acc.w += h * w.w;
            }
            float* dst = (m4 < 16) ? s_q : (m4 < 32 ? s_k : s_v);
            int c4 = m4 & 15;
            ((float4*)&dst[n * 68])[c4] = acc;
        }
    }
    __syncthreads();

    // attention: 512 tasks = (head, row); two-pass softmax with __expf
    if (tid < 512) {
        int h = tid >> 6, qi = tid & 63;
        const float inv_sqrt_d = 0.35355339059327373f;
        float qv[8];
        #pragma unroll
        for (int d = 0; d < 8; d++) qv[d] = s_q[qi * 68 + h * 8 + d];
        float mx = -1e30f;
        for (int k = 0; k < 64; k++) {
            float sc = 0.f;
            #pragma unroll
            for (int d = 0; d < 8; d++) sc += qv[d] * s_k[k * 68 + h * 8 + d];
            mx = fmaxf(mx, sc * inv_sqrt_d);
        }
        float denom = 0.f, acc[8] = {};
        for (int k = 0; k < 64; k++) {
            float sc = 0.f;
            #pragma unroll
            for (int d = 0; d < 8; d++) sc += qv[d] * s_k[k * 68 + h * 8 + d];
            float p = __expf(sc * inv_sqrt_d - mx);
            denom += p;
            #pragma unroll
            for (int d = 0; d < 8; d++) acc[d] += p * s_v[k * 68 + h * 8 + d];
        }
        float rinv = 1.f / denom;
        __syncthreads();
        #pragma unroll
        for (int d = 0; d < 8; d++) s_ao[qi * 65 + h * 8 + d] = acc[d] * rinv;
    } else {
        __syncthreads();
    }
    __syncthreads();

    // graph_features = ao @ WopT + bop ; output #2
    {
        const float4* bopv = (const float4*)bop;
        int n = tid >> 4, e4 = tid & 15;
        float4 acc = bopv[e4];
        #pragma unroll 8
        for (int f = 0; f < 64; f++) {
            float4 w = ((const float4*)&s_WT2[f * 64])[e4];
            float av = s_ao[n * 65 + f];
            acc.x += av * w.x; acc.y += av * w.y; acc.z += av * w.z; acc.w += av * w.w;
        }
        ((float4*)(out + (size_t)(B_SZ * 4096) + (size_t)b * 4096 + n * 64))[e4] = acc;
    }
}

// ---------------- launch ----------------
extern "C" void kernel_launch(void* const* d_in, const int* in_sizes, int n_in,
                              void* d_out, int out_size) {
    const float* x   = (const float*)d_in[0];
    const float* EE  = (const float*)d_in[1];
    const float* w1  = (const float*)d_in[2];
    const float* b1  = (const float*)d_in[3];
    const float* w2  = (const float*)d_in[4];
    const float* b2  = (const float*)d_in[5];
    const float* Wip = (const float*)d_in[6];
    const float* bip = (const float*)d_in[7];
    const float* Wop = (const float*)d_in[8];
    const float* bop = (const float*)d_in[9];
    float* out = (float*)d_out;

    cudaFuncSetAttribute(fft_hilbert_kernel,
                         cudaFuncAttributeMaxDynamicSharedMemorySize, 65536);
    cudaFuncSetAttribute(tail_kernel,
                         cudaFuncAttributeMaxDynamicSharedMemorySize, TAIL_FLOATS * 4);

    twiddle_init_kernel<<<16, 256>>>();
    fft_hilbert_kernel<<<B_SZ * C_SZ, 512, 65536>>>(x);
    gram_kernel<<<dim3(10, NSPLIT, B_SZ), 256>>>();
    tail_kernel<<<B_SZ, 1024, TAIL_FLOATS * 4>>>(EE, w1, b1, w2, b2,
                                                 Wip, bip, Wop, bop, out);
}

// round 6
// speedup vs baseline: 1.4046x; 1.2720x over previous
#include <cuda_runtime.h>
#include <cuda_bf16.h>
#include <math.h>

#define B_SZ 32
#define C_SZ 64
#define T_SZ 8192
#define KSPLIT 8
#define NCH 32               // 64-bf16 k-chunks per CTA (16384/8 splits/64)
#define NSTG 4
#define STG_B 16384          // per stage: hi tile 8KB + lo tile 8KB
#define GRAM_SMEM (NSTG * STG_B)

// ---------------- scratch (static device globals; no allocation) ----------------
// bf16 hi/lo planes: [b][c 0..63][16384 bf16 = (re,im) x 8192]
__device__ uint4  g_Ahi[(size_t)B_SZ * 64 * 2048];        // 67 MB
__device__ uint4  g_Alo[(size_t)B_SZ * 64 * 2048];        // 67 MB
__device__ float  g_G2[(size_t)KSPLIT * B_SZ * 128 * 64]; // partials: rows 0-63 Re, 64-127 Im
__device__ float2 g_tw[T_SZ / 2];                         // exp(-2pi i k/N)

__device__ __forceinline__ float2 cmul(float2 a, float2 b) {
    return make_float2(a.x * b.x - a.y * b.y, a.x * b.y + a.y * b.x);
}
__device__ __forceinline__ float2 cadd(float2 a, float2 b) { return make_float2(a.x + b.x, a.y + b.y); }
__device__ __forceinline__ float2 csub(float2 a, float2 b) { return make_float2(a.x - b.x, a.y - b.y); }
__device__ __forceinline__ int SW(int i) { return i ^ ((i >> 5) & 31); }

__device__ __forceinline__ unsigned smem_u32(const void* p) {
    unsigned a;
    asm("{ .reg .u64 t; cvta.to.shared.u64 t, %1; cvt.u32.u64 %0, t; }" : "=r"(a) : "l"(p));
    return a;
}
__device__ __forceinline__ void cpasync16(unsigned dst, const void* src) {
    asm volatile("cp.async.cg.shared.global [%0], [%1], 16;" :: "r"(dst), "l"(src) : "memory");
}
__device__ __forceinline__ void ldsm4(unsigned& r0, unsigned& r1, unsigned& r2, unsigned& r3,
                                      unsigned addr) {
    asm volatile("ldmatrix.sync.aligned.m8n8.x4.shared.b16 {%0,%1,%2,%3}, [%4];"
                 : "=r"(r0), "=r"(r1), "=r"(r2), "=r"(r3) : "r"(addr));
}
__device__ __forceinline__ void mma16816(float* c, unsigned a0, unsigned a1, unsigned a2,
                                         unsigned a3, unsigned b0, unsigned b1) {
    asm volatile("mma.sync.aligned.m16n8k16.row.col.f32.bf16.bf16.f32 "
                 "{%0,%1,%2,%3}, {%4,%5,%6,%7}, {%8,%9}, {%0,%1,%2,%3};"
                 : "+f"(c[0]), "+f"(c[1]), "+f"(c[2]), "+f"(c[3])
                 : "r"(a0), "r"(a1), "r"(a2), "r"(a3), "r"(b0), "r"(b1));
}
// (re,im) -> (im,-re): swap 16-bit halves, negate new hi (bf16 sign = bit 15 of half)
__device__ __forceinline__ unsigned rot_neg(unsigned x) {
    return __byte_perm(x, x, 0x1032) ^ 0x80000000u;
}

// ---------------- twiddle init ----------------
__global__ void twiddle_init_kernel() {
    int i = blockIdx.x * blockDim.x + threadIdx.x;
    if (i < T_SZ / 2) {
        double ang = -2.0 * 3.14159265358979323846 * (double)i / (double)T_SZ;
        g_tw[i] = make_float2((float)cos(ang), (float)sin(ang));
    }
}

// ---------------- FFT -> Hilbert -> IFFT -> normalize -> bf16 hi/lo planes ------
__global__ __launch_bounds__(512) void fft_hilbert_kernel(const float* __restrict__ x) {
    extern __shared__ float2 s[];   // 64 KB
    const int row = blockIdx.x;
    const float* xr = x + (size_t)row * T_SZ;
    const int tid = threadIdx.x;

    // fused: load x + forward stage pair (st=0,1)
    #pragma unroll
    for (int rr = 0; rr < 4; rr++) {
        int g = tid + rr * 512;
        float u0 = xr[g], u1 = xr[g + 2048], u2 = xr[g + 4096], u3 = xr[g + 6144];
        float2 w1 = g_tw[g];
        float2 w2 = g_tw[2 * g];
        float ap = u0 + u2, cd = u0 - u2;
        float bp = u1 + u3, dd = u1 - u3;
        float2 cp = make_float2(cd * w1.x, cd * w1.y);
        float2 dp = make_float2(dd * w1.y, -dd * w1.x);
        s[SW(g)]        = make_float2(ap + bp, 0.f);
        s[SW(g + 2048)] = make_float2((ap - bp) * w2.x, (ap - bp) * w2.y);
        s[SW(g + 4096)] = cadd(cp, dp);
        s[SW(g + 6144)] = cmul(csub(cp, dp), w2);
    }
    __syncthreads();

    // forward stage pairs st = 2,4,6,8,10
    #pragma unroll
    for (int st = 2; st < 12; st += 2) {
        const int shift = 12 - st;
        const int h = 1 << shift, h2 = h >> 1;
        #pragma unroll
        for (int rr = 0; rr < 4; rr++) {
            int g = tid + rr * 512;
            int j = g & (h2 - 1);
            int i = ((g >> (shift - 1)) << (shift + 1)) + j;
            int m = j << st;
            float2 u0 = s[SW(i)], u1 = s[SW(i + h2)];
            float2 u2 = s[SW(i + h)], u3 = s[SW(i + h + h2)];
            float2 w1 = g_tw[m];
            float2 w2 = g_tw[2 * m];
            float2 ap = cadd(u0, u2);
            float2 cp = cmul(csub(u0, u2), w1);
            float2 bp = cadd(u1, u3);
            float2 w1b = make_float2(w1.y, -w1.x);
            float2 dp = cmul(csub(u1, u3), w1b);
            s[SW(i)]          = cadd(ap, bp);
            s[SW(i + h2)]     = cmul(csub(ap, bp), w2);
            s[SW(i + h)]      = cadd(cp, dp);
            s[SW(i + h + h2)] = cmul(csub(cp, dp), w2);
        }
        __syncthreads();
    }

    // fused: final forward stage + Hilbert mask (bit-reversed domain)
    #pragma unroll
    for (int rr = 0; rr < 8; rr++) {
        int t = tid + rr * 512;
        int i0 = SW(2 * t), i1 = SW(2 * t + 1);
        float2 u = s[i0], v = s[i1];
        float2 a = cadd(u, v), d = csub(u, v);
        if (t == 0) { s[i0] = a; s[i1] = d; }
        else {
            s[i0] = make_float2(2.f * a.x, 2.f * a.y);
            s[i1] = make_float2(0.f, 0.f);
        }
    }
    __syncthreads();

    // inverse stage pairs st = 0,2,4,6,8,10 (conjugate twiddles)
    #pragma unroll
    for (int st = 0; st < 12; st += 2) {
        const int g1 = 1 << st;
        #pragma unroll
        for (int rr = 0; rr < 4; rr++) {
            int q = tid + rr * 512;
            int j = q & (g1 - 1);
            int i = ((q >> st) << (st + 2)) + j;
            int m = j << (12 - st);
            float2 tm = g_tw[m];
            float2 w  = make_float2(tm.x, -tm.y);
            float2 t2 = g_tw[m >> 1];
            float2 w2 = make_float2(t2.x, -t2.y);
            float2 w2b = make_float2(-w2.y, w2.x);
            float2 u0 = s[SW(i)], u1 = s[SW(i + g1)];
            float2 u2 = s[SW(i + 2 * g1)], u3 = s[SW(i + 3 * g1)];
            float2 v1 = cmul(u1, w), v3 = cmul(u3, w);
            float2 p0 = cadd(u0, v1), p1 = csub(u0, v1);
            float2 p2 = cadd(u2, v3), p3 = csub(u2, v3);
            float2 q2 = cmul(p2, w2), q3 = cmul(p3, w2b);
            s[SW(i)]          = cadd(p0, q2);
            s[SW(i + 2 * g1)] = csub(p0, q2);
            s[SW(i + g1)]     = cadd(p1, q3);
            s[SW(i + 3 * g1)] = csub(p1, q3);
        }
        __syncthreads();
    }

    // fused: final inverse stage + normalize + bf16 hi/lo split stores
    __nv_bfloat162* Ahi = (__nv_bfloat162*)g_Ahi;
    __nv_bfloat162* Alo = (__nv_bfloat162*)g_Alo;
    const size_t base = (size_t)row * 8192;
    #pragma unroll
    for (int rr = 0; rr < 8; rr++) {
        int t = tid + rr * 512;
        float2 tm = g_tw[t];
        float2 w = make_float2(tm.x, -tm.y);
        float2 u = s[SW(t)];
        float2 v = cmul(s[SW(t + 4096)], w);
        float2 zz[2] = { cadd(u, v), csub(u, v) };
        int ti[2] = { t, t + 4096 };
        #pragma unroll
        for (int e = 0; e < 2; e++) {
            float2 z = zz[e];
            float inv = rsqrtf(z.x * z.x + z.y * z.y);
            float zr = z.x * inv, zi = z.y * inv;
            __nv_bfloat16 rh = __float2bfloat16(zr);
            __nv_bfloat16 ih = __float2bfloat16(zi);
            __nv_bfloat16 rl = __float2bfloat16(zr - __bfloat162float(rh));
            __nv_bfloat16 il = __float2bfloat16(zi - __bfloat162float(ih));
            __nv_bfloat162 h;  h.x = rh; h.y = ih;
            __nv_bfloat162 l;  l.x = rl; l.y = il;
            Ahi[base + ti[e]] = h;
            Alo[base + ti[e]] = l;
        }
    }
}

// ---------------- gram via mma.sync (HMMA): G = Z . Z^H per batch ----------------
// grid (KSPLIT, B), 256 thr = 8 warps. Warps 0-3: Re (rows 16w..16w+15 x 64 cols),
// warps 4-7: Im via derived A' = (im,-re). bf16 hi/lo 3-pass split. 4-stage
// cp.async pipeline over 32 chunks of 64 bf16 (k).
__global__ __launch_bounds__(256) void gram_mma_kernel() {
    extern __shared__ __align__(1024) char gsm[];
    const unsigned sbase = smem_u32(gsm);
    const int split = blockIdx.x, b = blockIdx.y;
    const int tid = threadIdx.x, lane = tid & 31, w = tid >> 5;
    const int mrow = 16 * (w & 3);
    const bool isIm = (w >= 4);

    const uint4* __restrict__ hi0 = g_Ahi + (size_t)b * 64 * 2048 + split * 256;
    const uint4* __restrict__ lo0 = g_Alo + (size_t)b * 64 * 2048 + split * 256;

    // cp.async slots: per plane 512 uint4, 2 per thread
    unsigned swo[2]; int gofs[2];
    #pragma unroll
    for (int v = 0; v < 2; v++) {
        int idx = v * 256 + tid;
        int rw = idx >> 3, seg = idx & 7;
        unsigned off = rw * 128 + seg * 16;
        swo[v] = off ^ ((off >> 3) & 0x70);
        gofs[v] = rw * 2048 + seg;
    }

    // ldmatrix lane addressing (16B-granular, SW128)
    const int lr = lane & 15, lcb = lane >> 4;
    unsigned a_off0 = (mrow + lr) * 128 + lcb * 16;
    unsigned a_sw = a_off0 ^ ((a_off0 >> 3) & 0x70) - (a_off0 & 0x70) + (a_off0 & 0x70);
    // (compute swizzle per use; XOR bits are constant across ks since ks*32 < 128)
    unsigned aX = ((a_off0 >> 3) & 0x70);
    unsigned b_off0[4], bX[4];
    #pragma unroll
    for (int q = 0; q < 4; q++) {
        b_off0[q] = (16 * q + lr) * 128 + lcb * 16;
        bX[q] = ((b_off0[q] >> 3) & 0x70);
    }

    float c[8][4] = {};

    // prologue: load chunks 0..2
    #pragma unroll
    for (int j = 0; j < 3; j++) {
        unsigned st = sbase + j * STG_B;
        #pragma unroll
        for (int v = 0; v < 2; v++) {
            cpasync16(st + swo[v],        hi0 + gofs[v] + j * 8);
            cpasync16(st + 8192 + swo[v], lo0 + gofs[v] + j * 8);
        }
        asm volatile("cp.async.commit_group;" ::: "memory");
    }

    for (int i = 0; i < NCH; i++) {
        int jn = i + 3;
        if (jn < NCH) {
            unsigned st = sbase + (jn % NSTG) * STG_B;
            #pragma unroll
            for (int v = 0; v < 2; v++) {
                cpasync16(st + swo[v],        hi0 + gofs[v] + jn * 8);
                cpasync16(st + 8192 + swo[v], lo0 + gofs[v] + jn * 8);
            }
            asm volatile("cp.async.commit_group;" ::: "memory");
            asm volatile("cp.async.wait_group 3;" ::: "memory");
        } else {
            asm volatile("cp.async.wait_group 0;" ::: "memory");
        }
        __syncthreads();

        const unsigned sb = sbase + (i % NSTG) * STG_B;
        #pragma unroll
        for (int ks = 0; ks < 4; ks++) {
            // A fragments (hi, lo) for this warp's 16 rows
            unsigned ah0, ah1, ah2, ah3, al0, al1, al2, al3;
            unsigned aa = sb + ((a_off0 + ks * 32) ^ aX);
            ldsm4(ah0, ah1, ah2, ah3, aa);
            ldsm4(al0, al1, al2, al3, aa + 8192);
            if (isIm) {
                ah0 = rot_neg(ah0); ah1 = rot_neg(ah1); ah2 = rot_neg(ah2); ah3 = rot_neg(ah3);
                al0 = rot_neg(al0); al1 = rot_neg(al1); al2 = rot_neg(al2); al3 = rot_neg(al3);
            }
            // B fragments for all 64 cols (8 n-tiles), hi and lo planes
            #pragma unroll
            for (int q = 0; q < 4; q++) {
                unsigned bh0, bh1, bh2, bh3, bl0, bl1, bl2, bl3;
                unsigned ba = sb + ((b_off0[q] + ks * 32) ^ bX[q]);
                ldsm4(bh0, bh1, bh2, bh3, ba);
                ldsm4(bl0, bl1, bl2, bl3, ba + 8192);
                // n-tile 2q   : b = {r0, r2};  n-tile 2q+1 : b = {r1, r3}
                mma16816(c[2 * q],     ah0, ah1, ah2, ah3, bh0, bh2);
                mma16816(c[2 * q],     ah0, ah1, ah2, ah3, bl0, bl2);
                mma16816(c[2 * q],     al0, al1, al2, al3, bh0, bh2);
                mma16816(c[2 * q + 1], ah0, ah1, ah2, ah3, bh1, bh3);
                mma16816(c[2 * q + 1], ah0, ah1, ah2, ah3, bl1, bl3);
                mma16816(c[2 * q + 1], al0, al1, al2, al3, bh1, bh3);
            }
        }
        __syncthreads();
    }

    // write fp32 partials: Re rows 0-63, Im rows 64-127
    float* G = g_G2 + ((size_t)(split * B_SZ + b)) * 8192;
    int rbase = (isIm ? 64 : 0) + mrow + (lane >> 2);
    #pragma unroll
    for (int j = 0; j < 8; j++) {
        int col = 8 * j + 2 * (lane & 3);
        G[rbase * 64 + col]           = c[j][0];
        G[rbase * 64 + col + 1]       = c[j][1];
        G[(rbase + 8) * 64 + col]     = c[j][2];
        G[(rbase + 8) * 64 + col + 1] = c[j][3];
    }
}

// ---------------- tail: conn finalize + GCN + MHA. One block/batch, 1024 thr ----
#define OFF_EE   4160
#define OFF_F1   8320
#define OFF_H1   16768
#define OFF_T2   25216
#define OFF_H2   29568
#define OFF_Q    33728
#define OFF_K    38080
#define OFF_V    42432
#define TAIL_FLOATS 46784

__global__ __launch_bounds__(1024) void tail_kernel(
    const float* __restrict__ EE,  const float* __restrict__ w1, const float* __restrict__ b1,
    const float* __restrict__ w2,  const float* __restrict__ b2,
    const float* __restrict__ Wip, const float* __restrict__ bip,
    const float* __restrict__ Wop, const float* __restrict__ bop,
    float* __restrict__ out)
{
    extern __shared__ float sm[];
    float* s_conn = sm;
    float* s_EE  = sm + OFF_EE;
    float* s_F1  = sm + OFF_F1;
    float* s_h1  = sm + OFF_H1;
    float* s_t2  = sm + OFF_T2;
    float* s_h2  = sm + OFF_H2;
    float* s_q   = sm + OFF_Q;
    float* s_k   = sm + OFF_K;
    float* s_v   = sm + OFF_V;
    float* s_WT  = s_F1;
    float* s_WT2 = s_t2;
    float* s_ao  = s_conn;
    const int b = blockIdx.x;
    const int tid = threadIdx.x;

    #pragma unroll
    for (int i = tid; i < 4096; i += 1024)
        s_EE[(i >> 6) * 65 + (i & 63)] = EE[i];

    // connectivity: reduce K-split partials, |.|/T, zero diag; output #1
    #pragma unroll
    for (int i = tid; i < 4096; i += 1024) {
        int r = i >> 6, c = i & 63;
        float re = 0.f, im = 0.f;
        #pragma unroll
        for (int sp = 0; sp < KSPLIT; sp++) {
            const float* G = g_G2 + ((size_t)(sp * B_SZ + b)) * 8192;
            re += G[r * 64 + c];
            im += G[(64 + r) * 64 + c];
        }
        float v = (r == c) ? 0.f : sqrtf(re * re + im * im) * (1.f / (float)T_SZ);
        s_conn[r * 65 + c] = v;
        out[(size_t)b * 4096 + i] = v;
    }
    __syncthreads();

    // F1 = EE @ w1
    const float4* w1v = (const float4*)w1;
    const float4* b1v = (const float4*)b1;
    #pragma unroll
    for (int it = 0; it < 2; it++) {
        int slot = tid + it * 1024;
        int r = slot >> 5, f4 = slot & 31;
        float4 acc = make_float4(0.f, 0.f, 0.f, 0.f);
        #pragma unroll 8
        for (int e = 0; e < 64; e++) {
            float4 w = w1v[e * 32 + f4];
            float sc = s_EE[r * 65 + e];
            acc.x += sc * w.x; acc.y += sc * w.y; acc.z += sc * w.z; acc.w += sc * w.w;
        }
        ((float4*)&s_F1[r * 132])[f4] = acc;
    }
    __syncthreads();

    // h1 = relu(conn @ F1 + b1)
    #pragma unroll
    for (int it = 0; it < 2; it++) {
        int slot = tid + it * 1024;
        int r = slot >> 5, f4 = slot & 31;
        float4 acc = b1v[f4];
        #pragma unroll 8
        for (int j = 0; j < 64; j++) {
            float4 fv = ((const float4*)&s_F1[j * 132])[f4];
            float cn = s_conn[r * 65 + j];
            acc.x += cn * fv.x; acc.y += cn * fv.y; acc.z += cn * fv.z; acc.w += cn * fv.w;
        }
        acc.x = fmaxf(acc.x, 0.f); acc.y = fmaxf(acc.y, 0.f);
        acc.z = fmaxf(acc.z, 0.f); acc.w = fmaxf(acc.w, 0.f);
        ((float4*)&s_h1[r * 132])[f4] = acc;
    }
    __syncthreads();

    // t2 = h1 @ w2
    {
        const float4* w2v = (const float4*)w2;
        int r = tid >> 4, e4 = tid & 15;
        float4 acc = make_float4(0.f, 0.f, 0.f, 0.f);
        #pragma unroll 8
        for (int f = 0; f < 128; f++) {
            float4 w = w2v[f * 16 + e4];
            float h = s_h1[r * 132 + f];
            acc.x += h * w.x; acc.y += h * w.y; acc.z += h * w.z; acc.w += h * w.w;
        }
        ((float4*)&s_t2[r * 68])[e4] = acc;
    }
    __syncthreads();

    // h2 = conn @ t2 + b2 ; output #3
    {
        const float4* b2v = (const float4*)b2;
        int r = tid >> 4, e4 = tid & 15;
        float4 acc = b2v[e4];
        #pragma unroll 8
        for (int j = 0; j < 64; j++) {
            float4 t4 = ((const float4*)&s_t2[j * 68])[e4];
            float cn = s_conn[r * 65 + j];
            acc.x += cn * t4.x; acc.y += cn * t4.y; acc.z += cn * t4.z; acc.w += cn * t4.w;
        }
        s_h2[r * 65 + 4 * e4]     = acc.x;
        s_h2[r * 65 + 4 * e4 + 1] = acc.y;
        s_h2[r * 65 + 4 * e4 + 2] = acc.z;
        s_h2[r * 65 + 4 * e4 + 3] = acc.w;
        ((float4*)(out + (size_t)(2 * B_SZ * 4096) + (size_t)b * 4096 + r * 64))[e4] = acc;
    }
    __syncthreads();

    // transposes: WipT[e][m], WopT[f][e]
    #pragma unroll
    for (int i = tid; i < 192 * 64; i += 1024) {
        int m = i >> 6, e = i & 63;
        s_WT[e * 192 + m] = Wip[i];
    }
    #pragma unroll
    for (int i = tid; i < 4096; i += 1024) {
        int eo = i >> 6, f = i & 63;
        s_WT2[f * 64 + eo] = Wop[i];
    }
    __syncthreads();

    // qkv = h2 @ WipT + bip
    {
        const float4* bipv = (const float4*)bip;
        #pragma unroll
        for (int it = 0; it < 3; it++) {
            int slot = tid + it * 1024;
            int n = slot & 63, m4 = slot >> 6;
            float4 acc = bipv[m4];
            #pragma unroll 8
            for (int e = 0; e < 64; e++) {
                float4 w = ((const float4*)&s_WT[e * 192])[m4];
                float h = s_h2[n * 65 + e];
                acc.x += h * w.x; acc.y += h * w.y; acc.z += h * w.z; acc.w += h * w.w;
            }
            float* dst = (m4 < 16) ? s_q : (m4 < 32 ? s_k : s_v);
            int c4 = m4 & 15;
            ((float4*)&dst[n * 68])[c4] = acc;
        }
    }
    __syncthreads();

    // attention: 512 tasks = (head, row); two-pass softmax with __expf
    if (tid < 512) {
        int h = tid >> 6, qi = tid & 63;
        const float inv_sqrt_d = 0.35355339059327373f;
        float qv[8];
        #pragma unroll
        for (int d = 0; d < 8; d++) qv[d] = s_q[qi * 68 + h * 8 + d];
        float mx = -1e30f;
        for (int k = 0; k < 64; k++) {
            float sc = 0.f;
            #pragma unroll
            for (int d = 0; d < 8; d++) sc += qv[d] * s_k[k * 68 + h * 8 + d];
            mx = fmaxf(mx, sc * inv_sqrt_d);
        }
        float denom = 0.f, acc[8] = {};
        for (int k = 0; k < 64; k++) {
            float sc = 0.f;
            #pragma unroll
            for (int d = 0; d < 8; d++) sc += qv[d] * s_k[k * 68 + h * 8 + d];
            float p = __expf(sc * inv_sqrt_d - mx);
            denom += p;
            #pragma unroll
            for (int d = 0; d < 8; d++) acc[d] += p * s_v[k * 68 + h * 8 + d];
        }
        float rinv = 1.f / denom;
        __syncthreads();
        #pragma unroll
        for (int d = 0; d < 8; d++) s_ao[qi * 65 + h * 8 + d] = acc[d] * rinv;
    } else {
        __syncthreads();
    }
    __syncthreads();

    // graph_features = ao @ WopT + bop ; output #2
    {
        const float4* bopv = (const float4*)bop;
        int n = tid >> 4, e4 = tid & 15;
        float4 acc = bopv[e4];
        #pragma unroll 8
        for (int f = 0; f < 64; f++) {
            float4 w = ((const float4*)&s_WT2[f * 64])[e4];
            float av = s_ao[n * 65 + f];
            acc.x += av * w.x; acc.y += av * w.y; acc.z += av * w.z; acc.w += av * w.w;
        }
        ((float4*)(out + (size_t)(B_SZ * 4096) + (size_t)b * 4096 + n * 64))[e4] = acc;
    }
}

// ---------------- launch ----------------
extern "C" void kernel_launch(void* const* d_in, const int* in_sizes, int n_in,
                              void* d_out, int out_size) {
    const float* x   = (const float*)d_in[0];
    const float* EE  = (const float*)d_in[1];
    const float* w1  = (const float*)d_in[2];
    const float* b1  = (const float*)d_in[3];
    const float* w2  = (const float*)d_in[4];
    const float* b2  = (const float*)d_in[5];
    const float* Wip = (const float*)d_in[6];
    const float* bip = (const float*)d_in[7];
    const float* Wop = (const float*)d_in[8];
    const float* bop = (const float*)d_in[9];
    float* out = (float*)d_out;

    cudaFuncSetAttribute(fft_hilbert_kernel,
                         cudaFuncAttributeMaxDynamicSharedMemorySize, 65536);
    cudaFuncSetAttribute(gram_mma_kernel,
                         cudaFuncAttributeMaxDynamicSharedMemorySize, GRAM_SMEM);
    cudaFuncSetAttribute(tail_kernel,
                         cudaFuncAttributeMaxDynamicSharedMemorySize, TAIL_FLOATS * 4);

    twiddle_init_kernel<<<16, 256>>>();
    fft_hilbert_kernel<<<B_SZ * C_SZ, 512, 65536>>>(x);
    gram_mma_kernel<<<dim3(KSPLIT, B_SZ), 256, GRAM_SMEM>>>();
    tail_kernel<<<B_SZ, 1024, TAIL_FLOATS * 4>>>(EE, w1, b1, w2, b2,
                                                 Wip, bip, Wop, bop, out);
}

// round 7
// speedup vs baseline: 1.7776x; 1.2656x over previous
#include <cuda_runtime.h>
#include <cuda_bf16.h>
#include <math.h>

#define B_SZ 32
#define C_SZ 64
#define T_SZ 8192
#define KSPLIT 8
#define NCH 32               // 64-bf16 k-chunks per CTA (16384/8 splits/64)
#define NSTG 4
#define STG_B 16384          // per stage: hi tile 8KB + lo tile 8KB
#define GRAM_SMEM (NSTG * STG_B)

// ---------------- scratch (static device globals; no allocation) ----------------
// bf16 hi/lo planes: [b][c 0..63][16384 bf16 = (re,im) x 8192]
__device__ uint4  g_Ahi[(size_t)B_SZ * 64 * 2048];        // 67 MB
__device__ uint4  g_Alo[(size_t)B_SZ * 64 * 2048];        // 67 MB
__device__ float  g_G2[(size_t)KSPLIT * B_SZ * 128 * 64]; // partials: rows 0-63 Re, 64-127 Im
__device__ float2 g_tw[T_SZ / 2];                         // exp(-2pi i k/N)

__device__ __forceinline__ float2 cmul(float2 a, float2 b) {
    return make_float2(a.x * b.x - a.y * b.y, a.x * b.y + a.y * b.x);
}
__device__ __forceinline__ float2 cadd(float2 a, float2 b) { return make_float2(a.x + b.x, a.y + b.y); }
__device__ __forceinline__ float2 csub(float2 a, float2 b) { return make_float2(a.x - b.x, a.y - b.y); }
__device__ __forceinline__ int SW(int i) { return i ^ ((i >> 5) & 31); }

__device__ __forceinline__ unsigned smem_u32(const void* p) {
    unsigned a;
    asm("{ .reg .u64 t; cvta.to.shared.u64 t, %1; cvt.u32.u64 %0, t; }" : "=r"(a) : "l"(p));
    return a;
}
__device__ __forceinline__ void cpasync16(unsigned dst, const void* src) {
    asm volatile("cp.async.cg.shared.global [%0], [%1], 16;" :: "r"(dst), "l"(src) : "memory");
}
__device__ __forceinline__ void ldsm4(unsigned& r0, unsigned& r1, unsigned& r2, unsigned& r3,
                                      unsigned addr) {
    asm volatile("ldmatrix.sync.aligned.m8n8.x4.shared.b16 {%0,%1,%2,%3}, [%4];"
                 : "=r"(r0), "=r"(r1), "=r"(r2), "=r"(r3) : "r"(addr));
}
__device__ __forceinline__ void mma16816(float* c, unsigned a0, unsigned a1, unsigned a2,
                                         unsigned a3, unsigned b0, unsigned b1) {
    asm volatile("mma.sync.aligned.m16n8k16.row.col.f32.bf16.bf16.f32 "
                 "{%0,%1,%2,%3}, {%4,%5,%6,%7}, {%8,%9}, {%0,%1,%2,%3};"
                 : "+f"(c[0]), "+f"(c[1]), "+f"(c[2]), "+f"(c[3])
                 : "r"(a0), "r"(a1), "r"(a2), "r"(a3), "r"(b0), "r"(b1));
}
// (re,im) -> (im,-re): swap 16-bit halves, negate new hi (bf16 sign = bit 15 of half)
__device__ __forceinline__ unsigned rot_neg(unsigned x) {
    return __byte_perm(x, x, 0x1032) ^ 0x80000000u;
}

// ---------------- twiddle init ----------------
__global__ void twiddle_init_kernel() {
    int i = blockIdx.x * blockDim.x + threadIdx.x;
    if (i < T_SZ / 2) {
        double ang = -2.0 * 3.14159265358979323846 * (double)i / (double)T_SZ;
        g_tw[i] = make_float2((float)cos(ang), (float)sin(ang));
    }
}

// ---------------- FFT (two real channels packed as one complex signal) ----------
// z = xa + i*xb; W = IFFT(h . FFT(z)) / N. Then (complex-linearity of the analytic
// operator):  A_a = (xa, Im W - xb),  A_b = (xb, xa - Re W).
// One block per (batch, channel-pair): 1024 blocks total.
__global__ __launch_bounds__(512) void fft_hilbert_kernel(const float* __restrict__ x) {
    extern __shared__ float2 s[];   // 64 KB
    const int blk = blockIdx.x;                 // 0..1023
    const int b = blk >> 5, cp = blk & 31;
    const float* __restrict__ xa = x + ((size_t)b * C_SZ + 2 * cp) * T_SZ;
    const float* __restrict__ xb = xa + T_SZ;
    const int tid = threadIdx.x;

    // fused: load z + forward stage pair (st=0,1), complex input
    #pragma unroll
    for (int rr = 0; rr < 4; rr++) {
        int g = tid + rr * 512;
        float2 u0 = make_float2(xa[g],        xb[g]);
        float2 u1 = make_float2(xa[g + 2048], xb[g + 2048]);
        float2 u2 = make_float2(xa[g + 4096], xb[g + 4096]);
        float2 u3 = make_float2(xa[g + 6144], xb[g + 6144]);
        float2 w1 = g_tw[g];
        float2 w2 = g_tw[2 * g];
        float2 a0 = cadd(u0, u2), cd = csub(u0, u2);
        float2 a1 = cadd(u1, u3), dd = csub(u1, u3);
        float2 cpv = cmul(cd, w1);
        float2 w1b = make_float2(w1.y, -w1.x);      // w1 * (-i)
        float2 dp  = cmul(dd, w1b);
        s[SW(g)]        = cadd(a0, a1);
        s[SW(g + 2048)] = cmul(csub(a0, a1), w2);
        s[SW(g + 4096)] = cadd(cpv, dp);
        s[SW(g + 6144)] = cmul(csub(cpv, dp), w2);
    }
    __syncthreads();

    // forward stage pairs st = 2,4,6,8,10
    #pragma unroll
    for (int st = 2; st < 12; st += 2) {
        const int shift = 12 - st;
        const int h = 1 << shift, h2 = h >> 1;
        #pragma unroll
        for (int rr = 0; rr < 4; rr++) {
            int g = tid + rr * 512;
            int j = g & (h2 - 1);
            int i = ((g >> (shift - 1)) << (shift + 1)) + j;
            int m = j << st;
            float2 u0 = s[SW(i)], u1 = s[SW(i + h2)];
            float2 u2 = s[SW(i + h)], u3 = s[SW(i + h + h2)];
            float2 w1 = g_tw[m];
            float2 w2 = g_tw[2 * m];
            float2 ap = cadd(u0, u2);
            float2 cpv = cmul(csub(u0, u2), w1);
            float2 bp = cadd(u1, u3);
            float2 w1b = make_float2(w1.y, -w1.x);
            float2 dp = cmul(csub(u1, u3), w1b);
            s[SW(i)]          = cadd(ap, bp);
            s[SW(i + h2)]     = cmul(csub(ap, bp), w2);
            s[SW(i + h)]      = cadd(cpv, dp);
            s[SW(i + h + h2)] = cmul(csub(cpv, dp), w2);
        }
        __syncthreads();
    }

    // fused: final forward stage + Hilbert mask (bit-reversed domain)
    #pragma unroll
    for (int rr = 0; rr < 8; rr++) {
        int t = tid + rr * 512;
        int i0 = SW(2 * t), i1 = SW(2 * t + 1);
        float2 u = s[i0], v = s[i1];
        float2 a = cadd(u, v), d = csub(u, v);
        if (t == 0) { s[i0] = a; s[i1] = d; }
        else {
            s[i0] = make_float2(2.f * a.x, 2.f * a.y);
            s[i1] = make_float2(0.f, 0.f);
        }
    }
    __syncthreads();

    // inverse stage pairs st = 0,2,4,6,8,10 (conjugate twiddles)
    #pragma unroll
    for (int st = 0; st < 12; st += 2) {
        const int g1 = 1 << st;
        #pragma unroll
        for (int rr = 0; rr < 4; rr++) {
            int q = tid + rr * 512;
            int j = q & (g1 - 1);
            int i = ((q >> st) << (st + 2)) + j;
            int m = j << (12 - st);
            float2 tm = g_tw[m];
            float2 w  = make_float2(tm.x, -tm.y);
            float2 t2 = g_tw[m >> 1];
            float2 w2 = make_float2(t2.x, -t2.y);
            float2 w2b = make_float2(-w2.y, w2.x);
            float2 u0 = s[SW(i)], u1 = s[SW(i + g1)];
            float2 u2 = s[SW(i + 2 * g1)], u3 = s[SW(i + 3 * g1)];
            float2 v1 = cmul(u1, w), v3 = cmul(u3, w);
            float2 p0 = cadd(u0, v1), p1 = csub(u0, v1);
            float2 p2 = cadd(u2, v3), p3 = csub(u2, v3);
            float2 q2 = cmul(p2, w2), q3 = cmul(p3, w2b);
            s[SW(i)]          = cadd(p0, q2);
            s[SW(i + 2 * g1)] = csub(p0, q2);
            s[SW(i + g1)]     = cadd(p1, q3);
            s[SW(i + 3 * g1)] = csub(p1, q3);
        }
        __syncthreads();
    }

    // fused: final inverse stage + 1/N scale + un-pack two channels + normalize
    // + bf16 hi/lo split stores
    __nv_bfloat162* Ahi = (__nv_bfloat162*)g_Ahi;
    __nv_bfloat162* Alo = (__nv_bfloat162*)g_Alo;
    const size_t base0 = ((size_t)b * C_SZ + 2 * cp) * 8192;
    const size_t base1 = base0 + 8192;
    const float invN = 1.0f / 8192.0f;
    #pragma unroll
    for (int rr = 0; rr < 8; rr++) {
        int t = tid + rr * 512;
        float2 tm = g_tw[t];
        float2 w = make_float2(tm.x, -tm.y);
        float2 u = s[SW(t)];
        float2 v = cmul(s[SW(t + 4096)], w);
        float2 Wv[2] = { cadd(u, v), csub(u, v) };
        int ti[2] = { t, t + 4096 };
        #pragma unroll
        for (int e = 0; e < 2; e++) {
            int idx = ti[e];
            float Wr = Wv[e].x * invN, Wi = Wv[e].y * invN;
            float av = xa[idx], bv = xb[idx];
            // channel a: (av, Wi - bv); channel b: (bv, av - Wr)
            float zr[2] = { av, bv };
            float zi[2] = { Wi - bv, av - Wr };
            size_t bs[2] = { base0 + idx, base1 + idx };
            #pragma unroll
            for (int ch = 0; ch < 2; ch++) {
                float inv = rsqrtf(zr[ch] * zr[ch] + zi[ch] * zi[ch]);
                float r = zr[ch] * inv, i2 = zi[ch] * inv;
                __nv_bfloat16 rh = __float2bfloat16(r);
                __nv_bfloat16 ih = __float2bfloat16(i2);
                __nv_bfloat16 rl = __float2bfloat16(r - __bfloat162float(rh));
                __nv_bfloat16 il = __float2bfloat16(i2 - __bfloat162float(ih));
                __nv_bfloat162 h;  h.x = rh; h.y = ih;
                __nv_bfloat162 l;  l.x = rl; l.y = il;
                Ahi[bs[ch]] = h;
                Alo[bs[ch]] = l;
            }
        }
    }
}

// ---------------- gram via mma.sync (HMMA): G = Z . Z^H per batch ----------------
__global__ __launch_bounds__(256) void gram_mma_kernel() {
    extern __shared__ __align__(1024) char gsm[];
    const unsigned sbase = smem_u32(gsm);
    const int split = blockIdx.x, b = blockIdx.y;
    const int tid = threadIdx.x, lane = tid & 31, w = tid >> 5;
    const int mrow = 16 * (w & 3);
    const bool isIm = (w >= 4);

    const uint4* __restrict__ hi0 = g_Ahi + (size_t)b * 64 * 2048 + split * 256;
    const uint4* __restrict__ lo0 = g_Alo + (size_t)b * 64 * 2048 + split * 256;

    unsigned swo[2]; int gofs[2];
    #pragma unroll
    for (int v = 0; v < 2; v++) {
        int idx = v * 256 + tid;
        int rw = idx >> 3, seg = idx & 7;
        unsigned off = rw * 128 + seg * 16;
        swo[v] = off ^ ((off >> 3) & 0x70);
        gofs[v] = rw * 2048 + seg;
    }

    const int lr = lane & 15, lcb = lane >> 4;
    unsigned a_off0 = (mrow + lr) * 128 + lcb * 16;
    unsigned aX = ((a_off0 >> 3) & 0x70);
    unsigned b_off0[4], bX[4];
    #pragma unroll
    for (int q = 0; q < 4; q++) {
        b_off0[q] = (16 * q + lr) * 128 + lcb * 16;
        bX[q] = ((b_off0[q] >> 3) & 0x70);
    }

    float c[8][4] = {};

    #pragma unroll
    for (int j = 0; j < 3; j++) {
        unsigned st = sbase + j * STG_B;
        #pragma unroll
        for (int v = 0; v < 2; v++) {
            cpasync16(st + swo[v],        hi0 + gofs[v] + j * 8);
            cpasync16(st + 8192 + swo[v], lo0 + gofs[v] + j * 8);
        }
        asm volatile("cp.async.commit_group;" ::: "memory");
    }

    for (int i = 0; i < NCH; i++) {
        int jn = i + 3;
        if (jn < NCH) {
            unsigned st = sbase + (jn % NSTG) * STG_B;
            #pragma unroll
            for (int v = 0; v < 2; v++) {
                cpasync16(st + swo[v],        hi0 + gofs[v] + jn * 8);
                cpasync16(st + 8192 + swo[v], lo0 + gofs[v] + jn * 8);
            }
            asm volatile("cp.async.commit_group;" ::: "memory");
            asm volatile("cp.async.wait_group 3;" ::: "memory");
        } else {
            asm volatile("cp.async.wait_group 0;" ::: "memory");
        }
        __syncthreads();

        const unsigned sb = sbase + (i % NSTG) * STG_B;
        #pragma unroll
        for (int ks = 0; ks < 4; ks++) {
            unsigned ah0, ah1, ah2, ah3, al0, al1, al2, al3;
            unsigned aa = sb + ((a_off0 + ks * 32) ^ aX);
            ldsm4(ah0, ah1, ah2, ah3, aa);
            ldsm4(al0, al1, al2, al3, aa + 8192);
            if (isIm) {
                ah0 = rot_neg(ah0); ah1 = rot_neg(ah1); ah2 = rot_neg(ah2); ah3 = rot_neg(ah3);
                al0 = rot_neg(al0); al1 = rot_neg(al1); al2 = rot_neg(al2); al3 = rot_neg(al3);
            }
            #pragma unroll
            for (int q = 0; q < 4; q++) {
                unsigned bh0, bh1, bh2, bh3, bl0, bl1, bl2, bl3;
                unsigned ba = sb + ((b_off0[q] + ks * 32) ^ bX[q]);
                ldsm4(bh0, bh1, bh2, bh3, ba);
                ldsm4(bl0, bl1, bl2, bl3, ba + 8192);
                mma16816(c[2 * q],     ah0, ah1, ah2, ah3, bh0, bh2);
                mma16816(c[2 * q],     ah0, ah1, ah2, ah3, bl0, bl2);
                mma16816(c[2 * q],     al0, al1, al2, al3, bh0, bh2);
                mma16816(c[2 * q + 1], ah0, ah1, ah2, ah3, bh1, bh3);
                mma16816(c[2 * q + 1], ah0, ah1, ah2, ah3, bl1, bl3);
                mma16816(c[2 * q + 1], al0, al1, al2, al3, bh1, bh3);
            }
        }
        __syncthreads();
    }

    float* G = g_G2 + ((size_t)(split * B_SZ + b)) * 8192;
    int rbase = (isIm ? 64 : 0) + mrow + (lane >> 2);
    #pragma unroll
    for (int j = 0; j < 8; j++) {
        int col = 8 * j + 2 * (lane & 3);
        G[rbase * 64 + col]           = c[j][0];
        G[rbase * 64 + col + 1]       = c[j][1];
        G[(rbase + 8) * 64 + col]     = c[j][2];
        G[(rbase + 8) * 64 + col + 1] = c[j][3];
    }
}

// ---------------- tail: conn finalize + GCN + MHA. One block/batch, 1024 thr ----
#define OFF_EE   4160
#define OFF_F1   8320
#define OFF_H1   16768
#define OFF_T2   25216
#define OFF_H2   29568
#define OFF_Q    33728
#define OFF_K    38080
#define OFF_V    42432
#define TAIL_FLOATS 46784

__global__ __launch_bounds__(1024) void tail_kernel(
    const float* __restrict__ EE,  const float* __restrict__ w1, const float* __restrict__ b1,
    const float* __restrict__ w2,  const float* __restrict__ b2,
    const float* __restrict__ Wip, const float* __restrict__ bip,
    const float* __restrict__ Wop, const float* __restrict__ bop,
    float* __restrict__ out)
{
    extern __shared__ float sm[];
    float* s_conn = sm;
    float* s_EE  = sm + OFF_EE;
    float* s_F1  = sm + OFF_F1;
    float* s_h1  = sm + OFF_H1;
    float* s_t2  = sm + OFF_T2;
    float* s_h2  = sm + OFF_H2;
    float* s_q   = sm + OFF_Q;
    float* s_k   = sm + OFF_K;
    float* s_v   = sm + OFF_V;
    float* s_WT  = s_F1;
    float* s_WT2 = s_t2;
    float* s_ao  = s_conn;
    const int b = blockIdx.x;
    const int tid = threadIdx.x;

    #pragma unroll
    for (int i = tid; i < 4096; i += 1024)
        s_EE[(i >> 6) * 65 + (i & 63)] = EE[i];

    // connectivity: reduce K-split partials, |.|/T, zero diag; output #1
    #pragma unroll
    for (int i = tid; i < 4096; i += 1024) {
        int r = i >> 6, c = i & 63;
        float re = 0.f, im = 0.f;
        #pragma unroll
        for (int sp = 0; sp < KSPLIT; sp++) {
            const float* G = g_G2 + ((size_t)(sp * B_SZ + b)) * 8192;
            re += G[r * 64 + c];
            im += G[(64 + r) * 64 + c];
        }
        float v = (r == c) ? 0.f : sqrtf(re * re + im * im) * (1.f / (float)T_SZ);
        s_conn[r * 65 + c] = v;
        out[(size_t)b * 4096 + i] = v;
    }
    __syncthreads();

    // F1 = EE @ w1
    const float4* w1v = (const float4*)w1;
    const float4* b1v = (const float4*)b1;
    #pragma unroll
    for (int it = 0; it < 2; it++) {
        int slot = tid + it * 1024;
        int r = slot >> 5, f4 = slot & 31;
        float4 acc = make_float4(0.f, 0.f, 0.f, 0.f);
        #pragma unroll 8
        for (int e = 0; e < 64; e++) {
            float4 w = w1v[e * 32 + f4];
            float sc = s_EE[r * 65 + e];
            acc.x += sc * w.x; acc.y += sc * w.y; acc.z += sc * w.z; acc.w += sc * w.w;
        }
        ((float4*)&s_F1[r * 132])[f4] = acc;
    }
    __syncthreads();

    // h1 = relu(conn @ F1 + b1)
    #pragma unroll
    for (int it = 0; it < 2; it++) {
        int slot = tid + it * 1024;
        int r = slot >> 5, f4 = slot & 31;
        float4 acc = b1v[f4];
        #pragma unroll 8
        for (int j = 0; j < 64; j++) {
            float4 fv = ((const float4*)&s_F1[j * 132])[f4];
            float cn = s_conn[r * 65 + j];
            acc.x += cn * fv.x; acc.y += cn * fv.y; acc.z += cn * fv.z; acc.w += cn * fv.w;
        }
        acc.x = fmaxf(acc.x, 0.f); acc.y = fmaxf(acc.y, 0.f);
        acc.z = fmaxf(acc.z, 0.f); acc.w = fmaxf(acc.w, 0.f);
        ((float4*)&s_h1[r * 132])[f4] = acc;
    }
    __syncthreads();

    // t2 = h1 @ w2
    {
        const float4* w2v = (const float4*)w2;
        int r = tid >> 4, e4 = tid & 15;
        float4 acc = make_float4(0.f, 0.f, 0.f, 0.f);
        #pragma unroll 8
        for (int f = 0; f < 128; f++) {
            float4 w = w2v[f * 16 + e4];
            float h = s_h1[r * 132 + f];
            acc.x += h * w.x; acc.y += h * w.y; acc.z += h * w.z; acc.w += h * w.w;
        }
        ((float4*)&s_t2[r * 68])[e4] = acc;
    }
    __syncthreads();

    // h2 = conn @ t2 + b2 ; output #3
    {
        const float4* b2v = (const float4*)b2;
        int r = tid >> 4, e4 = tid & 15;
        float4 acc = b2v[e4];
        #pragma unroll 8
        for (int j = 0; j < 64; j++) {
            float4 t4 = ((const float4*)&s_t2[j * 68])[e4];
            float cn = s_conn[r * 65 + j];
            acc.x += cn * t4.x; acc.y += cn * t4.y; acc.z += cn * t4.z; acc.w += cn * t4.w;
        }
        s_h2[r * 65 + 4 * e4]     = acc.x;
        s_h2[r * 65 + 4 * e4 + 1] = acc.y;
        s_h2[r * 65 + 4 * e4 + 2] = acc.z;
        s_h2[r * 65 + 4 * e4 + 3] = acc.w;
        ((float4*)(out + (size_t)(2 * B_SZ * 4096) + (size_t)b * 4096 + r * 64))[e4] = acc;
    }
    __syncthreads();

    // transposes: WipT[e][m], WopT[f][e]
    #pragma unroll
    for (int i = tid; i < 192 * 64; i += 1024) {
        int m = i >> 6, e = i & 63;
        s_WT[e * 192 + m] = Wip[i];
    }
    #pragma unroll
    for (int i = tid; i < 4096; i += 1024) {
        int eo = i >> 6, f = i & 63;
        s_WT2[f * 64 + eo] = Wop[i];
    }
    __syncthreads();

    // qkv = h2 @ WipT + bip
    {
        const float4* bipv = (const float4*)bip;
        #pragma unroll
        for (int it = 0; it < 3; it++) {
            int slot = tid + it * 1024;
            int n = slot & 63, m4 = slot >> 6;
            float4 acc = bipv[m4];
            #pragma unroll 8
            for (int e = 0; e < 64; e++) {
                float4 w = ((const float4*)&s_WT[e * 192])[m4];
                float h = s_h2[n * 65 + e];
                acc.x += h * w.x; acc.y += h * w.y; acc.z += h * w.z; acc.w += h * w.w;
            }
            float* dst = (m4 < 16) ? s_q : (m4 < 32 ? s_k : s_v);
            int c4 = m4 & 15;
            ((float4*)&dst[n * 68])[c4] = acc;
        }
    }
    __syncthreads();

    // attention: 512 tasks = (head, row); two-pass softmax with __expf
    if (tid < 512) {
        int h = tid >> 6, qi = tid & 63;
        const float inv_sqrt_d = 0.35355339059327373f;
        float qv[8];
        #pragma unroll
        for (int d = 0; d < 8; d++) qv[d] = s_q[qi * 68 + h * 8 + d];
        float mx = -1e30f;
        for (int k = 0; k < 64; k++) {
            float sc = 0.f;
            #pragma unroll
            for (int d = 0; d < 8; d++) sc += qv[d] * s_k[k * 68 + h * 8 + d];
            mx = fmaxf(mx, sc * inv_sqrt_d);
        }
        float denom = 0.f, acc[8] = {};
        for (int k = 0; k < 64; k++) {
            float sc = 0.f;
            #pragma unroll
            for (int d = 0; d < 8; d++) sc += qv[d] * s_k[k * 68 + h * 8 + d];
            float p = __expf(sc * inv_sqrt_d - mx);
            denom += p;
            #pragma unroll
            for (int d = 0; d < 8; d++) acc[d] += p * s_v[k * 68 + h * 8 + d];
        }
        float rinv = 1.f / denom;
        __syncthreads();
        #pragma unroll
        for (int d = 0; d < 8; d++) s_ao[qi * 65 + h * 8 + d] = acc[d] * rinv;
    } else {
        __syncthreads();
    }
    __syncthreads();

    // graph_features = ao @ WopT + bop ; output #2
    {
        const float4* bopv = (const float4*)bop;
        int n = tid >> 4, e4 = tid & 15;
        float4 acc = bopv[e4];
        #pragma unroll 8
        for (int f = 0; f < 64; f++) {
            float4 w = ((const float4*)&s_WT2[f * 64])[e4];
            float av = s_ao[n * 65 + f];
            acc.x += av * w.x; acc.y += av * w.y; acc.z += av * w.z; acc.w += av * w.w;
        }
        ((float4*)(out + (size_t)(B_SZ * 4096) + (size_t)b * 4096 + n * 64))[e4] = acc;
    }
}

// ---------------- launch ----------------
extern "C" void kernel_launch(void* const* d_in, const int* in_sizes, int n_in,
                              void* d_out, int out_size) {
    const float* x   = (const float*)d_in[0];
    const float* EE  = (const float*)d_in[1];
    const float* w1  = (const float*)d_in[2];
    const float* b1  = (const float*)d_in[3];
    const float* w2  = (const float*)d_in[4];
    const float* b2  = (const float*)d_in[5];
    const float* Wip = (const float*)d_in[6];
    const float* bip = (const float*)d_in[7];
    const float* Wop = (const float*)d_in[8];
    const float* bop = (const float*)d_in[9];
    float* out = (float*)d_out;

    cudaFuncSetAttribute(fft_hilbert_kernel,
                         cudaFuncAttributeMaxDynamicSharedMemorySize, 65536);
    cudaFuncSetAttribute(gram_mma_kernel,
                         cudaFuncAttributeMaxDynamicSharedMemorySize, GRAM_SMEM);
    cudaFuncSetAttribute(tail_kernel,
                         cudaFuncAttributeMaxDynamicSharedMemorySize, TAIL_FLOATS * 4);

    twiddle_init_kernel<<<16, 256>>>();
    fft_hilbert_kernel<<<B_SZ * C_SZ / 2, 512, 65536>>>(x);
    gram_mma_kernel<<<dim3(KSPLIT, B_SZ), 256, GRAM_SMEM>>>();
    tail_kernel<<<B_SZ, 1024, TAIL_FLOATS * 4>>>(EE, w1, b1, w2, b2,
                                                 Wip, bip, Wop, bop, out);
}

// round 8
// speedup vs baseline: 2.1659x; 1.2185x over previous
#include <cuda_runtime.h>
#include <cuda_bf16.h>
#include <math.h>

#define B_SZ 32
#define C_SZ 64
#define T_SZ 8192
#define KSPLIT 8
#define NCH 32               // 64-bf16 k-chunks per CTA (16384/8 splits/64)
#define NSTG 4
#define STG_B 16384          // per stage: hi tile 8KB + lo tile 8KB
#define GRAM_SMEM (NSTG * STG_B)

// ---------------- scratch (static device globals; no allocation) ----------------
__device__ uint4  g_Ahi[(size_t)B_SZ * 64 * 2048];        // 67 MB
__device__ uint4  g_Alo[(size_t)B_SZ * 64 * 2048];        // 67 MB
__device__ float  g_G2[(size_t)KSPLIT * B_SZ * 128 * 64]; // partials: rows 0-63 Re, 64-127 Im
__device__ float2 g_tw[T_SZ / 2];                         // exp(-2pi i k/N)

__device__ __forceinline__ float2 cmul(float2 a, float2 b) {
    return make_float2(a.x * b.x - a.y * b.y, a.x * b.y + a.y * b.x);
}
__device__ __forceinline__ float2 cadd(float2 a, float2 b) { return make_float2(a.x + b.x, a.y + b.y); }
__device__ __forceinline__ float2 csub(float2 a, float2 b) { return make_float2(a.x - b.x, a.y - b.y); }
__device__ __forceinline__ int SW(int i) { return i ^ ((i >> 5) & 31); }

__device__ __forceinline__ unsigned smem_u32(const void* p) {
    unsigned a;
    asm("{ .reg .u64 t; cvta.to.shared.u64 t, %1; cvt.u32.u64 %0, t; }" : "=r"(a) : "l"(p));
    return a;
}
__device__ __forceinline__ void cpasync16(unsigned dst, const void* src) {
    asm volatile("cp.async.cg.shared.global [%0], [%1], 16;" :: "r"(dst), "l"(src) : "memory");
}
__device__ __forceinline__ void ldsm4(unsigned& r0, unsigned& r1, unsigned& r2, unsigned& r3,
                                      unsigned addr) {
    asm volatile("ldmatrix.sync.aligned.m8n8.x4.shared.b16 {%0,%1,%2,%3}, [%4];"
                 : "=r"(r0), "=r"(r1), "=r"(r2), "=r"(r3) : "r"(addr));
}
__device__ __forceinline__ void mma16816(float* c, unsigned a0, unsigned a1, unsigned a2,
                                         unsigned a3, unsigned b0, unsigned b1) {
    asm volatile("mma.sync.aligned.m16n8k16.row.col.f32.bf16.bf16.f32 "
                 "{%0,%1,%2,%3}, {%4,%5,%6,%7}, {%8,%9}, {%0,%1,%2,%3};"
                 : "+f"(c[0]), "+f"(c[1]), "+f"(c[2]), "+f"(c[3])
                 : "r"(a0), "r"(a1), "r"(a2), "r"(a3), "r"(b0), "r"(b1));
}
__device__ __forceinline__ unsigned rot_neg(unsigned x) {
    return __byte_perm(x, x, 0x1032) ^ 0x80000000u;
}

#define RC8 0.70710678118654752f

// ---- forward radix-8 (DIF stages st, st+1, st+2). d = 2^(10-st). ----
__device__ __forceinline__ void fwd8(float2* s, int g, int st) {
    const int d = 1 << (10 - st);
    const int j = g & (d - 1);
    const int i = ((g >> (10 - st)) << (13 - st)) + j;
    float2 W1 = g_tw[j << st];
    float2 W2 = g_tw[j << (st + 1)];
    float2 W4 = g_tw[j << (st + 2)];
    float2 u0 = s[SW(i)],       u1 = s[SW(i + d)];
    float2 u2 = s[SW(i + 2*d)], u3 = s[SW(i + 3*d)];
    float2 u4 = s[SW(i + 4*d)], u5 = s[SW(i + 5*d)];
    float2 u6 = s[SW(i + 6*d)], u7 = s[SW(i + 7*d)];
    // L1: pairs (k, k+4), twiddle W1 * E8^k, E8 = (RC8, -RC8)
    float2 a0 = cadd(u0, u4), a1 = cadd(u1, u5), a2 = cadd(u2, u6), a3 = cadd(u3, u7);
    float2 W1E  = make_float2(RC8 * (W1.x + W1.y), RC8 * (W1.y - W1.x));
    float2 W1m  = make_float2(W1.y, -W1.x);            // W1 * (-i)
    float2 W1Em = make_float2(W1E.y, -W1E.x);          // W1 * (-i) * E8
    float2 b0 = cmul(csub(u0, u4), W1);
    float2 b1 = cmul(csub(u1, u5), W1E);
    float2 b2 = cmul(csub(u2, u6), W1m);
    float2 b3 = cmul(csub(u3, u7), W1Em);
    // L2: pairs (0,2),(1,3) with W2, W2*(-i)
    float2 W2m = make_float2(W2.y, -W2.x);
    float2 A0 = cadd(a0, a2), A2 = cmul(csub(a0, a2), W2);
    float2 A1 = cadd(a1, a3), A3 = cmul(csub(a1, a3), W2m);
    float2 B0 = cadd(b0, b2), B2 = cmul(csub(b0, b2), W2);
    float2 B1 = cadd(b1, b3), B3 = cmul(csub(b1, b3), W2m);
    // L3: adjacent pairs, twiddle W4
    s[SW(i)]       = cadd(A0, A1);
    s[SW(i + d)]   = cmul(csub(A0, A1), W4);
    s[SW(i + 2*d)] = cadd(A2, A3);
    s[SW(i + 3*d)] = cmul(csub(A2, A3), W4);
    s[SW(i + 4*d)] = cadd(B0, B1);
    s[SW(i + 5*d)] = cmul(csub(B0, B1), W4);
    s[SW(i + 6*d)] = cadd(B2, B3);
    s[SW(i + 7*d)] = cmul(csub(B2, B3), W4);
}

// ---- inverse radix-8 (DIT stages st, st+1, st+2). e = 2^st. ----
__device__ __forceinline__ void inv8(float2* s, int q, int st) {
    const int e = 1 << st;
    const int j = q & (e - 1);
    const int i = ((q >> st) << (st + 3)) + j;
    float2 c1 = g_tw[j << (12 - st)]; float2 W1 = make_float2(c1.x, -c1.y);
    float2 c2 = g_tw[j << (11 - st)]; float2 W2 = make_float2(c2.x, -c2.y);
    float2 c4 = g_tw[j << (10 - st)]; float2 W4 = make_float2(c4.x, -c4.y);
    float2 u0 = s[SW(i)],       u1 = s[SW(i + e)];
    float2 u2 = s[SW(i + 2*e)], u3 = s[SW(i + 3*e)];
    float2 u4 = s[SW(i + 4*e)], u5 = s[SW(i + 5*e)];
    float2 u6 = s[SW(i + 6*e)], u7 = s[SW(i + 7*e)];
    // L1: pairs (0,1)(2,3)(4,5)(6,7) with W1
    float2 v;
    v = cmul(u1, W1); float2 t0 = cadd(u0, v), t1 = csub(u0, v);
    v = cmul(u3, W1); float2 t2 = cadd(u2, v), t3 = csub(u2, v);
    v = cmul(u5, W1); float2 t4 = cadd(u4, v), t5 = csub(u4, v);
    v = cmul(u7, W1); float2 t6 = cadd(u6, v), t7 = csub(u6, v);
    // L2: pairs (0,2)(4,6) with W2; (1,3)(5,7) with i*W2
    float2 W2i = make_float2(-W2.y, W2.x);
    v = cmul(t2, W2);  float2 s0 = cadd(t0, v), s2 = csub(t0, v);
    v = cmul(t3, W2i); float2 s1 = cadd(t1, v), s3 = csub(t1, v);
    v = cmul(t6, W2);  float2 s4 = cadd(t4, v), s6 = csub(t4, v);
    v = cmul(t7, W2i); float2 s5 = cadd(t5, v), s7 = csub(t5, v);
    // L3: pairs (k, k+4) with W4 * E8bar^k, E8bar = (RC8, RC8)
    float2 W4E  = make_float2(RC8 * (W4.x - W4.y), RC8 * (W4.x + W4.y));
    float2 W4i  = make_float2(-W4.y, W4.x);
    float2 W4Ei = make_float2(-W4E.y, W4E.x);
    v = cmul(s4, W4);   s[SW(i)]       = cadd(s0, v); s[SW(i + 4*e)] = csub(s0, v);
    v = cmul(s5, W4E);  s[SW(i + e)]   = cadd(s1, v); s[SW(i + 5*e)] = csub(s1, v);
    v = cmul(s6, W4i);  s[SW(i + 2*e)] = cadd(s2, v); s[SW(i + 6*e)] = csub(s2, v);
    v = cmul(s7, W4Ei); s[SW(i + 3*e)] = cadd(s3, v); s[SW(i + 7*e)] = csub(s3, v);
}

// ---------------- twiddle init ----------------
__global__ void twiddle_init_kernel() {
    int i = blockIdx.x * blockDim.x + threadIdx.x;
    if (i < T_SZ / 2) {
        double ang = -2.0 * 3.14159265358979323846 * (double)i / (double)T_SZ;
        g_tw[i] = make_float2((float)cos(ang), (float)sin(ang));
    }
}

// ---------------- FFT (pair-packed real channels), radix-8 trips -----------------
__global__ __launch_bounds__(512) void fft_hilbert_kernel(const float* __restrict__ x) {
    extern __shared__ float2 s[];   // 64 KB
    const int blk = blockIdx.x;                 // 0..1023
    const int b = blk >> 5, cp = blk & 31;
    const float* __restrict__ xa = x + ((size_t)b * C_SZ + 2 * cp) * T_SZ;
    const float* __restrict__ xb = xa + T_SZ;
    const int tid = threadIdx.x;

    // trip 0: load z + forward stages 0,1,2 (radix-8; d=1024, j=i=g)
    #pragma unroll
    for (int rr = 0; rr < 2; rr++) {
        int g = tid + rr * 512;
        float2 u0 = make_float2(xa[g],        xb[g]);
        float2 u1 = make_float2(xa[g + 1024], xb[g + 1024]);
        float2 u2 = make_float2(xa[g + 2048], xb[g + 2048]);
        float2 u3 = make_float2(xa[g + 3072], xb[g + 3072]);
        float2 u4 = make_float2(xa[g + 4096], xb[g + 4096]);
        float2 u5 = make_float2(xa[g + 5120], xb[g + 5120]);
        float2 u6 = make_float2(xa[g + 6144], xb[g + 6144]);
        float2 u7 = make_float2(xa[g + 7168], xb[g + 7168]);
        float2 W1 = g_tw[g], W2 = g_tw[2 * g], W4 = g_tw[4 * g];
        float2 a0 = cadd(u0, u4), a1 = cadd(u1, u5), a2 = cadd(u2, u6), a3 = cadd(u3, u7);
        float2 W1E  = make_float2(RC8 * (W1.x + W1.y), RC8 * (W1.y - W1.x));
        float2 W1m  = make_float2(W1.y, -W1.x);
        float2 W1Em = make_float2(W1E.y, -W1E.x);
        float2 b0 = cmul(csub(u0, u4), W1);
        float2 b1 = cmul(csub(u1, u5), W1E);
        float2 b2 = cmul(csub(u2, u6), W1m);
        float2 b3 = cmul(csub(u3, u7), W1Em);
        float2 W2m = make_float2(W2.y, -W2.x);
        float2 A0 = cadd(a0, a2), A2 = cmul(csub(a0, a2), W2);
        float2 A1 = cadd(a1, a3), A3 = cmul(csub(a1, a3), W2m);
        float2 B0 = cadd(b0, b2), B2 = cmul(csub(b0, b2), W2);
        float2 B1 = cadd(b1, b3), B3 = cmul(csub(b1, b3), W2m);
        s[SW(g)]        = cadd(A0, A1);
        s[SW(g + 1024)] = cmul(csub(A0, A1), W4);
        s[SW(g + 2048)] = cadd(A2, A3);
        s[SW(g + 3072)] = cmul(csub(A2, A3), W4);
        s[SW(g + 4096)] = cadd(B0, B1);
        s[SW(g + 5120)] = cmul(csub(B0, B1), W4);
        s[SW(g + 6144)] = cadd(B2, B3);
        s[SW(g + 7168)] = cmul(csub(B2, B3), W4);
    }
    __syncthreads();

    // forward trips st = 3, 6, 9
    #pragma unroll
    for (int st = 3; st < 12; st += 3) {
        #pragma unroll
        for (int rr = 0; rr < 2; rr++) fwd8(s, tid + rr * 512, st);
        __syncthreads();
    }

    // fused: final forward stage (12) + Hilbert mask (bit-reversed domain)
    #pragma unroll
    for (int rr = 0; rr < 8; rr++) {
        int t = tid + rr * 512;
        int i0 = SW(2 * t), i1 = SW(2 * t + 1);
        float2 u = s[i0], v = s[i1];
        float2 a = cadd(u, v), d = csub(u, v);
        if (t == 0) { s[i0] = a; s[i1] = d; }
        else {
            s[i0] = make_float2(2.f * a.x, 2.f * a.y);
            s[i1] = make_float2(0.f, 0.f);
        }
    }
    __syncthreads();

    // inverse trips st = 0, 3, 6, 9
    #pragma unroll
    for (int st = 0; st < 12; st += 3) {
        #pragma unroll
        for (int rr = 0; rr < 2; rr++) inv8(s, tid + rr * 512, st);
        __syncthreads();
    }

    // fused: final inverse stage (12) + 1/N + un-pack two channels + normalize
    __nv_bfloat162* Ahi = (__nv_bfloat162*)g_Ahi;
    __nv_bfloat162* Alo = (__nv_bfloat162*)g_Alo;
    const size_t base0 = ((size_t)b * C_SZ + 2 * cp) * 8192;
    const size_t base1 = base0 + 8192;
    const float invN = 1.0f / 8192.0f;
    #pragma unroll
    for (int rr = 0; rr < 8; rr++) {
        int t = tid + rr * 512;
        float2 tm = g_tw[t];
        float2 w = make_float2(tm.x, -tm.y);
        float2 u = s[SW(t)];
        float2 v = cmul(s[SW(t + 4096)], w);
        float2 Wv[2] = { cadd(u, v), csub(u, v) };
        int ti[2] = { t, t + 4096 };
        #pragma unroll
        for (int e = 0; e < 2; e++) {
            int idx = ti[e];
            float Wr = Wv[e].x * invN, Wi = Wv[e].y * invN;
            float av = xa[idx], bv = xb[idx];
            float zr[2] = { av, bv };
            float zi[2] = { Wi - bv, av - Wr };
            size_t bs[2] = { base0 + idx, base1 + idx };
            #pragma unroll
            for (int ch = 0; ch < 2; ch++) {
                float inv = rsqrtf(zr[ch] * zr[ch] + zi[ch] * zi[ch]);
                float r = zr[ch] * inv, i2 = zi[ch] * inv;
                __nv_bfloat16 rh = __float2bfloat16(r);
                __nv_bfloat16 ih = __float2bfloat16(i2);
                __nv_bfloat16 rl = __float2bfloat16(r - __bfloat162float(rh));
                __nv_bfloat16 il = __float2bfloat16(i2 - __bfloat162float(ih));
                __nv_bfloat162 h;  h.x = rh; h.y = ih;
                __nv_bfloat162 l;  l.x = rl; l.y = il;
                Ahi[bs[ch]] = h;
                Alo[bs[ch]] = l;
            }
        }
    }
}

// ---------------- gram via mma.sync (HMMA): G = Z . Z^H per batch ----------------
__global__ __launch_bounds__(256) void gram_mma_kernel() {
    extern __shared__ __align__(1024) char gsm[];
    const unsigned sbase = smem_u32(gsm);
    const int split = blockIdx.x, b = blockIdx.y;
    const int tid = threadIdx.x, lane = tid & 31, w = tid >> 5;
    const int mrow = 16 * (w & 3);
    const bool isIm = (w >= 4);

    const uint4* __restrict__ hi0 = g_Ahi + (size_t)b * 64 * 2048 + split * 256;
    const uint4* __restrict__ lo0 = g_Alo + (size_t)b * 64 * 2048 + split * 256;

    unsigned swo[2]; int gofs[2];
    #pragma unroll
    for (int v = 0; v < 2; v++) {
        int idx = v * 256 + tid;
        int rw = idx >> 3, seg = idx & 7;
        unsigned off = rw * 128 + seg * 16;
        swo[v] = off ^ ((off >> 3) & 0x70);
        gofs[v] = rw * 2048 + seg;
    }

    const int lr = lane & 15, lcb = lane >> 4;
    unsigned a_off0 = (mrow + lr) * 128 + lcb * 16;
    unsigned aX = ((a_off0 >> 3) & 0x70);
    unsigned b_off0[4], bX[4];
    #pragma unroll
    for (int q = 0; q < 4; q++) {
        b_off0[q] = (16 * q + lr) * 128 + lcb * 16;
        bX[q] = ((b_off0[q] >> 3) & 0x70);
    }

    float c[8][4] = {};

    #pragma unroll
    for (int j = 0; j < 3; j++) {
        unsigned st = sbase + j * STG_B;
        #pragma unroll
        for (int v = 0; v < 2; v++) {
            cpasync16(st + swo[v],        hi0 + gofs[v] + j * 8);
            cpasync16(st + 8192 + swo[v], lo0 + gofs[v] + j * 8);
        }
        asm volatile("cp.async.commit_group;" ::: "memory");
    }

    for (int i = 0; i < NCH; i++) {
        int jn = i + 3;
        if (jn < NCH) {
            unsigned st = sbase + (jn % NSTG) * STG_B;
            #pragma unroll
            for (int v = 0; v < 2; v++) {
                cpasync16(st + swo[v],        hi0 + gofs[v] + jn * 8);
                cpasync16(st + 8192 + swo[v], lo0 + gofs[v] + jn * 8);
            }
            asm volatile("cp.async.commit_group;" ::: "memory");
            asm volatile("cp.async.wait_group 3;" ::: "memory");
        } else {
            asm volatile("cp.async.wait_group 0;" ::: "memory");
        }
        __syncthreads();

        const unsigned sb = sbase + (i % NSTG) * STG_B;
        #pragma unroll
        for (int ks = 0; ks < 4; ks++) {
            unsigned ah0, ah1, ah2, ah3, al0, al1, al2, al3;
            unsigned aa = sb + ((a_off0 + ks * 32) ^ aX);
            ldsm4(ah0, ah1, ah2, ah3, aa);
            ldsm4(al0, al1, al2, al3, aa + 8192);
            if (isIm) {
                ah0 = rot_neg(ah0); ah1 = rot_neg(ah1); ah2 = rot_neg(ah2); ah3 = rot_neg(ah3);
                al0 = rot_neg(al0); al1 = rot_neg(al1); al2 = rot_neg(al2); al3 = rot_neg(al3);
            }
            #pragma unroll
            for (int q = 0; q < 4; q++) {
                unsigned bh0, bh1, bh2, bh3, bl0, bl1, bl2, bl3;
                unsigned ba = sb + ((b_off0[q] + ks * 32) ^ bX[q]);
                ldsm4(bh0, bh1, bh2, bh3, ba);
                ldsm4(bl0, bl1, bl2, bl3, ba + 8192);
                mma16816(c[2 * q],     ah0, ah1, ah2, ah3, bh0, bh2);
                mma16816(c[2 * q],     ah0, ah1, ah2, ah3, bl0, bl2);
                mma16816(c[2 * q],     al0, al1, al2, al3, bh0, bh2);
                mma16816(c[2 * q + 1], ah0, ah1, ah2, ah3, bh1, bh3);
                mma16816(c[2 * q + 1], ah0, ah1, ah2, ah3, bl1, bl3);
                mma16816(c[2 * q + 1], al0, al1, al2, al3, bh1, bh3);
            }
        }
        __syncthreads();
    }

    float* G = g_G2 + ((size_t)(split * B_SZ + b)) * 8192;
    int rbase = (isIm ? 64 : 0) + mrow + (lane >> 2);
    #pragma unroll
    for (int j = 0; j < 8; j++) {
        int col = 8 * j + 2 * (lane & 3);
        G[rbase * 64 + col]           = c[j][0];
        G[rbase * 64 + col + 1]       = c[j][1];
        G[(rbase + 8) * 64 + col]     = c[j][2];
        G[(rbase + 8) * 64 + col + 1] = c[j][3];
    }
}

// ---------------- tail: conn finalize + GCN + MHA. One block/batch, 1024 thr ----
// Weight prefetch aliases: w1 -> h1 region (dead until h1 stage);
// w2 -> q+k region (dead until qkv); Wip -> EE+F1 region (after h1);
// Wop -> h1 region (after t2).
#define OFF_EE   4160
#define OFF_F1   8320
#define OFF_H1   16768
#define OFF_T2   25216
#define OFF_H2   29568
#define OFF_Q    33728
#define OFF_K    38080
#define OFF_V    42432
#define TAIL_FLOATS 46784

__global__ __launch_bounds__(1024) void tail_kernel(
    const float* __restrict__ EE,  const float* __restrict__ w1, const float* __restrict__ b1,
    const float* __restrict__ w2,  const float* __restrict__ b2,
    const float* __restrict__ Wip, const float* __restrict__ bip,
    const float* __restrict__ Wop, const float* __restrict__ bop,
    float* __restrict__ out)
{
    extern __shared__ float sm[];
    float* s_conn = sm;
    float* s_EE  = sm + OFF_EE;
    float* s_F1  = sm + OFF_F1;
    float* s_h1  = sm + OFF_H1;
    float* s_t2  = sm + OFF_T2;
    float* s_h2  = sm + OFF_H2;
    float* s_q   = sm + OFF_Q;
    float* s_k   = sm + OFF_K;
    float* s_v   = sm + OFF_V;
    float* s_ao  = s_conn;                 // conn dead after h2
    const float* s_w1raw  = sm + OFF_H1;   // 8192 floats
    const float* s_w2raw  = sm + OFF_Q;    // 8192 floats (q+k regions)
    const float* s_wipraw = sm + OFF_EE;   // 12288 floats (EE+F1 regions)
    const float* s_wopraw = sm + OFF_H1;   // 4096 floats
    const int b = blockIdx.x;
    const int tid = threadIdx.x;

    // G0: prefetch w1 + w2
    {
        const uint4* s1 = (const uint4*)w1;
        const uint4* s2 = (const uint4*)w2;
        unsigned d1 = smem_u32(sm + OFF_H1);
        unsigned d2 = smem_u32(sm + OFF_Q);
        #pragma unroll
        for (int v = 0; v < 2; v++) {
            int idx = tid + v * 1024;
            cpasync16(d1 + idx * 16, s1 + idx);
            cpasync16(d2 + idx * 16, s2 + idx);
        }
        asm volatile("cp.async.commit_group;" ::: "memory");
    }

    #pragma unroll
    for (int i = tid; i < 4096; i += 1024)
        s_EE[(i >> 6) * 65 + (i & 63)] = EE[i];

    // connectivity: reduce K-split partials, |.|/T, zero diag; output #1
    #pragma unroll
    for (int i = tid; i < 4096; i += 1024) {
        int r = i >> 6, c = i & 63;
        float re = 0.f, im = 0.f;
        #pragma unroll
        for (int sp = 0; sp < KSPLIT; sp++) {
            const float* G = g_G2 + ((size_t)(sp * B_SZ + b)) * 8192;
            re += G[r * 64 + c];
            im += G[(64 + r) * 64 + c];
        }
        float v = (r == c) ? 0.f : sqrtf(re * re + im * im) * (1.f / (float)T_SZ);
        s_conn[r * 65 + c] = v;
        out[(size_t)b * 4096 + i] = v;
    }
    asm volatile("cp.async.wait_group 0;" ::: "memory");
    __syncthreads();

    // F1 = EE @ w1 (w1 from smem)
    const float4* b1v = (const float4*)b1;
    #pragma unroll
    for (int it = 0; it < 2; it++) {
        int slot = tid + it * 1024;
        int r = slot >> 5, f4 = slot & 31;
        float4 acc = make_float4(0.f, 0.f, 0.f, 0.f);
        #pragma unroll 8
        for (int e = 0; e < 64; e++) {
            float4 w = ((const float4*)s_w1raw)[e * 32 + f4];
            float sc = s_EE[r * 65 + e];
            acc.x += sc * w.x; acc.y += sc * w.y; acc.z += sc * w.z; acc.w += sc * w.w;
        }
        ((float4*)&s_F1[r * 132])[f4] = acc;
    }
    __syncthreads();

    // h1 = relu(conn @ F1 + b1)  (overwrites w1 region)
    #pragma unroll
    for (int it = 0; it < 2; it++) {
        int slot = tid + it * 1024;
        int r = slot >> 5, f4 = slot & 31;
        float4 acc = b1v[f4];
        #pragma unroll 8
        for (int j = 0; j < 64; j++) {
            float4 fv = ((const float4*)&s_F1[j * 132])[f4];
            float cn = s_conn[r * 65 + j];
            acc.x += cn * fv.x; acc.y += cn * fv.y; acc.z += cn * fv.z; acc.w += cn * fv.w;
        }
        acc.x = fmaxf(acc.x, 0.f); acc.y = fmaxf(acc.y, 0.f);
        acc.z = fmaxf(acc.z, 0.f); acc.w = fmaxf(acc.w, 0.f);
        ((float4*)&s_h1[r * 132])[f4] = acc;
    }
    __syncthreads();

    // G1: prefetch Wip into EE+F1 (both dead now)
    {
        const uint4* sw = (const uint4*)Wip;
        unsigned dw = smem_u32(sm + OFF_EE);
        #pragma unroll
        for (int v = 0; v < 3; v++) {
            int idx = tid + v * 1024;
            cpasync16(dw + idx * 16, sw + idx);
        }
        asm volatile("cp.async.commit_group;" ::: "memory");
    }

    // t2 = h1 @ w2 (w2 from smem)
    {
        int r = tid >> 4, e4 = tid & 15;
        float4 acc = make_float4(0.f, 0.f, 0.f, 0.f);
        #pragma unroll 8
        for (int f = 0; f < 128; f++) {
            float4 w = ((const float4*)s_w2raw)[f * 16 + e4];
            float h = s_h1[r * 132 + f];
            acc.x += h * w.x; acc.y += h * w.y; acc.z += h * w.z; acc.w += h * w.w;
        }
        ((float4*)&s_t2[r * 68])[e4] = acc;
    }
    __syncthreads();

    // G2: prefetch Wop into h1 region (dead now)
    {
        const uint4* sw = (const uint4*)Wop;
        unsigned dw = smem_u32(sm + OFF_H1);
        cpasync16(dw + tid * 16, sw + tid);
        asm volatile("cp.async.commit_group;" ::: "memory");
    }

    // h2 = conn @ t2 + b2 ; output #3
    {
        const float4* b2v = (const float4*)b2;
        int r = tid >> 4, e4 = tid & 15;
        float4 acc = b2v[e4];
        #pragma unroll 8
        for (int j = 0; j < 64; j++) {
            float4 t4 = ((const float4*)&s_t2[j * 68])[e4];
            float cn = s_conn[r * 65 + j];
            acc.x += cn * t4.x; acc.y += cn * t4.y; acc.z += cn * t4.z; acc.w += cn * t4.w;
        }
        s_h2[r * 65 + 4 * e4]     = acc.x;
        s_h2[r * 65 + 4 * e4 + 1] = acc.y;
        s_h2[r * 65 + 4 * e4 + 2] = acc.z;
        s_h2[r * 65 + 4 * e4 + 3] = acc.w;
        ((float4*)(out + (size_t)(2 * B_SZ * 4096) + (size_t)b * 4096 + r * 64))[e4] = acc;
    }
    asm volatile("cp.async.wait_group 1;" ::: "memory");
    __syncthreads();

    // qkv = h2 @ Wip^T + bip (raw Wip from smem; warp-uniform broadcast loads)
    {
        const float4* bipv = (const float4*)bip;
        #pragma unroll
        for (int it = 0; it < 3; it++) {
            int slot = tid + it * 1024;
            int n = slot & 63, m4 = slot >> 6;
            float4 acc = bipv[m4];
            #pragma unroll 8
            for (int e = 0; e < 64; e++) {
                float h = s_h2[n * 65 + e];
                acc.x += h * s_wipraw[(4 * m4 + 0) * 64 + e];
                acc.y += h * s_wipraw[(4 * m4 + 1) * 64 + e];
                acc.z += h * s_wipraw[(4 * m4 + 2) * 64 + e];
                acc.w += h * s_wipraw[(4 * m4 + 3) * 64 + e];
            }
            float* dst = (m4 < 16) ? s_q : (m4 < 32 ? s_k : s_v);
            int c4 = m4 & 15;
            ((float4*)&dst[n * 68])[c4] = acc;
        }
    }
    asm volatile("cp.async.wait_group 0;" ::: "memory");
    __syncthreads();

    // attention: 512 tasks = (head, row); two-pass softmax with __expf
    if (tid < 512) {
        int h = tid >> 6, qi = tid & 63;
        const float inv_sqrt_d = 0.35355339059327373f;
        float qv[8];
        #pragma unroll
        for (int d = 0; d < 8; d++) qv[d] = s_q[qi * 68 + h * 8 + d];
        float mx = -1e30f;
        for (int k = 0; k < 64; k++) {
            float sc = 0.f;
            #pragma unroll
            for (int d = 0; d < 8; d++) sc += qv[d] * s_k[k * 68 + h * 8 + d];
            mx = fmaxf(mx, sc * inv_sqrt_d);
        }
        float denom = 0.f, acc[8] = {};
        for (int k = 0; k < 64; k++) {
            float sc = 0.f;
            #pragma unroll
            for (int d = 0; d < 8; d++) sc += qv[d] * s_k[k * 68 + h * 8 + d];
            float p = __expf(sc * inv_sqrt_d - mx);
            denom += p;
            #pragma unroll
            for (int d = 0; d < 8; d++) acc[d] += p * s_v[k * 68 + h * 8 + d];
        }
        float rinv = 1.f / denom;
        __syncthreads();
        #pragma unroll
        for (int d = 0; d < 8; d++) s_ao[qi * 65 + h * 8 + d] = acc[d] * rinv;
    } else {
        __syncthreads();
    }
    __syncthreads();

    // graph_features = ao @ Wop^T + bop (raw Wop; broadcast loads); output #2
    {
        const float4* bopv = (const float4*)bop;
        int n = tid & 63, e4 = tid >> 6;
        float4 acc = bopv[e4];
        #pragma unroll 8
        for (int f = 0; f < 64; f++) {
            float av = s_ao[n * 65 + f];
            acc.x += av * s_wopraw[(4 * e4 + 0) * 64 + f];
            acc.y += av * s_wopraw[(4 * e4 + 1) * 64 + f];
            acc.z += av * s_wopraw[(4 * e4 + 2) * 64 + f];
            acc.w += av * s_wopraw[(4 * e4 + 3) * 64 + f];
        }
        ((float4*)(out + (size_t)(B_SZ * 4096) + (size_t)b * 4096 + n * 64 + 4 * e4))[0] = acc;
    }
}

// ---------------- launch ----------------
extern "C" void kernel_launch(void* const* d_in, const int* in_sizes, int n_in,
                              void* d_out, int out_size) {
    const float* x   = (const float*)d_in[0];
    const float* EE  = (const float*)d_in[1];
    const float* w1  = (const float*)d_in[2];
    const float* b1  = (const float*)d_in[3];
    const float* w2  = (const float*)d_in[4];
    const float* b2  = (const float*)d_in[5];
    const float* Wip = (const float*)d_in[6];
    const float* bip = (const float*)d_in[7];
    const float* Wop = (const float*)d_in[8];
    const float* bop = (const float*)d_in[9];
    float* out = (float*)d_out;

    cudaFuncSetAttribute(fft_hilbert_kernel,
                         cudaFuncAttributeMaxDynamicSharedMemorySize, 65536);
    cudaFuncSetAttribute(gram_mma_kernel,
                         cudaFuncAttributeMaxDynamicSharedMemorySize, GRAM_SMEM);
    cudaFuncSetAttribute(tail_kernel,
                         cudaFuncAttributeMaxDynamicSharedMemorySize, TAIL_FLOATS * 4);

    twiddle_init_kernel<<<16, 256>>>();
    fft_hilbert_kernel<<<B_SZ * C_SZ / 2, 512, 65536>>>(x);
    gram_mma_kernel<<<dim3(KSPLIT, B_SZ), 256, GRAM_SMEM>>>();
    tail_kernel<<<B_SZ, 1024, TAIL_FLOATS * 4>>>(EE, w1, b1, w2, b2,
                                                 Wip, bip, Wop, bop, out);
}

// round 9
// speedup vs baseline: 2.3272x; 1.0744x over previous
#include <cuda_runtime.h>
#include <cuda_bf16.h>
#include <math.h>

#define B_SZ 32
#define C_SZ 64
#define T_SZ 8192
#define KSPLIT 8
#define NCH 32               // 32-sample k-chunks per CTA (8192/8 splits/32)
#define NSTG 4
#define STG_B 16384          // per stage: hi tile 8KB + lo tile 8KB
#define GRAM_SMEM (NSTG * STG_B)

// ---------------- scratch (static device globals; no allocation) ----------------
// de-interleaved bf16 planes: [b][c][r|i][8192] (hi and lo arrays)
__device__ __nv_bfloat16 g_Zhi[(size_t)B_SZ * 64 * 2 * 8192];   // 67 MB
__device__ __nv_bfloat16 g_Zlo[(size_t)B_SZ * 64 * 2 * 8192];   // 67 MB
__device__ float  g_G2[(size_t)KSPLIT * B_SZ * 128 * 64]; // rows 0-63: Re, 64-127: R=Zi.Zr^T
__device__ float2 g_tw[T_SZ / 2];                         // exp(-2pi i k/N)

__device__ __forceinline__ float2 cmul(float2 a, float2 b) {
    return make_float2(a.x * b.x - a.y * b.y, a.x * b.y + a.y * b.x);
}
__device__ __forceinline__ float2 cadd(float2 a, float2 b) { return make_float2(a.x + b.x, a.y + b.y); }
__device__ __forceinline__ float2 csub(float2 a, float2 b) { return make_float2(a.x - b.x, a.y - b.y); }
__device__ __forceinline__ int SW(int i) { return i ^ ((i >> 5) & 31); }

__device__ __forceinline__ unsigned smem_u32(const void* p) {
    unsigned a;
    asm("{ .reg .u64 t; cvta.to.shared.u64 t, %1; cvt.u32.u64 %0, t; }" : "=r"(a) : "l"(p));
    return a;
}
__device__ __forceinline__ void cpasync16(unsigned dst, const void* src) {
    asm volatile("cp.async.cg.shared.global [%0], [%1], 16;" :: "r"(dst), "l"(src) : "memory");
}
__device__ __forceinline__ void ldsm4(unsigned& r0, unsigned& r1, unsigned& r2, unsigned& r3,
                                      unsigned addr) {
    asm volatile("ldmatrix.sync.aligned.m8n8.x4.shared.b16 {%0,%1,%2,%3}, [%4];"
                 : "=r"(r0), "=r"(r1), "=r"(r2), "=r"(r3) : "r"(addr));
}
__device__ __forceinline__ void mma16816(float* c, unsigned a0, unsigned a1, unsigned a2,
                                         unsigned a3, unsigned b0, unsigned b1) {
    asm volatile("mma.sync.aligned.m16n8k16.row.col.f32.bf16.bf16.f32 "
                 "{%0,%1,%2,%3}, {%4,%5,%6,%7}, {%8,%9}, {%0,%1,%2,%3};"
                 : "+f"(c[0]), "+f"(c[1]), "+f"(c[2]), "+f"(c[3])
                 : "r"(a0), "r"(a1), "r"(a2), "r"(a3), "r"(b0), "r"(b1));
}

#define RC8 0.70710678118654752f

// ---- forward radix-8 (DIF stages st, st+1, st+2). d = 2^(10-st). ----
__device__ __forceinline__ void fwd8(float2* s, int g, int st) {
    const int d = 1 << (10 - st);
    const int j = g & (d - 1);
    const int i = ((g >> (10 - st)) << (13 - st)) + j;
    float2 W1 = g_tw[j << st];
    float2 W2 = g_tw[j << (st + 1)];
    float2 W4 = g_tw[j << (st + 2)];
    float2 u0 = s[SW(i)],       u1 = s[SW(i + d)];
    float2 u2 = s[SW(i + 2*d)], u3 = s[SW(i + 3*d)];
    float2 u4 = s[SW(i + 4*d)], u5 = s[SW(i + 5*d)];
    float2 u6 = s[SW(i + 6*d)], u7 = s[SW(i + 7*d)];
    float2 a0 = cadd(u0, u4), a1 = cadd(u1, u5), a2 = cadd(u2, u6), a3 = cadd(u3, u7);
    float2 W1E  = make_float2(RC8 * (W1.x + W1.y), RC8 * (W1.y - W1.x));
    float2 W1m  = make_float2(W1.y, -W1.x);
    float2 W1Em = make_float2(W1E.y, -W1E.x);
    float2 b0 = cmul(csub(u0, u4), W1);
    float2 b1 = cmul(csub(u1, u5), W1E);
    float2 b2 = cmul(csub(u2, u6), W1m);
    float2 b3 = cmul(csub(u3, u7), W1Em);
    float2 W2m = make_float2(W2.y, -W2.x);
    float2 A0 = cadd(a0, a2), A2 = cmul(csub(a0, a2), W2);
    float2 A1 = cadd(a1, a3), A3 = cmul(csub(a1, a3), W2m);
    float2 B0 = cadd(b0, b2), B2 = cmul(csub(b0, b2), W2);
    float2 B1 = cadd(b1, b3), B3 = cmul(csub(b1, b3), W2m);
    s[SW(i)]       = cadd(A0, A1);
    s[SW(i + d)]   = cmul(csub(A0, A1), W4);
    s[SW(i + 2*d)] = cadd(A2, A3);
    s[SW(i + 3*d)] = cmul(csub(A2, A3), W4);
    s[SW(i + 4*d)] = cadd(B0, B1);
    s[SW(i + 5*d)] = cmul(csub(B0, B1), W4);
    s[SW(i + 6*d)] = cadd(B2, B3);
    s[SW(i + 7*d)] = cmul(csub(B2, B3), W4);
}

// ---- inverse radix-8 (DIT stages st, st+1, st+2). e = 2^st. ----
__device__ __forceinline__ void inv8(float2* s, int q, int st) {
    const int e = 1 << st;
    const int j = q & (e - 1);
    const int i = ((q >> st) << (st + 3)) + j;
    float2 c1 = g_tw[j << (12 - st)]; float2 W1 = make_float2(c1.x, -c1.y);
    float2 c2 = g_tw[j << (11 - st)]; float2 W2 = make_float2(c2.x, -c2.y);
    float2 c4 = g_tw[j << (10 - st)]; float2 W4 = make_float2(c4.x, -c4.y);
    float2 u0 = s[SW(i)],       u1 = s[SW(i + e)];
    float2 u2 = s[SW(i + 2*e)], u3 = s[SW(i + 3*e)];
    float2 u4 = s[SW(i + 4*e)], u5 = s[SW(i + 5*e)];
    float2 u6 = s[SW(i + 6*e)], u7 = s[SW(i + 7*e)];
    float2 v;
    v = cmul(u1, W1); float2 t0 = cadd(u0, v), t1 = csub(u0, v);
    v = cmul(u3, W1); float2 t2 = cadd(u2, v), t3 = csub(u2, v);
    v = cmul(u5, W1); float2 t4 = cadd(u4, v), t5 = csub(u4, v);
    v = cmul(u7, W1); float2 t6 = cadd(u6, v), t7 = csub(u6, v);
    float2 W2i = make_float2(-W2.y, W2.x);
    v = cmul(t2, W2);  float2 s0 = cadd(t0, v), s2 = csub(t0, v);
    v = cmul(t3, W2i); float2 s1 = cadd(t1, v), s3 = csub(t1, v);
    v = cmul(t6, W2);  float2 s4 = cadd(t4, v), s6 = csub(t4, v);
    v = cmul(t7, W2i); float2 s5 = cadd(t5, v), s7 = csub(t5, v);
    float2 W4E  = make_float2(RC8 * (W4.x - W4.y), RC8 * (W4.x + W4.y));
    float2 W4i  = make_float2(-W4.y, W4.x);
    float2 W4Ei = make_float2(-W4E.y, W4E.x);
    v = cmul(s4, W4);   s[SW(i)]       = cadd(s0, v); s[SW(i + 4*e)] = csub(s0, v);
    v = cmul(s5, W4E);  s[SW(i + e)]   = cadd(s1, v); s[SW(i + 5*e)] = csub(s1, v);
    v = cmul(s6, W4i);  s[SW(i + 2*e)] = cadd(s2, v); s[SW(i + 6*e)] = csub(s2, v);
    v = cmul(s7, W4Ei); s[SW(i + 3*e)] = cadd(s3, v); s[SW(i + 7*e)] = csub(s3, v);
}

// ---------------- twiddle init ----------------
__global__ void twiddle_init_kernel() {
    int i = blockIdx.x * blockDim.x + threadIdx.x;
    if (i < T_SZ / 2) {
        double ang = -2.0 * 3.14159265358979323846 * (double)i / (double)T_SZ;
        g_tw[i] = make_float2((float)cos(ang), (float)sin(ang));
    }
}

// ---------------- FFT (pair-packed real channels), radix-8 trips -----------------
__global__ __launch_bounds__(512) void fft_hilbert_kernel(const float* __restrict__ x) {
    extern __shared__ float2 s[];   // 64 KB
    const int blk = blockIdx.x;                 // 0..1023
    const int b = blk >> 5, cp = blk & 31;
    const float* __restrict__ xa = x + ((size_t)b * C_SZ + 2 * cp) * T_SZ;
    const float* __restrict__ xb = xa + T_SZ;
    const int tid = threadIdx.x;

    // trip 0: load z + forward stages 0,1,2 (radix-8; d=1024, j=i=g)
    #pragma unroll
    for (int rr = 0; rr < 2; rr++) {
        int g = tid + rr * 512;
        float2 u0 = make_float2(xa[g],        xb[g]);
        float2 u1 = make_float2(xa[g + 1024], xb[g + 1024]);
        float2 u2 = make_float2(xa[g + 2048], xb[g + 2048]);
        float2 u3 = make_float2(xa[g + 3072], xb[g + 3072]);
        float2 u4 = make_float2(xa[g + 4096], xb[g + 4096]);
        float2 u5 = make_float2(xa[g + 5120], xb[g + 5120]);
        float2 u6 = make_float2(xa[g + 6144], xb[g + 6144]);
        float2 u7 = make_float2(xa[g + 7168], xb[g + 7168]);
        float2 W1 = g_tw[g], W2 = g_tw[2 * g], W4 = g_tw[4 * g];
        float2 a0 = cadd(u0, u4), a1 = cadd(u1, u5), a2 = cadd(u2, u6), a3 = cadd(u3, u7);
        float2 W1E  = make_float2(RC8 * (W1.x + W1.y), RC8 * (W1.y - W1.x));
        float2 W1m  = make_float2(W1.y, -W1.x);
        float2 W1Em = make_float2(W1E.y, -W1E.x);
        float2 b0 = cmul(csub(u0, u4), W1);
        float2 b1 = cmul(csub(u1, u5), W1E);
        float2 b2 = cmul(csub(u2, u6), W1m);
        float2 b3 = cmul(csub(u3, u7), W1Em);
        float2 W2m = make_float2(W2.y, -W2.x);
        float2 A0 = cadd(a0, a2), A2 = cmul(csub(a0, a2), W2);
        float2 A1 = cadd(a1, a3), A3 = cmul(csub(a1, a3), W2m);
        float2 B0 = cadd(b0, b2), B2 = cmul(csub(b0, b2), W2);
        float2 B1 = cadd(b1, b3), B3 = cmul(csub(b1, b3), W2m);
        s[SW(g)]        = cadd(A0, A1);
        s[SW(g + 1024)] = cmul(csub(A0, A1), W4);
        s[SW(g + 2048)] = cadd(A2, A3);
        s[SW(g + 3072)] = cmul(csub(A2, A3), W4);
        s[SW(g + 4096)] = cadd(B0, B1);
        s[SW(g + 5120)] = cmul(csub(B0, B1), W4);
        s[SW(g + 6144)] = cadd(B2, B3);
        s[SW(g + 7168)] = cmul(csub(B2, B3), W4);
    }
    __syncthreads();

    // forward trips st = 3, 6, 9
    #pragma unroll
    for (int st = 3; st < 12; st += 3) {
        #pragma unroll
        for (int rr = 0; rr < 2; rr++) fwd8(s, tid + rr * 512, st);
        __syncthreads();
    }

    // fused trip: forward stage 12 + Hilbert mask + inverse stages 0,1,2
    // (inverse st=0 radix-8 spans 8 consecutive elements = 4 fwd-st12 pairs;
    //  all inverse twiddles are unit constants here)
    #pragma unroll
    for (int rr = 0; rr < 2; rr++) {
        int q = tid + rr * 512;           // 0..1023
        int i = q * 8;
        float2 e[8];
        #pragma unroll
        for (int k2 = 0; k2 < 4; k2++) {
            int t = 4 * q + k2;           // pair index
            float2 u = s[SW(i + 2 * k2)], vv = s[SW(i + 2 * k2 + 1)];
            float2 a = cadd(u, vv), d = csub(u, vv);
            if (t == 0) { e[0] = a; e[1] = d; }
            else {
                e[2 * k2]     = make_float2(2.f * a.x, 2.f * a.y);
                e[2 * k2 + 1] = make_float2(0.f, 0.f);
            }
        }
        float2 t0 = cadd(e[0], e[1]), t1 = csub(e[0], e[1]);
        float2 t2 = cadd(e[2], e[3]), t3 = csub(e[2], e[3]);
        float2 t4 = cadd(e[4], e[5]), t5 = csub(e[4], e[5]);
        float2 t6 = cadd(e[6], e[7]), t7 = csub(e[6], e[7]);
        float2 it3 = make_float2(-t3.y, t3.x);
        float2 it7 = make_float2(-t7.y, t7.x);
        float2 s0 = cadd(t0, t2), s2 = csub(t0, t2);
        float2 s1 = cadd(t1, it3), s3 = csub(t1, it3);
        float2 s4 = cadd(t4, t6), s6 = csub(t4, t6);
        float2 s5 = cadd(t5, it7), s7 = csub(t5, it7);
        float2 v5 = make_float2(RC8 * (s5.x - s5.y), RC8 * (s5.x + s5.y));
        float2 v6 = make_float2(-s6.y, s6.x);
        float2 v7 = make_float2(-RC8 * (s7.x + s7.y), RC8 * (s7.x - s7.y));
        s[SW(i)]     = cadd(s0, s4); s[SW(i + 4)] = csub(s0, s4);
        s[SW(i + 1)] = cadd(s1, v5); s[SW(i + 5)] = csub(s1, v5);
        s[SW(i + 2)] = cadd(s2, v6); s[SW(i + 6)] = csub(s2, v6);
        s[SW(i + 3)] = cadd(s3, v7); s[SW(i + 7)] = csub(s3, v7);
    }
    __syncthreads();

    // inverse trips st = 3, 6, 9
    #pragma unroll
    for (int st = 3; st < 12; st += 3) {
        #pragma unroll
        for (int rr = 0; rr < 2; rr++) inv8(s, tid + rr * 512, st);
        __syncthreads();
    }

    // fused: final inverse stage (12) + 1/N + un-pack + normalize + plane stores
    const size_t pbase0 = ((size_t)(b * C_SZ + 2 * cp)) * 16384;   // channel a: [r|i]
    const size_t pbase1 = pbase0 + 16384;                          // channel b
    const float invN = 1.0f / 8192.0f;
    #pragma unroll
    for (int rr = 0; rr < 8; rr++) {
        int t = tid + rr * 512;
        float2 tm = g_tw[t];
        float2 w = make_float2(tm.x, -tm.y);
        float2 u = s[SW(t)];
        float2 v = cmul(s[SW(t + 4096)], w);
        float2 Wv[2] = { cadd(u, v), csub(u, v) };
        int ti[2] = { t, t + 4096 };
        #pragma unroll
        for (int e = 0; e < 2; e++) {
            int idx = ti[e];
            float Wr = Wv[e].x * invN, Wi = Wv[e].y * invN;
            float av = xa[idx], bv = xb[idx];
            float zr[2] = { av, bv };
            float zi[2] = { Wi - bv, av - Wr };
            size_t pb[2] = { pbase0, pbase1 };
            #pragma unroll
            for (int ch = 0; ch < 2; ch++) {
                float inv = rsqrtf(zr[ch] * zr[ch] + zi[ch] * zi[ch]);
                float r = zr[ch] * inv, i2 = zi[ch] * inv;
                __nv_bfloat16 rh = __float2bfloat16(r);
                __nv_bfloat16 ih = __float2bfloat16(i2);
                __nv_bfloat16 rl = __float2bfloat16(r - __bfloat162float(rh));
                __nv_bfloat16 il = __float2bfloat16(i2 - __bfloat162float(ih));
                g_Zhi[pb[ch] + idx]        = rh;
                g_Zhi[pb[ch] + 8192 + idx] = ih;
                g_Zlo[pb[ch] + idx]        = rl;
                g_Zlo[pb[ch] + 8192 + idx] = il;
            }
        }
    }
}

// ---------------- gram via HMMA: Re = Zr.Zr^T + Zi.Zi^T, R = Zi.Zr^T -------------
// grid (KSPLIT, B), 256 thr = 8 warps. Warps 0-3: Re rows 16w (2 planes x 3 hi/lo
// passes). Warps 4-7: R rows 16(w-4) (A=Zi, B=Zr, 3 passes). Per-SMSP MMA issue
// is uniform (warp w pairs with w+4). Stage rows: [Zr 64B | Zi 64B] = 128B SW128.
__global__ __launch_bounds__(256) void gram_mma_kernel() {
    extern __shared__ __align__(1024) char gsm[];
    const unsigned sbase = smem_u32(gsm);
    const int split = blockIdx.x, b = blockIdx.y;
    const int tid = threadIdx.x, lane = tid & 31, w = tid >> 5;
    const int mrow = 16 * (w & 3);
    const bool isIm = (w >= 4);

    const char* hi0 = (const char*)g_Zhi + (size_t)b * 64 * 32768 + (size_t)split * 2048;
    const char* lo0 = (const char*)g_Zlo + (size_t)b * 64 * 32768 + (size_t)split * 2048;

    // cp.async slots: 512 16B units per tile (hi or lo), 2 per thread per tile
    unsigned swo[2]; size_t gofs[2];
    #pragma unroll
    for (int v = 0; v < 2; v++) {
        int u = v * 256 + tid;
        int rw = u >> 3, seg = u & 7;
        unsigned off = rw * 128 + seg * 16;
        swo[v] = off ^ ((off >> 3) & 0x70);
        gofs[v] = (size_t)rw * 32768 + (seg & 3) * 16 + ((seg >= 4) ? 16384 : 0);
    }

    const int lr = lane & 15, lcb = lane >> 4;
    unsigned a_off0 = (mrow + lr) * 128 + lcb * 16;
    unsigned aX = ((a_off0 >> 3) & 0x70);
    unsigned b_off0[4], bX[4];
    #pragma unroll
    for (int q = 0; q < 4; q++) {
        b_off0[q] = (16 * q + lr) * 128 + lcb * 16;
        bX[q] = ((b_off0[q] >> 3) & 0x70);
    }

    float c[8][4] = {};

    #pragma unroll
    for (int j = 0; j < 3; j++) {
        unsigned st = sbase + j * STG_B;
        #pragma unroll
        for (int v = 0; v < 2; v++) {
            cpasync16(st + swo[v],        hi0 + gofs[v] + j * 64);
            cpasync16(st + 8192 + swo[v], lo0 + gofs[v] + j * 64);
        }
        asm volatile("cp.async.commit_group;" ::: "memory");
    }

    for (int i = 0; i < NCH; i++) {
        int jn = i + 3;
        if (jn < NCH) {
            unsigned st = sbase + (jn % NSTG) * STG_B;
            #pragma unroll
            for (int v = 0; v < 2; v++) {
                cpasync16(st + swo[v],        hi0 + gofs[v] + (size_t)jn * 64);
                cpasync16(st + 8192 + swo[v], lo0 + gofs[v] + (size_t)jn * 64);
            }
            asm volatile("cp.async.commit_group;" ::: "memory");
            asm volatile("cp.async.wait_group 3;" ::: "memory");
        } else {
            asm volatile("cp.async.wait_group 0;" ::: "memory");
        }
        __syncthreads();

        const unsigned sb = sbase + (i % NSTG) * STG_B;
        const int npl = isIm ? 1 : 2;
        #pragma unroll
        for (int ks = 0; ks < 2; ks++) {
            #pragma unroll
            for (int p = 0; p < 2; p++) {
                if (p >= npl) break;
                int acol = ks * 32 + (isIm ? 64 : p * 64);   // A plane: Re->p, R->Zi
                int bcol = ks * 32 + (isIm ? 0  : p * 64);   // B plane: Re->p, R->Zr
                unsigned ah0, ah1, ah2, ah3, al0, al1, al2, al3;
                unsigned aa = sb + ((a_off0 + acol) ^ aX);
                ldsm4(ah0, ah1, ah2, ah3, aa);
                ldsm4(al0, al1, al2, al3, aa + 8192);
                #pragma unroll
                for (int q = 0; q < 4; q++) {
                    unsigned bh0, bh1, bh2, bh3, bl0, bl1, bl2, bl3;
                    unsigned ba = sb + ((b_off0[q] + bcol) ^ bX[q]);
                    ldsm4(bh0, bh1, bh2, bh3, ba);
                    ldsm4(bl0, bl1, bl2, bl3, ba + 8192);
                    mma16816(c[2 * q],     ah0, ah1, ah2, ah3, bh0, bh2);
                    mma16816(c[2 * q],     ah0, ah1, ah2, ah3, bl0, bl2);
                    mma16816(c[2 * q],     al0, al1, al2, al3, bh0, bh2);
                    mma16816(c[2 * q + 1], ah0, ah1, ah2, ah3, bh1, bh3);
                    mma16816(c[2 * q + 1], ah0, ah1, ah2, ah3, bl1, bl3);
                    mma16816(c[2 * q + 1], al0, al1, al2, al3, bh1, bh3);
                }
            }
        }
        __syncthreads();
    }

    float* G = g_G2 + ((size_t)(split * B_SZ + b)) * 8192;
    int rbase = (isIm ? 64 : 0) + mrow + (lane >> 2);
    #pragma unroll
    for (int j = 0; j < 8; j++) {
        int col = 8 * j + 2 * (lane & 3);
        G[rbase * 64 + col]           = c[j][0];
        G[rbase * 64 + col + 1]       = c[j][1];
        G[(rbase + 8) * 64 + col]     = c[j][2];
        G[(rbase + 8) * 64 + col + 1] = c[j][3];
    }
}

// ---------------- tail: conn finalize + GCN + MHA. One block/batch, 1024 thr ----
#define OFF_EE   4160
#define OFF_F1   8320
#define OFF_H1   16768
#define OFF_T2   25216
#define OFF_H2   29568
#define OFF_Q    33728
#define OFF_K    38080
#define OFF_V    42432
#define TAIL_FLOATS 46784

__global__ __launch_bounds__(1024) void tail_kernel(
    const float* __restrict__ EE,  const float* __restrict__ w1, const float* __restrict__ b1,
    const float* __restrict__ w2,  const float* __restrict__ b2,
    const float* __restrict__ Wip, const float* __restrict__ bip,
    const float* __restrict__ Wop, const float* __restrict__ bop,
    float* __restrict__ out)
{
    extern __shared__ float sm[];
    float* s_conn = sm;
    float* s_EE  = sm + OFF_EE;
    float* s_F1  = sm + OFF_F1;
    float* s_h1  = sm + OFF_H1;
    float* s_t2  = sm + OFF_T2;
    float* s_h2  = sm + OFF_H2;
    float* s_q   = sm + OFF_Q;
    float* s_k   = sm + OFF_K;
    float* s_v   = sm + OFF_V;
    float* s_ao  = s_conn;                 // conn dead after h2
    float* s_R   = s_F1;                   // R-sum [64][65] during conn stage
    const float* s_w1raw  = sm + OFF_H1;   // 8192 floats
    const float* s_w2raw  = sm + OFF_Q;    // 8192 floats (q+k regions)
    const float* s_wipraw = sm + OFF_EE;   // 12288 floats (EE+F1 regions)
    const float* s_wopraw = sm + OFF_H1;   // 4096 floats
    const int b = blockIdx.x;
    const int tid = threadIdx.x;

    // G0: prefetch w1 + w2
    {
        const uint4* s1 = (const uint4*)w1;
        const uint4* s2 = (const uint4*)w2;
        unsigned d1 = smem_u32(sm + OFF_H1);
        unsigned d2 = smem_u32(sm + OFF_Q);
        #pragma unroll
        for (int v = 0; v < 2; v++) {
            int idx = tid + v * 1024;
            cpasync16(d1 + idx * 16, s1 + idx);
            cpasync16(d2 + idx * 16, s2 + idx);
        }
        asm volatile("cp.async.commit_group;" ::: "memory");
    }

    #pragma unroll
    for (int i = tid; i < 4096; i += 1024)
        s_EE[(i >> 6) * 65 + (i & 63)] = EE[i];

    // connectivity: reduce K-split partials. Re direct; Im = R - R^T via smem.
    float reacc[4];
    #pragma unroll
    for (int v = 0; v < 4; v++) {
        int i = tid + v * 1024;
        int r = i >> 6, cc = i & 63;
        float re = 0.f, rsum = 0.f;
        #pragma unroll
        for (int sp = 0; sp < KSPLIT; sp++) {
            const float* G = g_G2 + ((size_t)(sp * B_SZ + b)) * 8192;
            re   += G[r * 64 + cc];
            rsum += G[(64 + r) * 64 + cc];
        }
        reacc[v] = re;
        s_R[r * 65 + cc] = rsum;
    }
    __syncthreads();
    #pragma unroll
    for (int v = 0; v < 4; v++) {
        int i = tid + v * 1024;
        int r = i >> 6, cc = i & 63;
        float im = s_R[r * 65 + cc] - s_R[cc * 65 + r];
        float re = reacc[v];
        float val = (r == cc) ? 0.f : sqrtf(re * re + im * im) * (1.f / (float)T_SZ);
        s_conn[r * 65 + cc] = val;
        out[(size_t)b * 4096 + i] = val;
    }
    asm volatile("cp.async.wait_group 0;" ::: "memory");
    __syncthreads();

    // F1 = EE @ w1 (w1 from smem)
    const float4* b1v = (const float4*)b1;
    #pragma unroll
    for (int it = 0; it < 2; it++) {
        int slot = tid + it * 1024;
        int r = slot >> 5, f4 = slot & 31;
        float4 acc = make_float4(0.f, 0.f, 0.f, 0.f);
        #pragma unroll 8
        for (int e = 0; e < 64; e++) {
            float4 w = ((const float4*)s_w1raw)[e * 32 + f4];
            float sc = s_EE[r * 65 + e];
            acc.x += sc * w.x; acc.y += sc * w.y; acc.z += sc * w.z; acc.w += sc * w.w;
        }
        ((float4*)&s_F1[r * 132])[f4] = acc;
    }
    __syncthreads();

    // h1 = relu(conn @ F1 + b1)  (overwrites w1 region)
    #pragma unroll
    for (int it = 0; it < 2; it++) {
        int slot = tid + it * 1024;
        int r = slot >> 5, f4 = slot & 31;
        float4 acc = b1v[f4];
        #pragma unroll 8
        for (int j = 0; j < 64; j++) {
            float4 fv = ((const float4*)&s_F1[j * 132])[f4];
            float cn = s_conn[r * 65 + j];
            acc.x += cn * fv.x; acc.y += cn * fv.y; acc.z += cn * fv.z; acc.w += cn * fv.w;
        }
        acc.x = fmaxf(acc.x, 0.f); acc.y = fmaxf(acc.y, 0.f);
        acc.z = fmaxf(acc.z, 0.f); acc.w = fmaxf(acc.w, 0.f);
        ((float4*)&s_h1[r * 132])[f4] = acc;
    }
    __syncthreads();

    // G1: prefetch Wip into EE+F1 (both dead now)
    {
        const uint4* sw = (const uint4*)Wip;
        unsigned dw = smem_u32(sm + OFF_EE);
        #pragma unroll
        for (int v = 0; v < 3; v++) {
            int idx = tid + v * 1024;
            cpasync16(dw + idx * 16, sw + idx);
        }
        asm volatile("cp.async.commit_group;" ::: "memory");
    }

    // t2 = h1 @ w2 (w2 from smem)
    {
        int r = tid >> 4, e4 = tid & 15;
        float4 acc = make_float4(0.f, 0.f, 0.f, 0.f);
        #pragma unroll 8
        for (int f = 0; f < 128; f++) {
            float4 w = ((const float4*)s_w2raw)[f * 16 + e4];
            float h = s_h1[r * 132 + f];
            acc.x += h * w.x; acc.y += h * w.y; acc.z += h * w.z; acc.w += h * w.w;
        }
        ((float4*)&s_t2[r * 68])[e4] = acc;
    }
    __syncthreads();

    // G2: prefetch Wop into h1 region (dead now)
    {
        const uint4* sw = (const uint4*)Wop;
        unsigned dw = smem_u32(sm + OFF_H1);
        cpasync16(dw + tid * 16, sw + tid);
        asm volatile("cp.async.commit_group;" ::: "memory");
    }

    // h2 = conn @ t2 + b2 ; output #3
    {
        const float4* b2v = (const float4*)b2;
        int r = tid >> 4, e4 = tid & 15;
        float4 acc = b2v[e4];
        #pragma unroll 8
        for (int j = 0; j < 64; j++) {
            float4 t4 = ((const float4*)&s_t2[j * 68])[e4];
            float cn = s_conn[r * 65 + j];
            acc.x += cn * t4.x; acc.y += cn * t4.y; acc.z += cn * t4.z; acc.w += cn * t4.w;
        }
        s_h2[r * 65 + 4 * e4]     = acc.x;
        s_h2[r * 65 + 4 * e4 + 1] = acc.y;
        s_h2[r * 65 + 4 * e4 + 2] = acc.z;
        s_h2[r * 65 + 4 * e4 + 3] = acc.w;
        ((float4*)(out + (size_t)(2 * B_SZ * 4096) + (size_t)b * 4096 + r * 64))[e4] = acc;
    }
    asm volatile("cp.async.wait_group 1;" ::: "memory");
    __syncthreads();

    // qkv = h2 @ Wip^T + bip (raw Wip from smem; warp-uniform broadcast loads)
    {
        const float4* bipv = (const float4*)bip;
        #pragma unroll
        for (int it = 0; it < 3; it++) {
            int slot = tid + it * 1024;
            int n = slot & 63, m4 = slot >> 6;
            float4 acc = bipv[m4];
            #pragma unroll 8
            for (int e = 0; e < 64; e++) {
                float h = s_h2[n * 65 + e];
                acc.x += h * s_wipraw[(4 * m4 + 0) * 64 + e];
                acc.y += h * s_wipraw[(4 * m4 + 1) * 64 + e];
                acc.z += h * s_wipraw[(4 * m4 + 2) * 64 + e];
                acc.w += h * s_wipraw[(4 * m4 + 3) * 64 + e];
            }
            float* dst = (m4 < 16) ? s_q : (m4 < 32 ? s_k : s_v);
            int c4 = m4 & 15;
            ((float4*)&dst[n * 68])[c4] = acc;
        }
    }
    asm volatile("cp.async.wait_group 0;" ::: "memory");
    __syncthreads();

    // attention: 512 tasks = (head, row); two-pass softmax with __expf
    if (tid < 512) {
        int h = tid >> 6, qi = tid & 63;
        const float inv_sqrt_d = 0.35355339059327373f;
        float qv[8];
        #pragma unroll
        for (int d = 0; d < 8; d++) qv[d] = s_q[qi * 68 + h * 8 + d];
        float mx = -1e30f;
        for (int k = 0; k < 64; k++) {
            float sc = 0.f;
            #pragma unroll
            for (int d = 0; d < 8; d++) sc += qv[d] * s_k[k * 68 + h * 8 + d];
            mx = fmaxf(mx, sc * inv_sqrt_d);
        }
        float denom = 0.f, acc[8] = {};
        for (int k = 0; k < 64; k++) {
            float sc = 0.f;
            #pragma unroll
            for (int d = 0; d < 8; d++) sc += qv[d] * s_k[k * 68 + h * 8 + d];
            float p = __expf(sc * inv_sqrt_d - mx);
            denom += p;
            #pragma unroll
            for (int d = 0; d < 8; d++) acc[d] += p * s_v[k * 68 + h * 8 + d];
        }
        float rinv = 1.f / denom;
        __syncthreads();
        #pragma unroll
        for (int d = 0; d < 8; d++) s_ao[qi * 65 + h * 8 + d] = acc[d] * rinv;
    } else {
        __syncthreads();
    }
    __syncthreads();

    // graph_features = ao @ Wop^T + bop (raw Wop; broadcast loads); output #2
    {
        const float4* bopv = (const float4*)bop;
        int n = tid & 63, e4 = tid >> 6;
        float4 acc = bopv[e4];
        #pragma unroll 8
        for (int f = 0; f < 64; f++) {
            float av = s_ao[n * 65 + f];
            acc.x += av * s_wopraw[(4 * e4 + 0) * 64 + f];
            acc.y += av * s_wopraw[(4 * e4 + 1) * 64 + f];
            acc.z += av * s_wopraw[(4 * e4 + 2) * 64 + f];
            acc.w += av * s_wopraw[(4 * e4 + 3) * 64 + f];
        }
        ((float4*)(out + (size_t)(B_SZ * 4096) + (size_t)b * 4096 + n * 64 + 4 * e4))[0] = acc;
    }
}

// ---------------- launch ----------------
extern "C" void kernel_launch(void* const* d_in, const int* in_sizes, int n_in,
                              void* d_out, int out_size) {
    const float* x   = (const float*)d_in[0];
    const float* EE  = (const float*)d_in[1];
    const float* w1  = (const float*)d_in[2];
    const float* b1  = (const float*)d_in[3];
    const float* w2  = (const float*)d_in[4];
    const float* b2  = (const float*)d_in[5];
    const float* Wip = (const float*)d_in[6];
    const float* bip = (const float*)d_in[7];
    const float* Wop = (const float*)d_in[8];
    const float* bop = (const float*)d_in[9];
    float* out = (float*)d_out;

    cudaFuncSetAttribute(fft_hilbert_kernel,
                         cudaFuncAttributeMaxDynamicSharedMemorySize, 65536);
    cudaFuncSetAttribute(gram_mma_kernel,
                         cudaFuncAttributeMaxDynamicSharedMemorySize, GRAM_SMEM);
    cudaFuncSetAttribute(tail_kernel,
                         cudaFuncAttributeMaxDynamicSharedMemorySize, TAIL_FLOATS * 4);

    twiddle_init_kernel<<<16, 256>>>();
    fft_hilbert_kernel<<<B_SZ * C_SZ / 2, 512, 65536>>>(x);
    gram_mma_kernel<<<dim3(KSPLIT, B_SZ), 256, GRAM_SMEM>>>();
    tail_kernel<<<B_SZ, 1024, TAIL_FLOATS * 4>>>(EE, w1, b1, w2, b2,
                                                 Wip, bip, Wop, bop, out);
}

// round 10
// speedup vs baseline: 2.4362x; 1.0468x over previous
#include <cuda_runtime.h>
#include <cuda_bf16.h>
#include <math.h>

#define B_SZ 32
#define C_SZ 64
#define T_SZ 8192
#define KSPLIT 8
#define NCH 32               // 32-sample k-chunks per CTA (8192/8 splits/32)
#define NSTG 4
#define STG_B 16384          // per stage: hi tile 8KB + lo tile 8KB
#define GRAM_SMEM (NSTG * STG_B)

// ---------------- scratch (static device globals; no allocation) ----------------
// de-interleaved bf16 planes: [b][c][r|i][8192] (hi and lo arrays)
__device__ __nv_bfloat16 g_Zhi[(size_t)B_SZ * 64 * 2 * 8192];   // 67 MB
__device__ __nv_bfloat16 g_Zlo[(size_t)B_SZ * 64 * 2 * 8192];   // 67 MB
__device__ float  g_G2[(size_t)KSPLIT * B_SZ * 128 * 64]; // rows 0-63: Re, 64-127: R=Zi.Zr^T
__device__ float2 g_tw[T_SZ / 2];                         // exp(-2pi i k/N)

__device__ __forceinline__ float2 cmul(float2 a, float2 b) {
    return make_float2(a.x * b.x - a.y * b.y, a.x * b.y + a.y * b.x);
}
__device__ __forceinline__ float2 cadd(float2 a, float2 b) { return make_float2(a.x + b.x, a.y + b.y); }
__device__ __forceinline__ float2 csub(float2 a, float2 b) { return make_float2(a.x - b.x, a.y - b.y); }
__device__ __forceinline__ float2 cmulc(float2 v, float cx, float cy) {
    return make_float2(v.x * cx - v.y * cy, v.x * cy + v.y * cx);
}
__device__ __forceinline__ int SW(int i) { return i ^ ((i >> 5) & 31); }

__device__ __forceinline__ unsigned smem_u32(const void* p) {
    unsigned a;
    asm("{ .reg .u64 t; cvta.to.shared.u64 t, %1; cvt.u32.u64 %0, t; }" : "=r"(a) : "l"(p));
    return a;
}
__device__ __forceinline__ void cpasync16(unsigned dst, const void* src) {
    asm volatile("cp.async.cg.shared.global [%0], [%1], 16;" :: "r"(dst), "l"(src) : "memory");
}
__device__ __forceinline__ void ldsm4(unsigned& r0, unsigned& r1, unsigned& r2, unsigned& r3,
                                      unsigned addr) {
    asm volatile("ldmatrix.sync.aligned.m8n8.x4.shared.b16 {%0,%1,%2,%3}, [%4];"
                 : "=r"(r0), "=r"(r1), "=r"(r2), "=r"(r3) : "r"(addr));
}
__device__ __forceinline__ void mma16816(float* c, unsigned a0, unsigned a1, unsigned a2,
                                         unsigned a3, unsigned b0, unsigned b1) {
    asm volatile("mma.sync.aligned.m16n8k16.row.col.f32.bf16.bf16.f32 "
                 "{%0,%1,%2,%3}, {%4,%5,%6,%7}, {%8,%9}, {%0,%1,%2,%3};"
                 : "+f"(c[0]), "+f"(c[1]), "+f"(c[2]), "+f"(c[3])
                 : "r"(a0), "r"(a1), "r"(a2), "r"(a3), "r"(b0), "r"(b1));
}

#define RC8 0.70710678118654752f
#define C16 0.92387953251128676f
#define S16 0.38268343236508977f

// ---- radix-16 forward butterfly in registers (DIF stages st..st+3) ----
// u[16] in natural in-group order; twiddles: Wp = tw[j0 << (st+p_log)].
__device__ __forceinline__ void fft16_fwd_regs(float2* u, float2 W1, float2 W2,
                                               float2 W4, float2 W8) {
    // L1: dist 8, twiddle W1 * E16^k (E16 = exp(-i pi/8))
    float2 W1k[8];
    W1k[0] = W1;
    W1k[1] = cmulc(W1,  C16, -S16);
    W1k[2] = cmulc(W1,  RC8, -RC8);
    W1k[3] = cmulc(W1,  S16, -C16);
    W1k[4] = make_float2(W1.y, -W1.x);
    W1k[5] = cmulc(W1, -S16, -C16);
    W1k[6] = cmulc(W1, -RC8, -RC8);
    W1k[7] = cmulc(W1, -C16, -S16);
    #pragma unroll
    for (int k = 0; k < 8; k++) {
        float2 sum = cadd(u[k], u[k + 8]);
        float2 dif = csub(u[k], u[k + 8]);
        u[k] = sum;
        u[k + 8] = cmul(dif, W1k[k]);
    }
    // L2: dist 4, twiddle W2 * E8^k
    float2 W2k[4];
    W2k[0] = W2;
    W2k[1] = cmulc(W2,  RC8, -RC8);
    W2k[2] = make_float2(W2.y, -W2.x);
    W2k[3] = cmulc(W2, -RC8, -RC8);
    #pragma unroll
    for (int g = 0; g < 16; g += 8)
        #pragma unroll
        for (int k = 0; k < 4; k++) {
            float2 sum = cadd(u[g + k], u[g + k + 4]);
            float2 dif = csub(u[g + k], u[g + k + 4]);
            u[g + k] = sum;
            u[g + k + 4] = cmul(dif, W2k[k]);
        }
    // L3: dist 2, twiddle W4 * (-i)^k
    float2 W4k[2] = { W4, make_float2(W4.y, -W4.x) };
    #pragma unroll
    for (int g = 0; g < 16; g += 4)
        #pragma unroll
        for (int k = 0; k < 2; k++) {
            float2 sum = cadd(u[g + k], u[g + k + 2]);
            float2 dif = csub(u[g + k], u[g + k + 2]);
            u[g + k] = sum;
            u[g + k + 2] = cmul(dif, W4k[k]);
        }
    // L4: dist 1, twiddle W8
    #pragma unroll
    for (int g = 0; g < 16; g += 2) {
        float2 sum = cadd(u[g], u[g + 1]);
        float2 dif = csub(u[g], u[g + 1]);
        u[g] = sum;
        u[g + 1] = cmul(dif, W8);
    }
}

// ---- radix-16 inverse butterfly in registers (DIT stages st..st+3) ----
// Twiddles passed ALREADY CONJUGATED: Wp = conj(tw[j0 << (12-st-p_log)]).
__device__ __forceinline__ void fft16_inv_regs(float2* u, float2 W1, float2 W2,
                                               float2 W4, float2 W8) {
    // L1: dist 1, twiddle W1
    #pragma unroll
    for (int g = 0; g < 16; g += 2) {
        float2 v = cmul(u[g + 1], W1);
        float2 t = u[g];
        u[g]     = cadd(t, v);
        u[g + 1] = csub(t, v);
    }
    // L2: dist 2, twiddle W2 * i^k
    float2 W2k[2] = { W2, make_float2(-W2.y, W2.x) };
    #pragma unroll
    for (int g = 0; g < 16; g += 4)
        #pragma unroll
        for (int k = 0; k < 2; k++) {
            float2 v = cmul(u[g + k + 2], W2k[k]);
            float2 t = u[g + k];
            u[g + k]     = cadd(t, v);
            u[g + k + 2] = csub(t, v);
        }
    // L3: dist 4, twiddle W4 * conjE8^k
    float2 W4k[4];
    W4k[0] = W4;
    W4k[1] = cmulc(W4,  RC8, RC8);
    W4k[2] = make_float2(-W4.y, W4.x);
    W4k[3] = cmulc(W4, -RC8, RC8);
    #pragma unroll
    for (int g = 0; g < 16; g += 8)
        #pragma unroll
        for (int k = 0; k < 4; k++) {
            float2 v = cmul(u[g + k + 4], W4k[k]);
            float2 t = u[g + k];
            u[g + k]     = cadd(t, v);
            u[g + k + 4] = csub(t, v);
        }
    // L4: dist 8, twiddle W8 * conjE16^k
    float2 W8k[8];
    W8k[0] = W8;
    W8k[1] = cmulc(W8,  C16, S16);
    W8k[2] = cmulc(W8,  RC8, RC8);
    W8k[3] = cmulc(W8,  S16, C16);
    W8k[4] = make_float2(-W8.y, W8.x);
    W8k[5] = cmulc(W8, -S16, C16);
    W8k[6] = cmulc(W8, -RC8, RC8);
    W8k[7] = cmulc(W8, -C16, S16);
    #pragma unroll
    for (int k = 0; k < 8; k++) {
        float2 v = cmul(u[k + 8], W8k[k]);
        float2 t = u[k];
        u[k]     = cadd(t, v);
        u[k + 8] = csub(t, v);
    }
}

// ---------------- twiddle init ----------------
__global__ void twiddle_init_kernel() {
    int i = blockIdx.x * blockDim.x + threadIdx.x;
    if (i < T_SZ / 2) {
        double ang = -2.0 * 3.14159265358979323846 * (double)i / (double)T_SZ;
        g_tw[i] = make_float2((float)cos(ang), (float)sin(ang));
    }
}

// ---------------- FFT (pair-packed real channels), radix-16 trips ---------------
// 7 smem round-trips: load+fwd(0-3), fwd(4-7), fwd(8-11),
// mid: fwd(12)+Hilbert+inv(0-3), inv(4-7), inv(8-11), inv(12)+unpack+store.
__global__ __launch_bounds__(512) void fft_hilbert_kernel(const float* __restrict__ x) {
    extern __shared__ float2 s[];   // 64 KB
    const int blk = blockIdx.x;                 // 0..1023
    const int b = blk >> 5, cp = blk & 31;
    const float* __restrict__ xa = x + ((size_t)b * C_SZ + 2 * cp) * T_SZ;
    const float* __restrict__ xb = xa + T_SZ;
    const int q = threadIdx.x;                  // 512 threads = 512 groups of 16

    float2 u[16];

    // trip 0: load z + forward stages 0-3 (d=512, j0=i=q)
    #pragma unroll
    for (int k = 0; k < 16; k++)
        u[k] = make_float2(xa[q + 512 * k], xb[q + 512 * k]);
    fft16_fwd_regs(u, g_tw[q], g_tw[2 * q], g_tw[4 * q], g_tw[8 * q]);
    #pragma unroll
    for (int k = 0; k < 16; k++) s[SW(q + 512 * k)] = u[k];
    __syncthreads();

    // trip 1: forward stages 4-7 (d=32)
    {
        const int j0 = q & 31, i = ((q >> 5) << 9) + j0;
        #pragma unroll
        for (int k = 0; k < 16; k++) u[k] = s[SW(i + 32 * k)];
        fft16_fwd_regs(u, g_tw[j0 << 4], g_tw[j0 << 5], g_tw[j0 << 6], g_tw[j0 << 7]);
        __syncthreads();
        #pragma unroll
        for (int k = 0; k < 16; k++) s[SW(i + 32 * k)] = u[k];
    }
    __syncthreads();

    // trip 2: forward stages 8-11 (d=2)
    {
        const int j0 = q & 1, i = ((q >> 1) << 5) + j0;
        #pragma unroll
        for (int k = 0; k < 16; k++) u[k] = s[SW(i + 2 * k)];
        fft16_fwd_regs(u, g_tw[j0 << 8], g_tw[j0 << 9], g_tw[j0 << 10], g_tw[j0 << 11]);
        __syncthreads();
        #pragma unroll
        for (int k = 0; k < 16; k++) s[SW(i + 2 * k)] = u[k];
    }
    __syncthreads();

    // mid trip: forward stage 12 (w=1) + Hilbert mask + inverse stages 0-3
    // (16 consecutive elements per thread; all inverse twiddles are unit here)
    {
        const int i = q * 16;
        #pragma unroll
        for (int k2 = 0; k2 < 8; k2++) {
            int t = 8 * q + k2;                  // pair index
            float2 a = cadd(s[SW(i + 2 * k2)], s[SW(i + 2 * k2 + 1)]);
            float2 d = csub(s[SW(i + 2 * k2)], s[SW(i + 2 * k2 + 1)]);
            if (t == 0) { u[0] = a; u[1] = d; }  // k=0 and k=N/2: x1
            else {
                u[2 * k2]     = make_float2(2.f * a.x, 2.f * a.y);
                u[2 * k2 + 1] = make_float2(0.f, 0.f);
            }
        }
        const float2 one = make_float2(1.f, 0.f);
        fft16_inv_regs(u, one, one, one, one);
        __syncthreads();
        #pragma unroll
        for (int k = 0; k < 16; k++) s[SW(i + k)] = u[k];
    }
    __syncthreads();

    // trip 4: inverse stages 4-7 (e=16)
    {
        const int j0 = q & 15, i = ((q >> 4) << 8) + j0;
        #pragma unroll
        for (int k = 0; k < 16; k++) u[k] = s[SW(i + 16 * k)];
        float2 c1 = g_tw[j0 << 8], c2 = g_tw[j0 << 7];
        float2 c4 = g_tw[j0 << 6], c8 = g_tw[j0 << 5];
        fft16_inv_regs(u, make_float2(c1.x, -c1.y), make_float2(c2.x, -c2.y),
                          make_float2(c4.x, -c4.y), make_float2(c8.x, -c8.y));
        __syncthreads();
        #pragma unroll
        for (int k = 0; k < 16; k++) s[SW(i + 16 * k)] = u[k];
    }
    __syncthreads();

    // trip 5: inverse stages 8-11 (e=256)
    {
        const int j0 = q & 255, i = ((q >> 8) << 12) + j0;
        #pragma unroll
        for (int k = 0; k < 16; k++) u[k] = s[SW(i + 256 * k)];
        float2 c1 = g_tw[j0 << 4], c2 = g_tw[j0 << 3];
        float2 c4 = g_tw[j0 << 2], c8 = g_tw[j0 << 1];
        fft16_inv_regs(u, make_float2(c1.x, -c1.y), make_float2(c2.x, -c2.y),
                          make_float2(c4.x, -c4.y), make_float2(c8.x, -c8.y));
        __syncthreads();
        #pragma unroll
        for (int k = 0; k < 16; k++) s[SW(i + 256 * k)] = u[k];
    }
    __syncthreads();

    // final trip: inverse stage 12 + 1/N + un-pack + normalize + plane stores
    const size_t pbase0 = ((size_t)(b * C_SZ + 2 * cp)) * 16384;   // channel a: [r|i]
    const size_t pbase1 = pbase0 + 16384;                          // channel b
    const float invN = 1.0f / 8192.0f;
    #pragma unroll
    for (int rr = 0; rr < 8; rr++) {
        int t = q + rr * 512;
        float2 tm = g_tw[t];
        float2 w = make_float2(tm.x, -tm.y);
        float2 uu = s[SW(t)];
        float2 v = cmul(s[SW(t + 4096)], w);
        float2 Wv[2] = { cadd(uu, v), csub(uu, v) };
        int ti[2] = { t, t + 4096 };
        #pragma unroll
        for (int e = 0; e < 2; e++) {
            int idx = ti[e];
            float Wr = Wv[e].x * invN, Wi = Wv[e].y * invN;
            float av = xa[idx], bv = xb[idx];
            float zr[2] = { av, bv };
            float zi[2] = { Wi - bv, av - Wr };
            size_t pb[2] = { pbase0, pbase1 };
            #pragma unroll
            for (int ch = 0; ch < 2; ch++) {
                float inv = rsqrtf(zr[ch] * zr[ch] + zi[ch] * zi[ch]);
                float r = zr[ch] * inv, i2 = zi[ch] * inv;
                __nv_bfloat16 rh = __float2bfloat16(r);
                __nv_bfloat16 ih = __float2bfloat16(i2);
                __nv_bfloat16 rl = __float2bfloat16(r - __bfloat162float(rh));
                __nv_bfloat16 il = __float2bfloat16(i2 - __bfloat162float(ih));
                g_Zhi[pb[ch] + idx]        = rh;
                g_Zhi[pb[ch] + 8192 + idx] = ih;
                g_Zlo[pb[ch] + idx]        = rl;
                g_Zlo[pb[ch] + 8192 + idx] = il;
            }
        }
    }
}

// ---------------- gram via HMMA: Re = Zr.Zr^T + Zi.Zi^T, R = Zi.Zr^T -------------
__global__ __launch_bounds__(256) void gram_mma_kernel() {
    extern __shared__ __align__(1024) char gsm[];
    const unsigned sbase = smem_u32(gsm);
    const int split = blockIdx.x, b = blockIdx.y;
    const int tid = threadIdx.x, lane = tid & 31, w = tid >> 5;
    const int mrow = 16 * (w & 3);
    const bool isIm = (w >= 4);

    const char* hi0 = (const char*)g_Zhi + (size_t)b * 64 * 32768 + (size_t)split * 2048;
    const char* lo0 = (const char*)g_Zlo + (size_t)b * 64 * 32768 + (size_t)split * 2048;

    unsigned swo[2]; size_t gofs[2];
    #pragma unroll
    for (int v = 0; v < 2; v++) {
        int u = v * 256 + tid;
        int rw = u >> 3, seg = u & 7;
        unsigned off = rw * 128 + seg * 16;
        swo[v] = off ^ ((off >> 3) & 0x70);
        gofs[v] = (size_t)rw * 32768 + (seg & 3) * 16 + ((seg >= 4) ? 16384 : 0);
    }

    const int lr = lane & 15, lcb = lane >> 4;
    unsigned a_off0 = (mrow + lr) * 128 + lcb * 16;
    unsigned aX = ((a_off0 >> 3) & 0x70);
    unsigned b_off0[4], bX[4];
    #pragma unroll
    for (int q = 0; q < 4; q++) {
        b_off0[q] = (16 * q + lr) * 128 + lcb * 16;
        bX[q] = ((b_off0[q] >> 3) & 0x70);
    }

    float c[8][4] = {};

    #pragma unroll
    for (int j = 0; j < 3; j++) {
        unsigned st = sbase + j * STG_B;
        #pragma unroll
        for (int v = 0; v < 2; v++) {
            cpasync16(st + swo[v],        hi0 + gofs[v] + j * 64);
            cpasync16(st + 8192 + swo[v], lo0 + gofs[v] + j * 64);
        }
        asm volatile("cp.async.commit_group;" ::: "memory");
    }

    for (int i = 0; i < NCH; i++) {
        int jn = i + 3;
        if (jn < NCH) {
            unsigned st = sbase + (jn % NSTG) * STG_B;
            #pragma unroll
            for (int v = 0; v < 2; v++) {
                cpasync16(st + swo[v],        hi0 + gofs[v] + (size_t)jn * 64);
                cpasync16(st + 8192 + swo[v], lo0 + gofs[v] + (size_t)jn * 64);
            }
            asm volatile("cp.async.commit_group;" ::: "memory");
            asm volatile("cp.async.wait_group 3;" ::: "memory");
        } else {
            asm volatile("cp.async.wait_group 0;" ::: "memory");
        }
        __syncthreads();

        const unsigned sb = sbase + (i % NSTG) * STG_B;
        const int npl = isIm ? 1 : 2;
        #pragma unroll
        for (int ks = 0; ks < 2; ks++) {
            #pragma unroll
            for (int p = 0; p < 2; p++) {
                if (p >= npl) break;
                int acol = ks * 32 + (isIm ? 64 : p * 64);   // A plane: Re->p, R->Zi
                int bcol = ks * 32 + (isIm ? 0  : p * 64);   // B plane: Re->p, R->Zr
                unsigned ah0, ah1, ah2, ah3, al0, al1, al2, al3;
                unsigned aa = sb + ((a_off0 + acol) ^ aX);
                ldsm4(ah0, ah1, ah2, ah3, aa);
                ldsm4(al0, al1, al2, al3, aa + 8192);
                #pragma unroll
                for (int q = 0; q < 4; q++) {
                    unsigned bh0, bh1, bh2, bh3, bl0, bl1, bl2, bl3;
                    unsigned ba = sb + ((b_off0[q] + bcol) ^ bX[q]);
                    ldsm4(bh0, bh1, bh2, bh3, ba);
                    ldsm4(bl0, bl1, bl2, bl3, ba + 8192);
                    mma16816(c[2 * q],     ah0, ah1, ah2, ah3, bh0, bh2);
                    mma16816(c[2 * q],     ah0, ah1, ah2, ah3, bl0, bl2);
                    mma16816(c[2 * q],     al0, al1, al2, al3, bh0, bh2);
                    mma16816(c[2 * q + 1], ah0, ah1, ah2, ah3, bh1, bh3);
                    mma16816(c[2 * q + 1], ah0, ah1, ah2, ah3, bl1, bl3);
                    mma16816(c[2 * q + 1], al0, al1, al2, al3, bh1, bh3);
                }
            }
        }
        __syncthreads();
    }

    float* G = g_G2 + ((size_t)(split * B_SZ + b)) * 8192;
    int rbase = (isIm ? 64 : 0) + mrow + (lane >> 2);
    #pragma unroll
    for (int j = 0; j < 8; j++) {
        int col = 8 * j + 2 * (lane & 3);
        G[rbase * 64 + col]           = c[j][0];
        G[rbase * 64 + col + 1]       = c[j][1];
        G[(rbase + 8) * 64 + col]     = c[j][2];
        G[(rbase + 8) * 64 + col + 1] = c[j][3];
    }
}

// ---------------- tail: conn finalize + GCN + MHA. One block/batch, 1024 thr ----
#define OFF_EE   4160
#define OFF_F1   8320
#define OFF_H1   16768
#define OFF_T2   25216
#define OFF_H2   29568
#define OFF_Q    33728
#define OFF_K    38080
#define OFF_V    42432
#define TAIL_FLOATS 46784

__global__ __launch_bounds__(1024) void tail_kernel(
    const float* __restrict__ EE,  const float* __restrict__ w1, const float* __restrict__ b1,
    const float* __restrict__ w2,  const float* __restrict__ b2,
    const float* __restrict__ Wip, const float* __restrict__ bip,
    const float* __restrict__ Wop, const float* __restrict__ bop,
    float* __restrict__ out)
{
    extern __shared__ float sm[];
    float* s_conn = sm;
    float* s_EE  = sm + OFF_EE;
    float* s_F1  = sm + OFF_F1;
    float* s_h1  = sm + OFF_H1;
    float* s_t2  = sm + OFF_T2;
    float* s_h2  = sm + OFF_H2;
    float* s_q   = sm + OFF_Q;
    float* s_k   = sm + OFF_K;
    float* s_v   = sm + OFF_V;
    float* s_ao  = s_conn;                 // conn dead after h2
    float* s_R   = s_F1;                   // R-sum [64][65] during conn stage
    const float* s_w1raw  = sm + OFF_H1;   // 8192 floats
    const float* s_w2raw  = sm + OFF_Q;    // 8192 floats (q+k regions)
    const float* s_wipraw = sm + OFF_EE;   // 12288 floats (EE+F1 regions)
    const float* s_wopraw = sm + OFF_H1;   // 4096 floats
    const int b = blockIdx.x;
    const int tid = threadIdx.x;

    // G0: prefetch w1 + w2
    {
        const uint4* s1 = (const uint4*)w1;
        const uint4* s2 = (const uint4*)w2;
        unsigned d1 = smem_u32(sm + OFF_H1);
        unsigned d2 = smem_u32(sm + OFF_Q);
        #pragma unroll
        for (int v = 0; v < 2; v++) {
            int idx = tid + v * 1024;
            cpasync16(d1 + idx * 16, s1 + idx);
            cpasync16(d2 + idx * 16, s2 + idx);
        }
        asm volatile("cp.async.commit_group;" ::: "memory");
    }

    #pragma unroll
    for (int i = tid; i < 4096; i += 1024)
        s_EE[(i >> 6) * 65 + (i & 63)] = EE[i];

    // connectivity: reduce K-split partials. Re direct; Im = R - R^T via smem.
    float reacc[4];
    #pragma unroll
    for (int v = 0; v < 4; v++) {
        int i = tid + v * 1024;
        int r = i >> 6, cc = i & 63;
        float re = 0.f, rsum = 0.f;
        #pragma unroll
        for (int sp = 0; sp < KSPLIT; sp++) {
            const float* G = g_G2 + ((size_t)(sp * B_SZ + b)) * 8192;
            re   += G[r * 64 + cc];
            rsum += G[(64 + r) * 64 + cc];
        }
        reacc[v] = re;
        s_R[r * 65 + cc] = rsum;
    }
    __syncthreads();
    #pragma unroll
    for (int v = 0; v < 4; v++) {
        int i = tid + v * 1024;
        int r = i >> 6, cc = i & 63;
        float im = s_R[r * 65 + cc] - s_R[cc * 65 + r];
        float re = reacc[v];
        float val = (r == cc) ? 0.f : sqrtf(re * re + im * im) * (1.f / (float)T_SZ);
        s_conn[r * 65 + cc] = val;
        out[(size_t)b * 4096 + i] = val;
    }
    asm volatile("cp.async.wait_group 0;" ::: "memory");
    __syncthreads();

    // F1 = EE @ w1 (w1 from smem)
    const float4* b1v = (const float4*)b1;
    #pragma unroll
    for (int it = 0; it < 2; it++) {
        int slot = tid + it * 1024;
        int r = slot >> 5, f4 = slot & 31;
        float4 acc = make_float4(0.f, 0.f, 0.f, 0.f);
        #pragma unroll 8
        for (int e = 0; e < 64; e++) {
            float4 w = ((const float4*)s_w1raw)[e * 32 + f4];
            float sc = s_EE[r * 65 + e];
            acc.x += sc * w.x; acc.y += sc * w.y; acc.z += sc * w.z; acc.w += sc * w.w;
        }
        ((float4*)&s_F1[r * 132])[f4] = acc;
    }
    __syncthreads();

    // h1 = relu(conn @ F1 + b1)  (overwrites w1 region)
    #pragma unroll
    for (int it = 0; it < 2; it++) {
        int slot = tid + it * 1024;
        int r = slot >> 5, f4 = slot & 31;
        float4 acc = b1v[f4];
        #pragma unroll 8
        for (int j = 0; j < 64; j++) {
            float4 fv = ((const float4*)&s_F1[j * 132])[f4];
            float cn = s_conn[r * 65 + j];
            acc.x += cn * fv.x; acc.y += cn * fv.y; acc.z += cn * fv.z; acc.w += cn * fv.w;
        }
        acc.x = fmaxf(acc.x, 0.f); acc.y = fmaxf(acc.y, 0.f);
        acc.z = fmaxf(acc.z, 0.f); acc.w = fmaxf(acc.w, 0.f);
        ((float4*)&s_h1[r * 132])[f4] = acc;
    }
    __syncthreads();

    // G1: prefetch Wip into EE+F1 (both dead now)
    {
        const uint4* sw = (const uint4*)Wip;
        unsigned dw = smem_u32(sm + OFF_EE);
        #pragma unroll
        for (int v = 0; v < 3; v++) {
            int idx = tid + v * 1024;
            cpasync16(dw + idx * 16, sw + idx);
        }
        asm volatile("cp.async.commit_group;" ::: "memory");
    }

    // t2 = h1 @ w2 (w2 from smem)
    {
        int r = tid >> 4, e4 = tid & 15;
        float4 acc = make_float4(0.f, 0.f, 0.f, 0.f);
        #pragma unroll 8
        for (int f = 0; f < 128; f++) {
            float4 w = ((const float4*)s_w2raw)[f * 16 + e4];
            float h = s_h1[r * 132 + f];
            acc.x += h * w.x; acc.y += h * w.y; acc.z += h * w.z; acc.w += h * w.w;
        }
        ((float4*)&s_t2[r * 68])[e4] = acc;
    }
    __syncthreads();

    // G2: prefetch Wop into h1 region (dead now)
    {
        const uint4* sw = (const uint4*)Wop;
        unsigned dw = smem_u32(sm + OFF_H1);
        cpasync16(dw + tid * 16, sw + tid);
        asm volatile("cp.async.commit_group;" ::: "memory");
    }

    // h2 = conn @ t2 + b2 ; output #3
    {
        const float4* b2v = (const float4*)b2;
        int r = tid >> 4, e4 = tid & 15;
        float4 acc = b2v[e4];
        #pragma unroll 8
        for (int j = 0; j < 64; j++) {
            float4 t4 = ((const float4*)&s_t2[j * 68])[e4];
            float cn = s_conn[r * 65 + j];
            acc.x += cn * t4.x; acc.y += cn * t4.y; acc.z += cn * t4.z; acc.w += cn * t4.w;
        }
        s_h2[r * 65 + 4 * e4]     = acc.x;
        s_h2[r * 65 + 4 * e4 + 1] = acc.y;
        s_h2[r * 65 + 4 * e4 + 2] = acc.z;
        s_h2[r * 65 + 4 * e4 + 3] = acc.w;
        ((float4*)(out + (size_t)(2 * B_SZ * 4096) + (size_t)b * 4096 + r * 64))[e4] = acc;
    }
    asm volatile("cp.async.wait_group 1;" ::: "memory");
    __syncthreads();

    // qkv = h2 @ Wip^T + bip (raw Wip from smem; warp-uniform broadcast loads)
    {
        const float4* bipv = (const float4*)bip;
        #pragma unroll
        for (int it = 0; it < 3; it++) {
            int slot = tid + it * 1024;
            int n = slot & 63, m4 = slot >> 6;
            float4 acc = bipv[m4];
            #pragma unroll 8
            for (int e = 0; e < 64; e++) {
                float h = s_h2[n * 65 + e];
                acc.x += h * s_wipraw[(4 * m4 + 0) * 64 + e];
                acc.y += h * s_wipraw[(4 * m4 + 1) * 64 + e];
                acc.z += h * s_wipraw[(4 * m4 + 2) * 64 + e];
                acc.w += h * s_wipraw[(4 * m4 + 3) * 64 + e];
            }
            float* dst = (m4 < 16) ? s_q : (m4 < 32 ? s_k : s_v);
            int c4 = m4 & 15;
            ((float4*)&dst[n * 68])[c4] = acc;
        }
    }
    asm volatile("cp.async.wait_group 0;" ::: "memory");
    __syncthreads();

    // attention: 512 tasks = (head, row); two-pass softmax with __expf
    if (tid < 512) {
        int h = tid >> 6, qi = tid & 63;
        const float inv_sqrt_d = 0.35355339059327373f;
        float qv[8];
        #pragma unroll
        for (int d = 0; d < 8; d++) qv[d] = s_q[qi * 68 + h * 8 + d];
        float mx = -1e30f;
        for (int k = 0; k < 64; k++) {
            float sc = 0.f;
            #pragma unroll
            for (int d = 0; d < 8; d++) sc += qv[d] * s_k[k * 68 + h * 8 + d];
            mx = fmaxf(mx, sc * inv_sqrt_d);
        }
        float denom = 0.f, acc[8] = {};
        for (int k = 0; k < 64; k++) {
            float sc = 0.f;
            #pragma unroll
            for (int d = 0; d < 8; d++) sc += qv[d] * s_k[k * 68 + h * 8 + d];
            float p = __expf(sc * inv_sqrt_d - mx);
            denom += p;
            #pragma unroll
            for (int d = 0; d < 8; d++) acc[d] += p * s_v[k * 68 + h * 8 + d];
        }
        float rinv = 1.f / denom;
        __syncthreads();
        #pragma unroll
        for (int d = 0; d < 8; d++) s_ao[qi * 65 + h * 8 + d] = acc[d] * rinv;
    } else {
        __syncthreads();
    }
    __syncthreads();

    // graph_features = ao @ Wop^T + bop (raw Wop; broadcast loads); output #2
    {
        const float4* bopv = (const float4*)bop;
        int n = tid & 63, e4 = tid >> 6;
        float4 acc = bopv[e4];
        #pragma unroll 8
        for (int f = 0; f < 64; f++) {
            float av = s_ao[n * 65 + f];
            acc.x += av * s_wopraw[(4 * e4 + 0) * 64 + f];
            acc.y += av * s_wopraw[(4 * e4 + 1) * 64 + f];
            acc.z += av * s_wopraw[(4 * e4 + 2) * 64 + f];
            acc.w += av * s_wopraw[(4 * e4 + 3) * 64 + f];
        }
        ((float4*)(out + (size_t)(B_SZ * 4096) + (size_t)b * 4096 + n * 64 + 4 * e4))[0] = acc;
    }
}

// ---------------- launch ----------------
extern "C" void kernel_launch(void* const* d_in, const int* in_sizes, int n_in,
                              void* d_out, int out_size) {
    const float* x   = (const float*)d_in[0];
    const float* EE  = (const float*)d_in[1];
    const float* w1  = (const float*)d_in[2];
    const float* b1  = (const float*)d_in[3];
    const float* w2  = (const float*)d_in[4];
    const float* b2  = (const float*)d_in[5];
    const float* Wip = (const float*)d_in[6];
    const float* bip = (const float*)d_in[7];
    const float* Wop = (const float*)d_in[8];
    const float* bop = (const float*)d_in[9];
    float* out = (float*)d_out;

    cudaFuncSetAttribute(fft_hilbert_kernel,
                         cudaFuncAttributeMaxDynamicSharedMemorySize, 65536);
    cudaFuncSetAttribute(gram_mma_kernel,
                         cudaFuncAttributeMaxDynamicSharedMemorySize, GRAM_SMEM);
    cudaFuncSetAttribute(tail_kernel,
                         cudaFuncAttributeMaxDynamicSharedMemorySize, TAIL_FLOATS * 4);

    twiddle_init_kernel<<<16, 256>>>();
    fft_hilbert_kernel<<<B_SZ * C_SZ / 2, 512, 65536>>>(x);
    gram_mma_kernel<<<dim3(KSPLIT, B_SZ), 256, GRAM_SMEM>>>();
    tail_kernel<<<B_SZ, 1024, TAIL_FLOATS * 4>>>(EE, w1, b1, w2, b2,
                                                 Wip, bip, Wop, bop, out);
}

// round 11
// speedup vs baseline: 2.5443x; 1.0444x over previous
#include <cuda_runtime.h>
#include <cuda_bf16.h>
#include <math.h>

#define B_SZ 32
#define C_SZ 64
#define T_SZ 8192
#define KSPLIT 8
#define NCH 32               // 32-sample k-chunks per CTA (8192/8 splits/32)
#define NSTG 4
#define STG_B 16384          // per stage: hi tile 8KB + lo tile 8KB
#define GRAM_SMEM (NSTG * STG_B)

// ---------------- scratch (static device globals; no allocation) ----------------
// de-interleaved bf16 planes: [b][c][r|i][8192] (hi and lo arrays)
__device__ __nv_bfloat16 g_Zhi[(size_t)B_SZ * 64 * 2 * 8192];   // 67 MB
__device__ __nv_bfloat16 g_Zlo[(size_t)B_SZ * 64 * 2 * 8192];   // 67 MB
__device__ float  g_G2[(size_t)KSPLIT * B_SZ * 128 * 64]; // rows 0-63: Re, 64-127: R=Zi.Zr^T
__device__ float2 g_tw[T_SZ / 2];                         // exp(-2pi i k/N)
__device__ float  g_F1[64 * 128];                         // EE @ w1 (batch-invariant)

__device__ __forceinline__ float2 cmul(float2 a, float2 b) {
    return make_float2(a.x * b.x - a.y * b.y, a.x * b.y + a.y * b.x);
}
__device__ __forceinline__ float2 cadd(float2 a, float2 b) { return make_float2(a.x + b.x, a.y + b.y); }
__device__ __forceinline__ float2 csub(float2 a, float2 b) { return make_float2(a.x - b.x, a.y - b.y); }
__device__ __forceinline__ float2 cmulc(float2 v, float cx, float cy) {
    return make_float2(v.x * cx - v.y * cy, v.x * cy + v.y * cx);
}
__device__ __forceinline__ int SW(int i) { return i ^ ((i >> 5) & 31); }

__device__ __forceinline__ unsigned smem_u32(const void* p) {
    unsigned a;
    asm("{ .reg .u64 t; cvta.to.shared.u64 t, %1; cvt.u32.u64 %0, t; }" : "=r"(a) : "l"(p));
    return a;
}
__device__ __forceinline__ void cpasync16(unsigned dst, const void* src) {
    asm volatile("cp.async.cg.shared.global [%0], [%1], 16;" :: "r"(dst), "l"(src) : "memory");
}
__device__ __forceinline__ void ldsm4(unsigned& r0, unsigned& r1, unsigned& r2, unsigned& r3,
                                      unsigned addr) {
    asm volatile("ldmatrix.sync.aligned.m8n8.x4.shared.b16 {%0,%1,%2,%3}, [%4];"
                 : "=r"(r0), "=r"(r1), "=r"(r2), "=r"(r3) : "r"(addr));
}
__device__ __forceinline__ void mma16816(float* c, unsigned a0, unsigned a1, unsigned a2,
                                         unsigned a3, unsigned b0, unsigned b1) {
    asm volatile("mma.sync.aligned.m16n8k16.row.col.f32.bf16.bf16.f32 "
                 "{%0,%1,%2,%3}, {%4,%5,%6,%7}, {%8,%9}, {%0,%1,%2,%3};"
                 : "+f"(c[0]), "+f"(c[1]), "+f"(c[2]), "+f"(c[3])
                 : "r"(a0), "r"(a1), "r"(a2), "r"(a3), "r"(b0), "r"(b1));
}

#define RC8 0.70710678118654752f
#define C16 0.92387953251128676f
#define S16 0.38268343236508977f

// ---- radix-16 forward butterfly in registers (DIF stages st..st+3) ----
__device__ __forceinline__ void fft16_fwd_regs(float2* u, float2 W1, float2 W2,
                                               float2 W4, float2 W8) {
    float2 W1k[8];
    W1k[0] = W1;
    W1k[1] = cmulc(W1,  C16, -S16);
    W1k[2] = cmulc(W1,  RC8, -RC8);
    W1k[3] = cmulc(W1,  S16, -C16);
    W1k[4] = make_float2(W1.y, -W1.x);
    W1k[5] = cmulc(W1, -S16, -C16);
    W1k[6] = cmulc(W1, -RC8, -RC8);
    W1k[7] = cmulc(W1, -C16, -S16);
    #pragma unroll
    for (int k = 0; k < 8; k++) {
        float2 sum = cadd(u[k], u[k + 8]);
        float2 dif = csub(u[k], u[k + 8]);
        u[k] = sum;
        u[k + 8] = cmul(dif, W1k[k]);
    }
    float2 W2k[4];
    W2k[0] = W2;
    W2k[1] = cmulc(W2,  RC8, -RC8);
    W2k[2] = make_float2(W2.y, -W2.x);
    W2k[3] = cmulc(W2, -RC8, -RC8);
    #pragma unroll
    for (int g = 0; g < 16; g += 8)
        #pragma unroll
        for (int k = 0; k < 4; k++) {
            float2 sum = cadd(u[g + k], u[g + k + 4]);
            float2 dif = csub(u[g + k], u[g + k + 4]);
            u[g + k] = sum;
            u[g + k + 4] = cmul(dif, W2k[k]);
        }
    float2 W4k[2] = { W4, make_float2(W4.y, -W4.x) };
    #pragma unroll
    for (int g = 0; g < 16; g += 4)
        #pragma unroll
        for (int k = 0; k < 2; k++) {
            float2 sum = cadd(u[g + k], u[g + k + 2]);
            float2 dif = csub(u[g + k], u[g + k + 2]);
            u[g + k] = sum;
            u[g + k + 2] = cmul(dif, W4k[k]);
        }
    #pragma unroll
    for (int g = 0; g < 16; g += 2) {
        float2 sum = cadd(u[g], u[g + 1]);
        float2 dif = csub(u[g], u[g + 1]);
        u[g] = sum;
        u[g + 1] = cmul(dif, W8);
    }
}

// ---- radix-16 inverse butterfly in registers (DIT stages st..st+3) ----
__device__ __forceinline__ void fft16_inv_regs(float2* u, float2 W1, float2 W2,
                                               float2 W4, float2 W8) {
    #pragma unroll
    for (int g = 0; g < 16; g += 2) {
        float2 v = cmul(u[g + 1], W1);
        float2 t = u[g];
        u[g]     = cadd(t, v);
        u[g + 1] = csub(t, v);
    }
    float2 W2k[2] = { W2, make_float2(-W2.y, W2.x) };
    #pragma unroll
    for (int g = 0; g < 16; g += 4)
        #pragma unroll
        for (int k = 0; k < 2; k++) {
            float2 v = cmul(u[g + k + 2], W2k[k]);
            float2 t = u[g + k];
            u[g + k]     = cadd(t, v);
            u[g + k + 2] = csub(t, v);
        }
    float2 W4k[4];
    W4k[0] = W4;
    W4k[1] = cmulc(W4,  RC8, RC8);
    W4k[2] = make_float2(-W4.y, W4.x);
    W4k[3] = cmulc(W4, -RC8, RC8);
    #pragma unroll
    for (int g = 0; g < 16; g += 8)
        #pragma unroll
        for (int k = 0; k < 4; k++) {
            float2 v = cmul(u[g + k + 4], W4k[k]);
            float2 t = u[g + k];
            u[g + k]     = cadd(t, v);
            u[g + k + 4] = csub(t, v);
        }
    float2 W8k[8];
    W8k[0] = W8;
    W8k[1] = cmulc(W8,  C16, S16);
    W8k[2] = cmulc(W8,  RC8, RC8);
    W8k[3] = cmulc(W8,  S16, C16);
    W8k[4] = make_float2(-W8.y, W8.x);
    W8k[5] = cmulc(W8, -S16, C16);
    W8k[6] = cmulc(W8, -RC8, RC8);
    W8k[7] = cmulc(W8, -C16, S16);
    #pragma unroll
    for (int k = 0; k < 8; k++) {
        float2 v = cmul(u[k + 8], W8k[k]);
        float2 t = u[k];
        u[k]     = cadd(t, v);
        u[k + 8] = csub(t, v);
    }
}

// ---------------- init: twiddles (blocks 0-15) + F1 = EE @ w1 (blocks 16-31) ----
__global__ void init_kernel(const float* __restrict__ EE, const float* __restrict__ w1) {
    const int blk = blockIdx.x, tid = threadIdx.x;
    if (blk < 16) {
        int i = blk * 256 + tid;
        if (i < T_SZ / 2) {
            double ang = -2.0 * 3.14159265358979323846 * (double)i / (double)T_SZ;
            g_tw[i] = make_float2((float)cos(ang), (float)sin(ang));
        }
    } else {
        #pragma unroll
        for (int v = 0; v < 2; v++) {
            int idx = (blk - 16) * 512 + v * 256 + tid;
            int r = idx >> 7, f = idx & 127;
            float acc = 0.f;
            #pragma unroll 8
            for (int e = 0; e < 64; e++) acc += EE[r * 64 + e] * w1[e * 128 + f];
            g_F1[idx] = acc;
        }
    }
}

// ---------------- FFT (pair-packed real channels), radix-16 trips ---------------
__global__ __launch_bounds__(512) void fft_hilbert_kernel(const float* __restrict__ x) {
    extern __shared__ float2 s[];   // 64 KB
    const int blk = blockIdx.x;                 // 0..1023
    const int b = blk >> 5, cp = blk & 31;
    const float* __restrict__ xa = x + ((size_t)b * C_SZ + 2 * cp) * T_SZ;
    const float* __restrict__ xb = xa + T_SZ;
    const int q = threadIdx.x;

    float2 u[16];

    // trip 0: load z + forward stages 0-3
    #pragma unroll
    for (int k = 0; k < 16; k++)
        u[k] = make_float2(xa[q + 512 * k], xb[q + 512 * k]);
    fft16_fwd_regs(u, g_tw[q], g_tw[2 * q], g_tw[4 * q], g_tw[8 * q]);
    #pragma unroll
    for (int k = 0; k < 16; k++) s[SW(q + 512 * k)] = u[k];
    __syncthreads();

    // trip 1: forward stages 4-7
    {
        const int j0 = q & 31, i = ((q >> 5) << 9) + j0;
        #pragma unroll
        for (int k = 0; k < 16; k++) u[k] = s[SW(i + 32 * k)];
        fft16_fwd_regs(u, g_tw[j0 << 4], g_tw[j0 << 5], g_tw[j0 << 6], g_tw[j0 << 7]);
        __syncthreads();
        #pragma unroll
        for (int k = 0; k < 16; k++) s[SW(i + 32 * k)] = u[k];
    }
    __syncthreads();

    // trip 2: forward stages 8-11
    {
        const int j0 = q & 1, i = ((q >> 1) << 5) + j0;
        #pragma unroll
        for (int k = 0; k < 16; k++) u[k] = s[SW(i + 2 * k)];
        fft16_fwd_regs(u, g_tw[j0 << 8], g_tw[j0 << 9], g_tw[j0 << 10], g_tw[j0 << 11]);
        __syncthreads();
        #pragma unroll
        for (int k = 0; k < 16; k++) s[SW(i + 2 * k)] = u[k];
    }
    __syncthreads();

    // mid trip: forward stage 12 + Hilbert mask + inverse stages 0-3
    {
        const int i = q * 16;
        #pragma unroll
        for (int k2 = 0; k2 < 8; k2++) {
            int t = 8 * q + k2;
            float2 a = cadd(s[SW(i + 2 * k2)], s[SW(i + 2 * k2 + 1)]);
            float2 d = csub(s[SW(i + 2 * k2)], s[SW(i + 2 * k2 + 1)]);
            if (t == 0) { u[0] = a; u[1] = d; }
            else {
                u[2 * k2]     = make_float2(2.f * a.x, 2.f * a.y);
                u[2 * k2 + 1] = make_float2(0.f, 0.f);
            }
        }
        const float2 one = make_float2(1.f, 0.f);
        fft16_inv_regs(u, one, one, one, one);
        __syncthreads();
        #pragma unroll
        for (int k = 0; k < 16; k++) s[SW(i + k)] = u[k];
    }
    __syncthreads();

    // trip 4: inverse stages 4-7
    {
        const int j0 = q & 15, i = ((q >> 4) << 8) + j0;
        #pragma unroll
        for (int k = 0; k < 16; k++) u[k] = s[SW(i + 16 * k)];
        float2 c1 = g_tw[j0 << 8], c2 = g_tw[j0 << 7];
        float2 c4 = g_tw[j0 << 6], c8 = g_tw[j0 << 5];
        fft16_inv_regs(u, make_float2(c1.x, -c1.y), make_float2(c2.x, -c2.y),
                          make_float2(c4.x, -c4.y), make_float2(c8.x, -c8.y));
        __syncthreads();
        #pragma unroll
        for (int k = 0; k < 16; k++) s[SW(i + 16 * k)] = u[k];
    }
    __syncthreads();

    // trip 5: inverse stages 8-11
    {
        const int j0 = q & 255, i = ((q >> 8) << 12) + j0;
        #pragma unroll
        for (int k = 0; k < 16; k++) u[k] = s[SW(i + 256 * k)];
        float2 c1 = g_tw[j0 << 4], c2 = g_tw[j0 << 3];
        float2 c4 = g_tw[j0 << 2], c8 = g_tw[j0 << 1];
        fft16_inv_regs(u, make_float2(c1.x, -c1.y), make_float2(c2.x, -c2.y),
                          make_float2(c4.x, -c4.y), make_float2(c8.x, -c8.y));
        __syncthreads();
        #pragma unroll
        for (int k = 0; k < 16; k++) s[SW(i + 256 * k)] = u[k];
    }
    __syncthreads();

    // final trip: inverse stage 12 + 1/N + un-pack + normalize + plane stores
    const size_t pbase0 = ((size_t)(b * C_SZ + 2 * cp)) * 16384;
    const size_t pbase1 = pbase0 + 16384;
    const float invN = 1.0f / 8192.0f;
    #pragma unroll
    for (int rr = 0; rr < 8; rr++) {
        int t = q + rr * 512;
        float2 tm = g_tw[t];
        float2 w = make_float2(tm.x, -tm.y);
        float2 uu = s[SW(t)];
        float2 v = cmul(s[SW(t + 4096)], w);
        float2 Wv[2] = { cadd(uu, v), csub(uu, v) };
        int ti[2] = { t, t + 4096 };
        #pragma unroll
        for (int e = 0; e < 2; e++) {
            int idx = ti[e];
            float Wr = Wv[e].x * invN, Wi = Wv[e].y * invN;
            float av = xa[idx], bv = xb[idx];
            float zr[2] = { av, bv };
            float zi[2] = { Wi - bv, av - Wr };
            size_t pb[2] = { pbase0, pbase1 };
            #pragma unroll
            for (int ch = 0; ch < 2; ch++) {
                float inv = rsqrtf(zr[ch] * zr[ch] + zi[ch] * zi[ch]);
                float r = zr[ch] * inv, i2 = zi[ch] * inv;
                __nv_bfloat16 rh = __float2bfloat16(r);
                __nv_bfloat16 ih = __float2bfloat16(i2);
                __nv_bfloat16 rl = __float2bfloat16(r - __bfloat162float(rh));
                __nv_bfloat16 il = __float2bfloat16(i2 - __bfloat162float(ih));
                g_Zhi[pb[ch] + idx]        = rh;
                g_Zhi[pb[ch] + 8192 + idx] = ih;
                g_Zlo[pb[ch] + idx]        = rl;
                g_Zlo[pb[ch] + 8192 + idx] = il;
            }
        }
    }
}

// ---------------- gram via HMMA: Re = Zr.Zr^T + Zi.Zi^T, R = Zi.Zr^T -------------
__global__ __launch_bounds__(256) void gram_mma_kernel() {
    extern __shared__ __align__(1024) char gsm[];
    const unsigned sbase = smem_u32(gsm);
    const int split = blockIdx.x, b = blockIdx.y;
    const int tid = threadIdx.x, lane = tid & 31, w = tid >> 5;
    const int mrow = 16 * (w & 3);
    const bool isIm = (w >= 4);

    const char* hi0 = (const char*)g_Zhi + (size_t)b * 64 * 32768 + (size_t)split * 2048;
    const char* lo0 = (const char*)g_Zlo + (size_t)b * 64 * 32768 + (size_t)split * 2048;

    unsigned swo[2]; size_t gofs[2];
    #pragma unroll
    for (int v = 0; v < 2; v++) {
        int u = v * 256 + tid;
        int rw = u >> 3, seg = u & 7;
        unsigned off = rw * 128 + seg * 16;
        swo[v] = off ^ ((off >> 3) & 0x70);
        gofs[v] = (size_t)rw * 32768 + (seg & 3) * 16 + ((seg >= 4) ? 16384 : 0);
    }

    const int lr = lane & 15, lcb = lane >> 4;
    unsigned a_off0 = (mrow + lr) * 128 + lcb * 16;
    unsigned aX = ((a_off0 >> 3) & 0x70);
    unsigned b_off0[4], bX[4];
    #pragma unroll
    for (int q = 0; q < 4; q++) {
        b_off0[q] = (16 * q + lr) * 128 + lcb * 16;
        bX[q] = ((b_off0[q] >> 3) & 0x70);
    }

    float c[8][4] = {};

    #pragma unroll
    for (int j = 0; j < 3; j++) {
        unsigned st = sbase + j * STG_B;
        #pragma unroll
        for (int v = 0; v < 2; v++) {
            cpasync16(st + swo[v],        hi0 + gofs[v] + j * 64);
            cpasync16(st + 8192 + swo[v], lo0 + gofs[v] + j * 64);
        }
        asm volatile("cp.async.commit_group;" ::: "memory");
    }

    for (int i = 0; i < NCH; i++) {
        int jn = i + 3;
        if (jn < NCH) {
            unsigned st = sbase + (jn % NSTG) * STG_B;
            #pragma unroll
            for (int v = 0; v < 2; v++) {
                cpasync16(st + swo[v],        hi0 + gofs[v] + (size_t)jn * 64);
                cpasync16(st + 8192 + swo[v], lo0 + gofs[v] + (size_t)jn * 64);
            }
            asm volatile("cp.async.commit_group;" ::: "memory");
            asm volatile("cp.async.wait_group 3;" ::: "memory");
        } else {
            asm volatile("cp.async.wait_group 0;" ::: "memory");
        }
        __syncthreads();

        const unsigned sb = sbase + (i % NSTG) * STG_B;
        const int npl = isIm ? 1 : 2;
        #pragma unroll
        for (int ks = 0; ks < 2; ks++) {
            #pragma unroll
            for (int p = 0; p < 2; p++) {
                if (p >= npl) break;
                int acol = ks * 32 + (isIm ? 64 : p * 64);
                int bcol = ks * 32 + (isIm ? 0  : p * 64);
                unsigned ah0, ah1, ah2, ah3, al0, al1, al2, al3;
                unsigned aa = sb + ((a_off0 + acol) ^ aX);
                ldsm4(ah0, ah1, ah2, ah3, aa);
                ldsm4(al0, al1, al2, al3, aa + 8192);
                #pragma unroll
                for (int q = 0; q < 4; q++) {
                    unsigned bh0, bh1, bh2, bh3, bl0, bl1, bl2, bl3;
                    unsigned ba = sb + ((b_off0[q] + bcol) ^ bX[q]);
                    ldsm4(bh0, bh1, bh2, bh3, ba);
                    ldsm4(bl0, bl1, bl2, bl3, ba + 8192);
                    mma16816(c[2 * q],     ah0, ah1, ah2, ah3, bh0, bh2);
                    mma16816(c[2 * q],     ah0, ah1, ah2, ah3, bl0, bl2);
                    mma16816(c[2 * q],     al0, al1, al2, al3, bh0, bh2);
                    mma16816(c[2 * q + 1], ah0, ah1, ah2, ah3, bh1, bh3);
                    mma16816(c[2 * q + 1], ah0, ah1, ah2, ah3, bl1, bl3);
                    mma16816(c[2 * q + 1], al0, al1, al2, al3, bh1, bh3);
                }
            }
        }
        __syncthreads();
    }

    float* G = g_G2 + ((size_t)(split * B_SZ + b)) * 8192;
    int rbase = (isIm ? 64 : 0) + mrow + (lane >> 2);
    #pragma unroll
    for (int j = 0; j < 8; j++) {
        int col = 8 * j + 2 * (lane & 3);
        G[rbase * 64 + col]           = c[j][0];
        G[rbase * 64 + col + 1]       = c[j][1];
        G[(rbase + 8) * 64 + col]     = c[j][2];
        G[(rbase + 8) * 64 + col + 1] = c[j][3];
    }
}

// ---------------- tail: conn finalize + GCN + MHA. One block/batch, 1024 thr ----
// smem layout (floats): conn 0(4160) | F1 4160(8448,[64][132],prefetched) |
// wipraw 12608(12288) | h1 24896(8448) | t2 33344(4352) | h2 37696(4160) |
// q 41856(4352) | k 46208(4352) | v 50560(4352). WT[64][196] overlays h1+t2.
#define OFF_F1   4160
#define OFF_WIPR 12608
#define OFF_H1   24896
#define OFF_T2   33344
#define OFF_H2   37696
#define OFF_Q    41856
#define OFF_K    46208
#define OFF_V    50560
#define TAIL_FLOATS 54912   // 219648 bytes

__global__ __launch_bounds__(1024) void tail_kernel(
    const float* __restrict__ EE,  const float* __restrict__ w1, const float* __restrict__ b1,
    const float* __restrict__ w2,  const float* __restrict__ b2,
    const float* __restrict__ Wip, const float* __restrict__ bip,
    const float* __restrict__ Wop, const float* __restrict__ bop,
    float* __restrict__ out)
{
    extern __shared__ float sm[];
    float* s_conn = sm;
    float* s_F1   = sm + OFF_F1;
    float* s_wipr = sm + OFF_WIPR;
    float* s_h1   = sm + OFF_H1;
    float* s_t2   = sm + OFF_T2;
    float* s_h2   = sm + OFF_H2;
    float* s_q    = sm + OFF_Q;
    float* s_k    = sm + OFF_K;
    float* s_v    = sm + OFF_V;
    float* s_ao   = s_conn;                // conn dead after h2
    float* s_R    = sm + OFF_H1;           // R-sum temp during conn stage
    float* s_WT   = sm + OFF_H1;           // WipT [64][196] over h1+t2 (dead at qkv)
    const float* s_w2raw  = sm + OFF_Q;    // 8192 floats (q+k regions, prefetched)
    const float* s_wopraw = sm + OFF_F1;   // 4096 floats (F1 region, after h1)
    const int b = blockIdx.x;
    const int tid = threadIdx.x;

    // G0: prefetch F1 ([64][132] padded), w2 (contiguous), Wip raw (contiguous)
    {
        unsigned dF = smem_u32(sm + OFF_F1);
        unsigned dW2 = smem_u32(sm + OFF_Q);
        unsigned dWi = smem_u32(sm + OFF_WIPR);
        const uint4* sF = (const uint4*)g_F1;
        const uint4* s2 = (const uint4*)w2;
        const uint4* si = (const uint4*)Wip;
        #pragma unroll
        for (int v = 0; v < 2; v++) {
            int u = tid + v * 1024;                      // 0..2047
            int r = u >> 5, f4 = u & 31;
            cpasync16(dF + (r * 132 + f4 * 4) * 4, sF + u);
            cpasync16(dW2 + u * 16, s2 + u);
        }
        #pragma unroll
        for (int v = 0; v < 3; v++) {
            int u = tid + v * 1024;                      // 0..3071
            cpasync16(dWi + u * 16, si + u);
        }
        asm volatile("cp.async.commit_group;" ::: "memory");
    }

    // connectivity: reduce K-split partials. Re direct; Im = R - R^T via smem.
    float reacc[4];
    #pragma unroll
    for (int v = 0; v < 4; v++) {
        int i = tid + v * 1024;
        int r = i >> 6, cc = i & 63;
        float re = 0.f, rsum = 0.f;
        #pragma unroll
        for (int sp = 0; sp < KSPLIT; sp++) {
            const float* G = g_G2 + ((size_t)(sp * B_SZ + b)) * 8192;
            re   += G[r * 64 + cc];
            rsum += G[(64 + r) * 64 + cc];
        }
        reacc[v] = re;
        s_R[r * 65 + cc] = rsum;
    }
    __syncthreads();
    #pragma unroll
    for (int v = 0; v < 4; v++) {
        int i = tid + v * 1024;
        int r = i >> 6, cc = i & 63;
        float im = s_R[r * 65 + cc] - s_R[cc * 65 + r];
        float re = reacc[v];
        float val = (r == cc) ? 0.f : sqrtf(re * re + im * im) * (1.f / (float)T_SZ);
        s_conn[r * 65 + cc] = val;
        out[(size_t)b * 4096 + i] = val;
    }
    asm volatile("cp.async.wait_group 0;" ::: "memory");
    __syncthreads();

    // h1 = relu(conn @ F1 + b1), paired rows (r, r+32) share F1 loads
    {
        const float4* b1v = (const float4*)b1;
        int f4 = tid & 31, r = tid >> 5;        // r 0..31
        float4 bb = b1v[f4];
        float4 a0 = bb, a1 = bb;
        #pragma unroll 8
        for (int j = 0; j < 64; j++) {
            float4 w = ((const float4*)&s_F1[j * 132])[f4];
            float c0 = s_conn[r * 65 + j];
            float c1 = s_conn[(r + 32) * 65 + j];
            a0.x += c0 * w.x; a0.y += c0 * w.y; a0.z += c0 * w.z; a0.w += c0 * w.w;
            a1.x += c1 * w.x; a1.y += c1 * w.y; a1.z += c1 * w.z; a1.w += c1 * w.w;
        }
        a0.x = fmaxf(a0.x, 0.f); a0.y = fmaxf(a0.y, 0.f);
        a0.z = fmaxf(a0.z, 0.f); a0.w = fmaxf(a0.w, 0.f);
        a1.x = fmaxf(a1.x, 0.f); a1.y = fmaxf(a1.y, 0.f);
        a1.z = fmaxf(a1.z, 0.f); a1.w = fmaxf(a1.w, 0.f);
        ((float4*)&s_h1[r * 132])[f4] = a0;
        ((float4*)&s_h1[(r + 32) * 132])[f4] = a1;
    }
    __syncthreads();

    // G2: prefetch Wop into F1 region (dead now)
    {
        unsigned dw = smem_u32(sm + OFF_F1);
        cpasync16(dw + tid * 16, (const uint4*)Wop + tid);
        asm volatile("cp.async.commit_group;" ::: "memory");
    }

    // t2 = h1 @ w2 (w2 from smem)
    {
        int r = tid >> 4, e4 = tid & 15;
        float4 acc = make_float4(0.f, 0.f, 0.f, 0.f);
        #pragma unroll 8
        for (int f = 0; f < 128; f++) {
            float4 w = ((const float4*)s_w2raw)[f * 16 + e4];
            float h = s_h1[r * 132 + f];
            acc.x += h * w.x; acc.y += h * w.y; acc.z += h * w.z; acc.w += h * w.w;
        }
        ((float4*)&s_t2[r * 68])[e4] = acc;
    }
    __syncthreads();

    // h2 = conn @ t2 + b2 ; output #3
    {
        const float4* b2v = (const float4*)b2;
        int r = tid >> 4, e4 = tid & 15;
        float4 acc = b2v[e4];
        #pragma unroll 8
        for (int j = 0; j < 64; j++) {
            float4 t4 = ((const float4*)&s_t2[j * 68])[e4];
            float cn = s_conn[r * 65 + j];
            acc.x += cn * t4.x; acc.y += cn * t4.y; acc.z += cn * t4.z; acc.w += cn * t4.w;
        }
        s_h2[r * 65 + 4 * e4]     = acc.x;
        s_h2[r * 65 + 4 * e4 + 1] = acc.y;
        s_h2[r * 65 + 4 * e4 + 2] = acc.z;
        s_h2[r * 65 + 4 * e4 + 3] = acc.w;
        ((float4*)(out + (size_t)(2 * B_SZ * 4096) + (size_t)b * 4096 + r * 64))[e4] = acc;
    }
    __syncthreads();

    // transpose raw Wip (smem) -> WT[e][196] over dead h1+t2 regions
    #pragma unroll
    for (int it = 0; it < 12; it++) {
        int idx = tid + it * 1024;        // 0..12287
        int e = idx & 63, m = idx >> 6;   // warp lanes span e -> coalesced reads
        s_WT[e * 196 + m] = s_wipr[m * 64 + e];
    }
    __syncthreads();

    // qkv = h2 @ WT + bip: per warp-iter 1 broadcast float4 + 1 h2 phase
    {
        const float4* bipv = (const float4*)bip;
        #pragma unroll
        for (int it = 0; it < 3; it++) {
            int slot = tid + it * 1024;
            int n = slot & 63, m4 = slot >> 6;   // m4 0..47
            float4 acc = bipv[m4];
            #pragma unroll 8
            for (int e = 0; e < 64; e++) {
                float4 w = *(const float4*)&s_WT[e * 196 + 4 * m4];
                float h = s_h2[n * 65 + e];
                acc.x += h * w.x; acc.y += h * w.y; acc.z += h * w.z; acc.w += h * w.w;
            }
            float* dst = (m4 < 16) ? s_q : (m4 < 32 ? s_k : s_v);
            int c4 = m4 & 15;
            ((float4*)&dst[n * 68])[c4] = acc;
        }
    }
    asm volatile("cp.async.wait_group 0;" ::: "memory");
    __syncthreads();

    // attention: 512 tasks = (head, row); float4 k/v loads; __expf
    if (tid < 512) {
        int h = tid >> 6, qi = tid & 63;
        const float inv_sqrt_d = 0.35355339059327373f;
        float4 q0 = *(const float4*)&s_q[qi * 68 + h * 8];
        float4 q1 = *(const float4*)&s_q[qi * 68 + h * 8 + 4];
        float mx = -1e30f;
        for (int k = 0; k < 64; k++) {
            float4 k0 = *(const float4*)&s_k[k * 68 + h * 8];
            float4 k1 = *(const float4*)&s_k[k * 68 + h * 8 + 4];
            float sc = q0.x * k0.x + q0.y * k0.y + q0.z * k0.z + q0.w * k0.w
                     + q1.x * k1.x + q1.y * k1.y + q1.z * k1.z + q1.w * k1.w;
            mx = fmaxf(mx, sc * inv_sqrt_d);
        }
        float denom = 0.f;
        float4 ac0 = make_float4(0.f, 0.f, 0.f, 0.f);
        float4 ac1 = make_float4(0.f, 0.f, 0.f, 0.f);
        for (int k = 0; k < 64; k++) {
            float4 k0 = *(const float4*)&s_k[k * 68 + h * 8];
            float4 k1 = *(const float4*)&s_k[k * 68 + h * 8 + 4];
            float sc = q0.x * k0.x + q0.y * k0.y + q0.z * k0.z + q0.w * k0.w
                     + q1.x * k1.x + q1.y * k1.y + q1.z * k1.z + q1.w * k1.w;
            float p = __expf(sc * inv_sqrt_d - mx);
            denom += p;
            float4 v0 = *(const float4*)&s_v[k * 68 + h * 8];
            float4 v1 = *(const float4*)&s_v[k * 68 + h * 8 + 4];
            ac0.x += p * v0.x; ac0.y += p * v0.y; ac0.z += p * v0.z; ac0.w += p * v0.w;
            ac1.x += p * v1.x; ac1.y += p * v1.y; ac1.z += p * v1.z; ac1.w += p * v1.w;
        }
        float rinv = 1.f / denom;
        __syncthreads();               // all conn reads complete; safe to overwrite
        s_ao[qi * 65 + h * 8 + 0] = ac0.x * rinv;
        s_ao[qi * 65 + h * 8 + 1] = ac0.y * rinv;
        s_ao[qi * 65 + h * 8 + 2] = ac0.z * rinv;
        s_ao[qi * 65 + h * 8 + 3] = ac0.w * rinv;
        s_ao[qi * 65 + h * 8 + 4] = ac1.x * rinv;
        s_ao[qi * 65 + h * 8 + 5] = ac1.y * rinv;
        s_ao[qi * 65 + h * 8 + 6] = ac1.z * rinv;
        s_ao[qi * 65 + h * 8 + 7] = ac1.w * rinv;
    } else {
        __syncthreads();
    }
    __syncthreads();

    // graph_features = ao @ Wop^T + bop (raw Wop in F1 region); output #2
    {
        const float4* bopv = (const float4*)bop;
        int n = tid & 63, e4 = tid >> 6;
        float4 acc = bopv[e4];
        #pragma unroll 8
        for (int f = 0; f < 64; f++) {
            float av = s_ao[n * 65 + f];
            acc.x += av * s_wopraw[(4 * e4 + 0) * 64 + f];
            acc.y += av * s_wopraw[(4 * e4 + 1) * 64 + f];
            acc.z += av * s_wopraw[(4 * e4 + 2) * 64 + f];
            acc.w += av * s_wopraw[(4 * e4 + 3) * 64 + f];
        }
        ((float4*)(out + (size_t)(B_SZ * 4096) + (size_t)b * 4096 + n * 64 + 4 * e4))[0] = acc;
    }
}

// ---------------- launch ----------------
extern "C" void kernel_launch(void* const* d_in, const int* in_sizes, int n_in,
                              void* d_out, int out_size) {
    const float* x   = (const float*)d_in[0];
    const float* EE  = (const float*)d_in[1];
    const float* w1  = (const float*)d_in[2];
    const float* b1  = (const float*)d_in[3];
    const float* w2  = (const float*)d_in[4];
    const float* b2  = (const float*)d_in[5];
    const float* Wip = (const float*)d_in[6];
    const float* bip = (const float*)d_in[7];
    const float* Wop = (const float*)d_in[8];
    const float* bop = (const float*)d_in[9];
    float* out = (float*)d_out;

    cudaFuncSetAttribute(fft_hilbert_kernel,
                         cudaFuncAttributeMaxDynamicSharedMemorySize, 65536);
    cudaFuncSetAttribute(gram_mma_kernel,
                         cudaFuncAttributeMaxDynamicSharedMemorySize, GRAM_SMEM);
    cudaFuncSetAttribute(tail_kernel,
                         cudaFuncAttributeMaxDynamicSharedMemorySize, TAIL_FLOATS * 4);

    init_kernel<<<32, 256>>>(EE, w1);
    fft_hilbert_kernel<<<B_SZ * C_SZ / 2, 512, 65536>>>(x);
    gram_mma_kernel<<<dim3(KSPLIT, B_SZ), 256, GRAM_SMEM>>>();
    tail_kernel<<<B_SZ, 1024, TAIL_FLOATS * 4>>>(EE, w1, b1, w2, b2,
                                                 Wip, bip, Wop, bop, out);
}

// round 12
// speedup vs baseline: 2.6250x; 1.0317x over previous
#include <cuda_runtime.h>
#include <cuda_bf16.h>
#include <math.h>

#define B_SZ 32
#define C_SZ 64
#define T_SZ 8192
#define KSPLIT 8
#define NCH 32               // 32-sample k-chunks per CTA (8192/8 splits/32)
#define NSTG 4
#define STG_B 16384          // per stage: hi tile 8KB + lo tile 8KB
#define GRAM_SMEM (NSTG * STG_B)

// ---------------- scratch (static device globals; no allocation) ----------------
// de-interleaved bf16 planes: [b][c][r|i][8192] (hi and lo arrays)
__device__ __nv_bfloat16 g_Zhi[(size_t)B_SZ * 64 * 2 * 8192];   // 67 MB
__device__ __nv_bfloat16 g_Zlo[(size_t)B_SZ * 64 * 2 * 8192];   // 67 MB
// partials per (split,b): rows 0-63 c_hh, 64-127 c_hl, 128-191 R=Zi.Zr^T
__device__ float  g_G2[(size_t)KSPLIT * B_SZ * 192 * 64];       // 12.6 MB
__device__ float2 g_tw[T_SZ / 2];                               // exp(-2pi i k/N)
__device__ float  g_F1[64 * 128];                               // EE @ w1 (batch-invariant)

__device__ __forceinline__ float2 cmul(float2 a, float2 b) {
    return make_float2(a.x * b.x - a.y * b.y, a.x * b.y + a.y * b.x);
}
__device__ __forceinline__ float2 cadd(float2 a, float2 b) { return make_float2(a.x + b.x, a.y + b.y); }
__device__ __forceinline__ float2 csub(float2 a, float2 b) { return make_float2(a.x - b.x, a.y - b.y); }
__device__ __forceinline__ float2 cmulc(float2 v, float cx, float cy) {
    return make_float2(v.x * cx - v.y * cy, v.x * cy + v.y * cx);
}
__device__ __forceinline__ int SW(int i) { return i ^ ((i >> 5) & 31); }

__device__ __forceinline__ unsigned smem_u32(const void* p) {
    unsigned a;
    asm("{ .reg .u64 t; cvta.to.shared.u64 t, %1; cvt.u32.u64 %0, t; }" : "=r"(a) : "l"(p));
    return a;
}
__device__ __forceinline__ void cpasync16(unsigned dst, const void* src) {
    asm volatile("cp.async.cg.shared.global [%0], [%1], 16;" :: "r"(dst), "l"(src) : "memory");
}
__device__ __forceinline__ void ldsm4(unsigned& r0, unsigned& r1, unsigned& r2, unsigned& r3,
                                      unsigned addr) {
    asm volatile("ldmatrix.sync.aligned.m8n8.x4.shared.b16 {%0,%1,%2,%3}, [%4];"
                 : "=r"(r0), "=r"(r1), "=r"(r2), "=r"(r3) : "r"(addr));
}
__device__ __forceinline__ void mma16816(float* c, unsigned a0, unsigned a1, unsigned a2,
                                         unsigned a3, unsigned b0, unsigned b1) {
    asm volatile("mma.sync.aligned.m16n8k16.row.col.f32.bf16.bf16.f32 "
                 "{%0,%1,%2,%3}, {%4,%5,%6,%7}, {%8,%9}, {%0,%1,%2,%3};"
                 : "+f"(c[0]), "+f"(c[1]), "+f"(c[2]), "+f"(c[3])
                 : "r"(a0), "r"(a1), "r"(a2), "r"(a3), "r"(b0), "r"(b1));
}

#define RC8 0.70710678118654752f
#define C16 0.92387953251128676f
#define S16 0.38268343236508977f

// ---- radix-16 forward butterfly in registers (DIF stages st..st+3) ----
__device__ __forceinline__ void fft16_fwd_regs(float2* u, float2 W1, float2 W2,
                                               float2 W4, float2 W8) {
    float2 W1k[8];
    W1k[0] = W1;
    W1k[1] = cmulc(W1,  C16, -S16);
    W1k[2] = cmulc(W1,  RC8, -RC8);
    W1k[3] = cmulc(W1,  S16, -C16);
    W1k[4] = make_float2(W1.y, -W1.x);
    W1k[5] = cmulc(W1, -S16, -C16);
    W1k[6] = cmulc(W1, -RC8, -RC8);
    W1k[7] = cmulc(W1, -C16, -S16);
    #pragma unroll
    for (int k = 0; k < 8; k++) {
        float2 sum = cadd(u[k], u[k + 8]);
        float2 dif = csub(u[k], u[k + 8]);
        u[k] = sum;
        u[k + 8] = cmul(dif, W1k[k]);
    }
    float2 W2k[4];
    W2k[0] = W2;
    W2k[1] = cmulc(W2,  RC8, -RC8);
    W2k[2] = make_float2(W2.y, -W2.x);
    W2k[3] = cmulc(W2, -RC8, -RC8);
    #pragma unroll
    for (int g = 0; g < 16; g += 8)
        #pragma unroll
        for (int k = 0; k < 4; k++) {
            float2 sum = cadd(u[g + k], u[g + k + 4]);
            float2 dif = csub(u[g + k], u[g + k + 4]);
            u[g + k] = sum;
            u[g + k + 4] = cmul(dif, W2k[k]);
        }
    float2 W4k[2] = { W4, make_float2(W4.y, -W4.x) };
    #pragma unroll
    for (int g = 0; g < 16; g += 4)
        #pragma unroll
        for (int k = 0; k < 2; k++) {
            float2 sum = cadd(u[g + k], u[g + k + 2]);
            float2 dif = csub(u[g + k], u[g + k + 2]);
            u[g + k] = sum;
            u[g + k + 2] = cmul(dif, W4k[k]);
        }
    #pragma unroll
    for (int g = 0; g < 16; g += 2) {
        float2 sum = cadd(u[g], u[g + 1]);
        float2 dif = csub(u[g], u[g + 1]);
        u[g] = sum;
        u[g + 1] = cmul(dif, W8);
    }
}

// ---- radix-16 inverse butterfly in registers (DIT stages st..st+3) ----
__device__ __forceinline__ void fft16_inv_regs(float2* u, float2 W1, float2 W2,
                                               float2 W4, float2 W8) {
    #pragma unroll
    for (int g = 0; g < 16; g += 2) {
        float2 v = cmul(u[g + 1], W1);
        float2 t = u[g];
        u[g]     = cadd(t, v);
        u[g + 1] = csub(t, v);
    }
    float2 W2k[2] = { W2, make_float2(-W2.y, W2.x) };
    #pragma unroll
    for (int g = 0; g < 16; g += 4)
        #pragma unroll
        for (int k = 0; k < 2; k++) {
            float2 v = cmul(u[g + k + 2], W2k[k]);
            float2 t = u[g + k];
            u[g + k]     = cadd(t, v);
            u[g + k + 2] = csub(t, v);
        }
    float2 W4k[4];
    W4k[0] = W4;
    W4k[1] = cmulc(W4,  RC8, RC8);
    W4k[2] = make_float2(-W4.y, W4.x);
    W4k[3] = cmulc(W4, -RC8, RC8);
    #pragma unroll
    for (int g = 0; g < 16; g += 8)
        #pragma unroll
        for (int k = 0; k < 4; k++) {
            float2 v = cmul(u[g + k + 4], W4k[k]);
            float2 t = u[g + k];
            u[g + k]     = cadd(t, v);
            u[g + k + 4] = csub(t, v);
        }
    float2 W8k[8];
    W8k[0] = W8;
    W8k[1] = cmulc(W8,  C16, S16);
    W8k[2] = cmulc(W8,  RC8, RC8);
    W8k[3] = cmulc(W8,  S16, C16);
    W8k[4] = make_float2(-W8.y, W8.x);
    W8k[5] = cmulc(W8, -S16, C16);
    W8k[6] = cmulc(W8, -RC8, RC8);
    W8k[7] = cmulc(W8, -C16, S16);
    #pragma unroll
    for (int k = 0; k < 8; k++) {
        float2 v = cmul(u[k + 8], W8k[k]);
        float2 t = u[k];
        u[k]     = cadd(t, v);
        u[k + 8] = csub(t, v);
    }
}

// ---------------- init: twiddles (blocks 0-15) + F1 = EE @ w1 (blocks 16-31) ----
__global__ void init_kernel(const float* __restrict__ EE, const float* __restrict__ w1) {
    const int blk = blockIdx.x, tid = threadIdx.x;
    if (blk < 16) {
        int i = blk * 256 + tid;
        if (i < T_SZ / 2) {
            double ang = -2.0 * 3.14159265358979323846 * (double)i / (double)T_SZ;
            g_tw[i] = make_float2((float)cos(ang), (float)sin(ang));
        }
    } else {
        #pragma unroll
        for (int v = 0; v < 2; v++) {
            int idx = (blk - 16) * 512 + v * 256 + tid;
            int r = idx >> 7, f = idx & 127;
            float acc = 0.f;
            #pragma unroll 8
            for (int e = 0; e < 64; e++) acc += EE[r * 64 + e] * w1[e * 128 + f];
            g_F1[idx] = acc;
        }
    }
}

// ---------------- FFT (pair-packed real channels), radix-16 trips ---------------
__global__ __launch_bounds__(512) void fft_hilbert_kernel(const float* __restrict__ x) {
    extern __shared__ float2 s[];   // 64 KB
    const int blk = blockIdx.x;                 // 0..1023
    const int b = blk >> 5, cp = blk & 31;
    const float* __restrict__ xa = x + ((size_t)b * C_SZ + 2 * cp) * T_SZ;
    const float* __restrict__ xb = xa + T_SZ;
    const int q = threadIdx.x;

    float2 u[16];

    // trip 0: load z + forward stages 0-3
    #pragma unroll
    for (int k = 0; k < 16; k++)
        u[k] = make_float2(xa[q + 512 * k], xb[q + 512 * k]);
    fft16_fwd_regs(u, g_tw[q], g_tw[2 * q], g_tw[4 * q], g_tw[8 * q]);
    #pragma unroll
    for (int k = 0; k < 16; k++) s[SW(q + 512 * k)] = u[k];
    __syncthreads();

    // trip 1: forward stages 4-7
    {
        const int j0 = q & 31, i = ((q >> 5) << 9) + j0;
        #pragma unroll
        for (int k = 0; k < 16; k++) u[k] = s[SW(i + 32 * k)];
        fft16_fwd_regs(u, g_tw[j0 << 4], g_tw[j0 << 5], g_tw[j0 << 6], g_tw[j0 << 7]);
        __syncthreads();
        #pragma unroll
        for (int k = 0; k < 16; k++) s[SW(i + 32 * k)] = u[k];
    }
    __syncthreads();

    // trip 2: forward stages 8-11
    {
        const int j0 = q & 1, i = ((q >> 1) << 5) + j0;
        #pragma unroll
        for (int k = 0; k < 16; k++) u[k] = s[SW(i + 2 * k)];
        fft16_fwd_regs(u, g_tw[j0 << 8], g_tw[j0 << 9], g_tw[j0 << 10], g_tw[j0 << 11]);
        __syncthreads();
        #pragma unroll
        for (int k = 0; k < 16; k++) s[SW(i + 2 * k)] = u[k];
    }
    __syncthreads();

    // mid trip: forward stage 12 + Hilbert mask + inverse stages 0-3
    {
        const int i = q * 16;
        #pragma unroll
        for (int k2 = 0; k2 < 8; k2++) {
            int t = 8 * q + k2;
            float2 a = cadd(s[SW(i + 2 * k2)], s[SW(i + 2 * k2 + 1)]);
            float2 d = csub(s[SW(i + 2 * k2)], s[SW(i + 2 * k2 + 1)]);
            if (t == 0) { u[0] = a; u[1] = d; }
            else {
                u[2 * k2]     = make_float2(2.f * a.x, 2.f * a.y);
                u[2 * k2 + 1] = make_float2(0.f, 0.f);
            }
        }
        const float2 one = make_float2(1.f, 0.f);
        fft16_inv_regs(u, one, one, one, one);
        __syncthreads();
        #pragma unroll
        for (int k = 0; k < 16; k++) s[SW(i + k)] = u[k];
    }
    __syncthreads();

    // trip 4: inverse stages 4-7
    {
        const int j0 = q & 15, i = ((q >> 4) << 8) + j0;
        #pragma unroll
        for (int k = 0; k < 16; k++) u[k] = s[SW(i + 16 * k)];
        float2 c1 = g_tw[j0 << 8], c2 = g_tw[j0 << 7];
        float2 c4 = g_tw[j0 << 6], c8 = g_tw[j0 << 5];
        fft16_inv_regs(u, make_float2(c1.x, -c1.y), make_float2(c2.x, -c2.y),
                          make_float2(c4.x, -c4.y), make_float2(c8.x, -c8.y));
        __syncthreads();
        #pragma unroll
        for (int k = 0; k < 16; k++) s[SW(i + 16 * k)] = u[k];
    }
    __syncthreads();

    // trip 5: inverse stages 8-11
    {
        const int j0 = q & 255, i = ((q >> 8) << 12) + j0;
        #pragma unroll
        for (int k = 0; k < 16; k++) u[k] = s[SW(i + 256 * k)];
        float2 c1 = g_tw[j0 << 4], c2 = g_tw[j0 << 3];
        float2 c4 = g_tw[j0 << 2], c8 = g_tw[j0 << 1];
        fft16_inv_regs(u, make_float2(c1.x, -c1.y), make_float2(c2.x, -c2.y),
                          make_float2(c4.x, -c4.y), make_float2(c8.x, -c8.y));
        __syncthreads();
        #pragma unroll
        for (int k = 0; k < 16; k++) s[SW(i + 256 * k)] = u[k];
    }
    __syncthreads();

    // final trip: inverse stage 12 + 1/N + un-pack + normalize + plane stores
    const size_t pbase0 = ((size_t)(b * C_SZ + 2 * cp)) * 16384;
    const size_t pbase1 = pbase0 + 16384;
    const float invN = 1.0f / 8192.0f;
    #pragma unroll
    for (int rr = 0; rr < 8; rr++) {
        int t = q + rr * 512;
        float2 tm = g_tw[t];
        float2 w = make_float2(tm.x, -tm.y);
        float2 uu = s[SW(t)];
        float2 v = cmul(s[SW(t + 4096)], w);
        float2 Wv[2] = { cadd(uu, v), csub(uu, v) };
        int ti[2] = { t, t + 4096 };
        #pragma unroll
        for (int e = 0; e < 2; e++) {
            int idx = ti[e];
            float Wr = Wv[e].x * invN, Wi = Wv[e].y * invN;
            float av = xa[idx], bv = xb[idx];
            float zr[2] = { av, bv };
            float zi[2] = { Wi - bv, av - Wr };
            size_t pb[2] = { pbase0, pbase1 };
            #pragma unroll
            for (int ch = 0; ch < 2; ch++) {
                float inv = rsqrtf(zr[ch] * zr[ch] + zi[ch] * zi[ch]);
                float r = zr[ch] * inv, i2 = zi[ch] * inv;
                __nv_bfloat16 rh = __float2bfloat16(r);
                __nv_bfloat16 ih = __float2bfloat16(i2);
                __nv_bfloat16 rl = __float2bfloat16(r - __bfloat162float(rh));
                __nv_bfloat16 il = __float2bfloat16(i2 - __bfloat162float(ih));
                g_Zhi[pb[ch] + idx]        = rh;
                g_Zhi[pb[ch] + 8192 + idx] = ih;
                g_Zlo[pb[ch] + idx]        = rl;
                g_Zlo[pb[ch] + 8192 + idx] = il;
            }
        }
    }
}

// ---------------- gram via HMMA, 7 exact passes ----------------------------------
// Warps 0-3 (rows 16w): c_hh = rh.rh^T + ih.ih^T (2 passes),
//                       c_hl = rh.rl^T + ih.il^T (2 passes).
// Warps 4-7 (rows 16(w-4)): R = ih.rh^T + ih.rl^T + il.rh^T (3 passes).
// Tail reconstructs: Re = c_hh + c_hl + c_hl^T, Im = R - R^T.
__global__ __launch_bounds__(256) void gram_mma_kernel() {
    extern __shared__ __align__(1024) char gsm[];
    const unsigned sbase = smem_u32(gsm);
    const int split = blockIdx.x, b = blockIdx.y;
    const int tid = threadIdx.x, lane = tid & 31, w = tid >> 5;
    const int mrow = 16 * (w & 3);
    const bool isIm = (w >= 4);

    const char* hi0 = (const char*)g_Zhi + (size_t)b * 64 * 32768 + (size_t)split * 2048;
    const char* lo0 = (const char*)g_Zlo + (size_t)b * 64 * 32768 + (size_t)split * 2048;

    unsigned swo[2]; size_t gofs[2];
    #pragma unroll
    for (int v = 0; v < 2; v++) {
        int u = v * 256 + tid;
        int rw = u >> 3, seg = u & 7;
        unsigned off = rw * 128 + seg * 16;
        swo[v] = off ^ ((off >> 3) & 0x70);
        gofs[v] = (size_t)rw * 32768 + (seg & 3) * 16 + ((seg >= 4) ? 16384 : 0);
    }

    const int lr = lane & 15, lcb = lane >> 4;
    unsigned a_off0 = (mrow + lr) * 128 + lcb * 16;
    unsigned aX = ((a_off0 >> 3) & 0x70);
    unsigned b_off0[4], bX[4];
    #pragma unroll
    for (int q = 0; q < 4; q++) {
        b_off0[q] = (16 * q + lr) * 128 + lcb * 16;
        bX[q] = ((b_off0[q] >> 3) & 0x70);
    }

    float c1[8][4] = {};   // Re warps: c_hh   | Im warps: R
    float c2[8][4] = {};   // Re warps: c_hl   | Im warps: unused

    #pragma unroll
    for (int j = 0; j < 3; j++) {
        unsigned st = sbase + j * STG_B;
        #pragma unroll
        for (int v = 0; v < 2; v++) {
            cpasync16(st + swo[v],        hi0 + gofs[v] + j * 64);
            cpasync16(st + 8192 + swo[v], lo0 + gofs[v] + j * 64);
        }
        asm volatile("cp.async.commit_group;" ::: "memory");
    }

    for (int i = 0; i < NCH; i++) {
        int jn = i + 3;
        if (jn < NCH) {
            unsigned st = sbase + (jn % NSTG) * STG_B;
            #pragma unroll
            for (int v = 0; v < 2; v++) {
                cpasync16(st + swo[v],        hi0 + gofs[v] + (size_t)jn * 64);
                cpasync16(st + 8192 + swo[v], lo0 + gofs[v] + (size_t)jn * 64);
            }
            asm volatile("cp.async.commit_group;" ::: "memory");
            asm volatile("cp.async.wait_group 3;" ::: "memory");
        } else {
            asm volatile("cp.async.wait_group 0;" ::: "memory");
        }
        __syncthreads();

        const unsigned sb = sbase + (i % NSTG) * STG_B;
        if (!isIm) {
            #pragma unroll
            for (int ks = 0; ks < 2; ks++) {
                // A fragments: rh and ih (hi plane only)
                unsigned ar0, ar1, ar2, ar3, ai0, ai1, ai2, ai3;
                ldsm4(ar0, ar1, ar2, ar3, sb + ((a_off0 + ks * 32) ^ aX));
                ldsm4(ai0, ai1, ai2, ai3, sb + ((a_off0 + 64 + ks * 32) ^ aX));
                #pragma unroll
                for (int q = 0; q < 4; q++) {
                    unsigned rh0, rh1, rh2, rh3, ih0, ih1, ih2, ih3;
                    unsigned rl0, rl1, rl2, rl3, il0, il1, il2, il3;
                    unsigned bar = sb + ((b_off0[q] + ks * 32) ^ bX[q]);
                    unsigned bai = sb + ((b_off0[q] + 64 + ks * 32) ^ bX[q]);
                    ldsm4(rh0, rh1, rh2, rh3, bar);
                    ldsm4(ih0, ih1, ih2, ih3, bai);
                    ldsm4(rl0, rl1, rl2, rl3, bar + 8192);
                    ldsm4(il0, il1, il2, il3, bai + 8192);
                    mma16816(c1[2 * q],     ar0, ar1, ar2, ar3, rh0, rh2);
                    mma16816(c1[2 * q + 1], ar0, ar1, ar2, ar3, rh1, rh3);
                    mma16816(c1[2 * q],     ai0, ai1, ai2, ai3, ih0, ih2);
                    mma16816(c1[2 * q + 1], ai0, ai1, ai2, ai3, ih1, ih3);
                    mma16816(c2[2 * q],     ar0, ar1, ar2, ar3, rl0, rl2);
                    mma16816(c2[2 * q + 1], ar0, ar1, ar2, ar3, rl1, rl3);
                    mma16816(c2[2 * q],     ai0, ai1, ai2, ai3, il0, il2);
                    mma16816(c2[2 * q + 1], ai0, ai1, ai2, ai3, il1, il3);
                }
            }
        } else {
            #pragma unroll
            for (int ks = 0; ks < 2; ks++) {
                // A fragments: ih (hi) and il (lo)
                unsigned ah0, ah1, ah2, ah3, al0, al1, al2, al3;
                unsigned aai = sb + ((a_off0 + 64 + ks * 32) ^ aX);
                ldsm4(ah0, ah1, ah2, ah3, aai);
                ldsm4(al0, al1, al2, al3, aai + 8192);
                #pragma unroll
                for (int q = 0; q < 4; q++) {
                    unsigned rh0, rh1, rh2, rh3, rl0, rl1, rl2, rl3;
                    unsigned bar = sb + ((b_off0[q] + ks * 32) ^ bX[q]);
                    ldsm4(rh0, rh1, rh2, rh3, bar);
                    ldsm4(rl0, rl1, rl2, rl3, bar + 8192);
                    mma16816(c1[2 * q],     ah0, ah1, ah2, ah3, rh0, rh2);
                    mma16816(c1[2 * q + 1], ah0, ah1, ah2, ah3, rh1, rh3);
                    mma16816(c1[2 * q],     ah0, ah1, ah2, ah3, rl0, rl2);
                    mma16816(c1[2 * q + 1], ah0, ah1, ah2, ah3, rl1, rl3);
                    mma16816(c1[2 * q],     al0, al1, al2, al3, rh0, rh2);
                    mma16816(c1[2 * q + 1], al0, al1, al2, al3, rh1, rh3);
                }
            }
        }
        __syncthreads();
    }

    float* G = g_G2 + ((size_t)(split * B_SZ + b)) * 12288;
    int rr0 = mrow + (lane >> 2);
    if (!isIm) {
        #pragma unroll
        for (int j = 0; j < 8; j++) {
            int col = 8 * j + 2 * (lane & 3);
            G[rr0 * 64 + col]              = c1[j][0];
            G[rr0 * 64 + col + 1]          = c1[j][1];
            G[(rr0 + 8) * 64 + col]        = c1[j][2];
            G[(rr0 + 8) * 64 + col + 1]    = c1[j][3];
            G[(64 + rr0) * 64 + col]       = c2[j][0];
            G[(64 + rr0) * 64 + col + 1]   = c2[j][1];
            G[(64 + rr0 + 8) * 64 + col]   = c2[j][2];
            G[(64 + rr0 + 8) * 64 + col + 1] = c2[j][3];
        }
    } else {
        #pragma unroll
        for (int j = 0; j < 8; j++) {
            int col = 8 * j + 2 * (lane & 3);
            G[(128 + rr0) * 64 + col]         = c1[j][0];
            G[(128 + rr0) * 64 + col + 1]     = c1[j][1];
            G[(128 + rr0 + 8) * 64 + col]     = c1[j][2];
            G[(128 + rr0 + 8) * 64 + col + 1] = c1[j][3];
        }
    }
}

// ---------------- tail: conn finalize + GCN + MHA. One block/batch, 1024 thr ----
// smem layout (floats): conn 0(4160) | F1 4160(8448,[64][132],prefetched) |
// wipraw 12608(12288) | h1 24896(8448) | t2 33344(4352) | h2 37696(4160) |
// q 41856(4352) | k 46208(4352) | v 50560(4352). WT[64][196] overlays h1+t2.
#define OFF_F1   4160
#define OFF_WIPR 12608
#define OFF_H1   24896
#define OFF_T2   33344
#define OFF_H2   37696
#define OFF_Q    41856
#define OFF_K    46208
#define OFF_V    50560
#define TAIL_FLOATS 54912   // 219648 bytes

__global__ __launch_bounds__(1024) void tail_kernel(
    const float* __restrict__ EE,  const float* __restrict__ w1, const float* __restrict__ b1,
    const float* __restrict__ w2,  const float* __restrict__ b2,
    const float* __restrict__ Wip, const float* __restrict__ bip,
    const float* __restrict__ Wop, const float* __restrict__ bop,
    float* __restrict__ out)
{
    extern __shared__ float sm[];
    float* s_conn = sm;
    float* s_F1   = sm + OFF_F1;
    float* s_wipr = sm + OFF_WIPR;
    float* s_h1   = sm + OFF_H1;
    float* s_t2   = sm + OFF_T2;
    float* s_h2   = sm + OFF_H2;
    float* s_q    = sm + OFF_Q;
    float* s_k    = sm + OFF_K;
    float* s_v    = sm + OFF_V;
    float* s_ao   = s_conn;                // conn dead after h2
    float* s_R    = sm + OFF_H1;           // R-sum temp during conn stage
    float* s_HL   = sm + OFF_T2;           // c_hl-sum temp during conn stage
    float* s_WT   = sm + OFF_H1;           // WipT [64][196] over h1+t2 (dead at qkv)
    const float* s_w2raw  = sm + OFF_Q;    // 8192 floats (q+k regions, prefetched)
    const float* s_wopraw = sm + OFF_F1;   // 4096 floats (F1 region, after h1)
    const int b = blockIdx.x;
    const int tid = threadIdx.x;

    // G0: prefetch F1 ([64][132] padded), w2 (contiguous), Wip raw (contiguous)
    {
        unsigned dF = smem_u32(sm + OFF_F1);
        unsigned dW2 = smem_u32(sm + OFF_Q);
        unsigned dWi = smem_u32(sm + OFF_WIPR);
        const uint4* sF = (const uint4*)g_F1;
        const uint4* s2 = (const uint4*)w2;
        const uint4* si = (const uint4*)Wip;
        #pragma unroll
        for (int v = 0; v < 2; v++) {
            int u = tid + v * 1024;
            int r = u >> 5, f4 = u & 31;
            cpasync16(dF + (r * 132 + f4 * 4) * 4, sF + u);
            cpasync16(dW2 + u * 16, s2 + u);
        }
        #pragma unroll
        for (int v = 0; v < 3; v++) {
            int u = tid + v * 1024;
            cpasync16(dWi + u * 16, si + u);
        }
        asm volatile("cp.async.commit_group;" ::: "memory");
    }

    // connectivity: Re = hh + hl + hl^T, Im = R - R^T (transposes via smem)
    float reacc[4];
    #pragma unroll
    for (int v = 0; v < 4; v++) {
        int i = tid + v * 1024;
        int r = i >> 6, cc = i & 63;
        float hh = 0.f, hl = 0.f, rs = 0.f;
        #pragma unroll
        for (int sp = 0; sp < KSPLIT; sp++) {
            const float* G = g_G2 + ((size_t)(sp * B_SZ + b)) * 12288;
            hh += G[r * 64 + cc];
            hl += G[(64 + r) * 64 + cc];
            rs += G[(128 + r) * 64 + cc];
        }
        reacc[v] = hh + hl;
        s_HL[r * 65 + cc] = hl;
        s_R[r * 65 + cc] = rs;
    }
    __syncthreads();
    #pragma unroll
    for (int v = 0; v < 4; v++) {
        int i = tid + v * 1024;
        int r = i >> 6, cc = i & 63;
        float re = reacc[v] + s_HL[cc * 65 + r];
        float im = s_R[r * 65 + cc] - s_R[cc * 65 + r];
        float val = (r == cc) ? 0.f : sqrtf(re * re + im * im) * (1.f / (float)T_SZ);
        s_conn[r * 65 + cc] = val;
        out[(size_t)b * 4096 + i] = val;
    }
    asm volatile("cp.async.wait_group 0;" ::: "memory");
    __syncthreads();

    // h1 = relu(conn @ F1 + b1), paired rows (r, r+32) share F1 loads
    {
        const float4* b1v = (const float4*)b1;
        int f4 = tid & 31, r = tid >> 5;
        float4 bb = b1v[f4];
        float4 a0 = bb, a1 = bb;
        #pragma unroll 8
        for (int j = 0; j < 64; j++) {
            float4 w = ((const float4*)&s_F1[j * 132])[f4];
            float c0 = s_conn[r * 65 + j];
            float c1v = s_conn[(r + 32) * 65 + j];
            a0.x += c0 * w.x; a0.y += c0 * w.y; a0.z += c0 * w.z; a0.w += c0 * w.w;
            a1.x += c1v * w.x; a1.y += c1v * w.y; a1.z += c1v * w.z; a1.w += c1v * w.w;
        }
        a0.x = fmaxf(a0.x, 0.f); a0.y = fmaxf(a0.y, 0.f);
        a0.z = fmaxf(a0.z, 0.f); a0.w = fmaxf(a0.w, 0.f);
        a1.x = fmaxf(a1.x, 0.f); a1.y = fmaxf(a1.y, 0.f);
        a1.z = fmaxf(a1.z, 0.f); a1.w = fmaxf(a1.w, 0.f);
        ((float4*)&s_h1[r * 132])[f4] = a0;
        ((float4*)&s_h1[(r + 32) * 132])[f4] = a1;
    }
    __syncthreads();

    // G2: prefetch Wop into F1 region (dead now)
    {
        unsigned dw = smem_u32(sm + OFF_F1);
        cpasync16(dw + tid * 16, (const uint4*)Wop + tid);
        asm volatile("cp.async.commit_group;" ::: "memory");
    }

    // t2 = h1 @ w2 (w2 from smem)
    {
        int r = tid >> 4, e4 = tid & 15;
        float4 acc = make_float4(0.f, 0.f, 0.f, 0.f);
        #pragma unroll 8
        for (int f = 0; f < 128; f++) {
            float4 w = ((const float4*)s_w2raw)[f * 16 + e4];
            float h = s_h1[r * 132 + f];
            acc.x += h * w.x; acc.y += h * w.y; acc.z += h * w.z; acc.w += h * w.w;
        }
        ((float4*)&s_t2[r * 68])[e4] = acc;
    }
    __syncthreads();

    // h2 = conn @ t2 + b2 ; output #3
    {
        const float4* b2v = (const float4*)b2;
        int r = tid >> 4, e4 = tid & 15;
        float4 acc = b2v[e4];
        #pragma unroll 8
        for (int j = 0; j < 64; j++) {
            float4 t4 = ((const float4*)&s_t2[j * 68])[e4];
            float cn = s_conn[r * 65 + j];
            acc.x += cn * t4.x; acc.y += cn * t4.y; acc.z += cn * t4.z; acc.w += cn * t4.w;
        }
        s_h2[r * 65 + 4 * e4]     = acc.x;
        s_h2[r * 65 + 4 * e4 + 1] = acc.y;
        s_h2[r * 65 + 4 * e4 + 2] = acc.z;
        s_h2[r * 65 + 4 * e4 + 3] = acc.w;
        ((float4*)(out + (size_t)(2 * B_SZ * 4096) + (size_t)b * 4096 + r * 64))[e4] = acc;
    }
    __syncthreads();

    // transpose raw Wip (smem) -> WT[e][196] over dead h1+t2 regions
    #pragma unroll
    for (int it = 0; it < 12; it++) {
        int idx = tid + it * 1024;
        int e = idx & 63, m = idx >> 6;
        s_WT[e * 196 + m] = s_wipr[m * 64 + e];
    }
    __syncthreads();

    // qkv = h2 @ WT + bip
    {
        const float4* bipv = (const float4*)bip;
        #pragma unroll
        for (int it = 0; it < 3; it++) {
            int slot = tid + it * 1024;
            int n = slot & 63, m4 = slot >> 6;
            float4 acc = bipv[m4];
            #pragma unroll 8
            for (int e = 0; e < 64; e++) {
                float4 w = *(const float4*)&s_WT[e * 196 + 4 * m4];
                float h = s_h2[n * 65 + e];
                acc.x += h * w.x; acc.y += h * w.y; acc.z += h * w.z; acc.w += h * w.w;
            }
            float* dst = (m4 < 16) ? s_q : (m4 < 32 ? s_k : s_v);
            int c4 = m4 & 15;
            ((float4*)&dst[n * 68])[c4] = acc;
        }
    }
    asm volatile("cp.async.wait_group 0;" ::: "memory");
    __syncthreads();

    // attention: 512 tasks = (head, row); float4 k/v loads; __expf
    if (tid < 512) {
        int h = tid >> 6, qi = tid & 63;
        const float inv_sqrt_d = 0.35355339059327373f;
        float4 q0 = *(const float4*)&s_q[qi * 68 + h * 8];
        float4 q1 = *(const float4*)&s_q[qi * 68 + h * 8 + 4];
        float mx = -1e30f;
        for (int k = 0; k < 64; k++) {
            float4 k0 = *(const float4*)&s_k[k * 68 + h * 8];
            float4 k1 = *(const float4*)&s_k[k * 68 + h * 8 + 4];
            float sc = q0.x * k0.x + q0.y * k0.y + q0.z * k0.z + q0.w * k0.w
                     + q1.x * k1.x + q1.y * k1.y + q1.z * k1.z + q1.w * k1.w;
            mx = fmaxf(mx, sc * inv_sqrt_d);
        }
        float denom = 0.f;
        float4 ac0 = make_float4(0.f, 0.f, 0.f, 0.f);
        float4 ac1 = make_float4(0.f, 0.f, 0.f, 0.f);
        for (int k = 0; k < 64; k++) {
            float4 k0 = *(const float4*)&s_k[k * 68 + h * 8];
            float4 k1 = *(const float4*)&s_k[k * 68 + h * 8 + 4];
            float sc = q0.x * k0.x + q0.y * k0.y + q0.z * k0.z + q0.w * k0.w
                     + q1.x * k1.x + q1.y * k1.y + q1.z * k1.z + q1.w * k1.w;
            float p = __expf(sc * inv_sqrt_d - mx);
            denom += p;
            float4 v0 = *(const float4*)&s_v[k * 68 + h * 8];
            float4 v1 = *(const float4*)&s_v[k * 68 + h * 8 + 4];
            ac0.x += p * v0.x; ac0.y += p * v0.y; ac0.z += p * v0.z; ac0.w += p * v0.w;
            ac1.x += p * v1.x; ac1.y += p * v1.y; ac1.z += p * v1.z; ac1.w += p * v1.w;
        }
        float rinv = 1.f / denom;
        __syncthreads();
        s_ao[qi * 65 + h * 8 + 0] = ac0.x * rinv;
        s_ao[qi * 65 + h * 8 + 1] = ac0.y * rinv;
        s_ao[qi * 65 + h * 8 + 2] = ac0.z * rinv;
        s_ao[qi * 65 + h * 8 + 3] = ac0.w * rinv;
        s_ao[qi * 65 + h * 8 + 4] = ac1.x * rinv;
        s_ao[qi * 65 + h * 8 + 5] = ac1.y * rinv;
        s_ao[qi * 65 + h * 8 + 6] = ac1.z * rinv;
        s_ao[qi * 65 + h * 8 + 7] = ac1.w * rinv;
    } else {
        __syncthreads();
    }
    __syncthreads();

    // graph_features = ao @ Wop^T + bop ; output #2
    {
        const float4* bopv = (const float4*)bop;
        int n = tid & 63, e4 = tid >> 6;
        float4 acc = bopv[e4];
        #pragma unroll 8
        for (int f = 0; f < 64; f++) {
            float av = s_ao[n * 65 + f];
            acc.x += av * s_wopraw[(4 * e4 + 0) * 64 + f];
            acc.y += av * s_wopraw[(4 * e4 + 1) * 64 + f];
            acc.z += av * s_wopraw[(4 * e4 + 2) * 64 + f];
            acc.w += av * s_wopraw[(4 * e4 + 3) * 64 + f];
        }
        ((float4*)(out + (size_t)(B_SZ * 4096) + (size_t)b * 4096 + n * 64 + 4 * e4))[0] = acc;
    }
}

// ---------------- launch ----------------
extern "C" void kernel_launch(void* const* d_in, const int* in_sizes, int n_in,
                              void* d_out, int out_size) {
    const float* x   = (const float*)d_in[0];
    const float* EE  = (const float*)d_in[1];
    const float* w1  = (const float*)d_in[2];
    const float* b1  = (const float*)d_in[3];
    const float* w2  = (const float*)d_in[4];
    const float* b2  = (const float*)d_in[5];
    const float* Wip = (const float*)d_in[6];
    const float* bip = (const float*)d_in[7];
    const float* Wop = (const float*)d_in[8];
    const float* bop = (const float*)d_in[9];
    float* out = (float*)d_out;

    cudaFuncSetAttribute(fft_hilbert_kernel,
                         cudaFuncAttributeMaxDynamicSharedMemorySize, 65536);
    cudaFuncSetAttribute(gram_mma_kernel,
                         cudaFuncAttributeMaxDynamicSharedMemorySize, GRAM_SMEM);
    cudaFuncSetAttribute(tail_kernel,
                         cudaFuncAttributeMaxDynamicSharedMemorySize, TAIL_FLOATS * 4);

    init_kernel<<<32, 256>>>(EE, w1);
    fft_hilbert_kernel<<<B_SZ * C_SZ / 2, 512, 65536>>>(x);
    gram_mma_kernel<<<dim3(KSPLIT, B_SZ), 256, GRAM_SMEM>>>();
    tail_kernel<<<B_SZ, 1024, TAIL_FLOATS * 4>>>(EE, w1, b1, w2, b2,
                                                 Wip, bip, Wop, bop, out);
}

// round 13
// speedup vs baseline: 2.8139x; 1.0720x over previous
#include <cuda_runtime.h>
#include <cuda_bf16.h>
#include <math.h>

#define B_SZ 32
#define C_SZ 64
#define T_SZ 8192
#define KSPLIT 8
#define NCH 32               // 32-sample k-chunks per CTA (8192/8 splits/32)
#define NSTG 4
#define STG_B 16384          // per stage: hi tile 8KB + lo tile 8KB
#define GRAM_SMEM (NSTG * STG_B)

// ---------------- scratch (static device globals; no allocation) ----------------
__device__ __nv_bfloat16 g_Zhi[(size_t)B_SZ * 64 * 2 * 8192];   // 67 MB
__device__ __nv_bfloat16 g_Zlo[(size_t)B_SZ * 64 * 2 * 8192];   // 67 MB
// partials per (split,b): rows 0-63 c_hh, 64-127 c_hl, 128-191 R=Zi.Zr^T
__device__ float  g_G2[(size_t)KSPLIT * B_SZ * 192 * 64];       // 12.6 MB
__device__ float2 g_tw[T_SZ / 2];
__device__ float  g_F1[64 * 128];                               // EE @ w1 (batch-invariant)
// tail inter-kernel scratch
__device__ float  g_conn[(size_t)B_SZ * 4096];
__device__ float  g_t2s [(size_t)B_SZ * 4096];
__device__ float  g_qs  [(size_t)B_SZ * 4096];
__device__ float  g_ks  [(size_t)B_SZ * 4096];
__device__ float  g_vs  [(size_t)B_SZ * 4096];

__device__ __forceinline__ float2 cmul(float2 a, float2 b) {
    return make_float2(a.x * b.x - a.y * b.y, a.x * b.y + a.y * b.x);
}
__device__ __forceinline__ float2 cadd(float2 a, float2 b) { return make_float2(a.x + b.x, a.y + b.y); }
__device__ __forceinline__ float2 csub(float2 a, float2 b) { return make_float2(a.x - b.x, a.y - b.y); }
__device__ __forceinline__ float2 cmulc(float2 v, float cx, float cy) {
    return make_float2(v.x * cx - v.y * cy, v.x * cy + v.y * cx);
}
__device__ __forceinline__ int SW(int i) { return i ^ ((i >> 5) & 31); }

__device__ __forceinline__ unsigned smem_u32(const void* p) {
    unsigned a;
    asm("{ .reg .u64 t; cvta.to.shared.u64 t, %1; cvt.u32.u64 %0, t; }" : "=r"(a) : "l"(p));
    return a;
}
__device__ __forceinline__ void cpasync16(unsigned dst, const void* src) {
    asm volatile("cp.async.cg.shared.global [%0], [%1], 16;" :: "r"(dst), "l"(src) : "memory");
}
__device__ __forceinline__ void ldsm4(unsigned& r0, unsigned& r1, unsigned& r2, unsigned& r3,
                                      unsigned addr) {
    asm volatile("ldmatrix.sync.aligned.m8n8.x4.shared.b16 {%0,%1,%2,%3}, [%4];"
                 : "=r"(r0), "=r"(r1), "=r"(r2), "=r"(r3) : "r"(addr));
}
__device__ __forceinline__ void mma16816(float* c, unsigned a0, unsigned a1, unsigned a2,
                                         unsigned a3, unsigned b0, unsigned b1) {
    asm volatile("mma.sync.aligned.m16n8k16.row.col.f32.bf16.bf16.f32 "
                 "{%0,%1,%2,%3}, {%4,%5,%6,%7}, {%8,%9}, {%0,%1,%2,%3};"
                 : "+f"(c[0]), "+f"(c[1]), "+f"(c[2]), "+f"(c[3])
                 : "r"(a0), "r"(a1), "r"(a2), "r"(a3), "r"(b0), "r"(b1));
}

#define RC8 0.70710678118654752f
#define C16 0.92387953251128676f
#define S16 0.38268343236508977f

// ---- radix-16 forward butterfly in registers (DIF stages st..st+3) ----
__device__ __forceinline__ void fft16_fwd_regs(float2* u, float2 W1, float2 W2,
                                               float2 W4, float2 W8) {
    float2 W1k[8];
    W1k[0] = W1;
    W1k[1] = cmulc(W1,  C16, -S16);
    W1k[2] = cmulc(W1,  RC8, -RC8);
    W1k[3] = cmulc(W1,  S16, -C16);
    W1k[4] = make_float2(W1.y, -W1.x);
    W1k[5] = cmulc(W1, -S16, -C16);
    W1k[6] = cmulc(W1, -RC8, -RC8);
    W1k[7] = cmulc(W1, -C16, -S16);
    #pragma unroll
    for (int k = 0; k < 8; k++) {
        float2 sum = cadd(u[k], u[k + 8]);
        float2 dif = csub(u[k], u[k + 8]);
        u[k] = sum;
        u[k + 8] = cmul(dif, W1k[k]);
    }
    float2 W2k[4];
    W2k[0] = W2;
    W2k[1] = cmulc(W2,  RC8, -RC8);
    W2k[2] = make_float2(W2.y, -W2.x);
    W2k[3] = cmulc(W2, -RC8, -RC8);
    #pragma unroll
    for (int g = 0; g < 16; g += 8)
        #pragma unroll
        for (int k = 0; k < 4; k++) {
            float2 sum = cadd(u[g + k], u[g + k + 4]);
            float2 dif = csub(u[g + k], u[g + k + 4]);
            u[g + k] = sum;
            u[g + k + 4] = cmul(dif, W2k[k]);
        }
    float2 W4k[2] = { W4, make_float2(W4.y, -W4.x) };
    #pragma unroll
    for (int g = 0; g < 16; g += 4)
        #pragma unroll
        for (int k = 0; k < 2; k++) {
            float2 sum = cadd(u[g + k], u[g + k + 2]);
            float2 dif = csub(u[g + k], u[g + k + 2]);
            u[g + k] = sum;
            u[g + k + 2] = cmul(dif, W4k[k]);
        }
    #pragma unroll
    for (int g = 0; g < 16; g += 2) {
        float2 sum = cadd(u[g], u[g + 1]);
        float2 dif = csub(u[g], u[g + 1]);
        u[g] = sum;
        u[g + 1] = cmul(dif, W8);
    }
}

// ---- radix-16 inverse butterfly in registers (DIT stages st..st+3) ----
__device__ __forceinline__ void fft16_inv_regs(float2* u, float2 W1, float2 W2,
                                               float2 W4, float2 W8) {
    #pragma unroll
    for (int g = 0; g < 16; g += 2) {
        float2 v = cmul(u[g + 1], W1);
        float2 t = u[g];
        u[g]     = cadd(t, v);
        u[g + 1] = csub(t, v);
    }
    float2 W2k[2] = { W2, make_float2(-W2.y, W2.x) };
    #pragma unroll
    for (int g = 0; g < 16; g += 4)
        #pragma unroll
        for (int k = 0; k < 2; k++) {
            float2 v = cmul(u[g + k + 2], W2k[k]);
            float2 t = u[g + k];
            u[g + k]     = cadd(t, v);
            u[g + k + 2] = csub(t, v);
        }
    float2 W4k[4];
    W4k[0] = W4;
    W4k[1] = cmulc(W4,  RC8, RC8);
    W4k[2] = make_float2(-W4.y, W4.x);
    W4k[3] = cmulc(W4, -RC8, RC8);
    #pragma unroll
    for (int g = 0; g < 16; g += 8)
        #pragma unroll
        for (int k = 0; k < 4; k++) {
            float2 v = cmul(u[g + k + 4], W4k[k]);
            float2 t = u[g + k];
            u[g + k]     = cadd(t, v);
            u[g + k + 4] = csub(t, v);
        }
    float2 W8k[8];
    W8k[0] = W8;
    W8k[1] = cmulc(W8,  C16, S16);
    W8k[2] = cmulc(W8,  RC8, RC8);
    W8k[3] = cmulc(W8,  S16, C16);
    W8k[4] = make_float2(-W8.y, W8.x);
    W8k[5] = cmulc(W8, -S16, C16);
    W8k[6] = cmulc(W8, -RC8, RC8);
    W8k[7] = cmulc(W8, -C16, S16);
    #pragma unroll
    for (int k = 0; k < 8; k++) {
        float2 v = cmul(u[k + 8], W8k[k]);
        float2 t = u[k];
        u[k]     = cadd(t, v);
        u[k + 8] = csub(t, v);
    }
}

// ---------------- init: twiddles (blocks 0-15) + F1 = EE @ w1 (blocks 16-31) ----
__global__ void init_kernel(const float* __restrict__ EE, const float* __restrict__ w1) {
    const int blk = blockIdx.x, tid = threadIdx.x;
    if (blk < 16) {
        int i = blk * 256 + tid;
        if (i < T_SZ / 2) {
            double ang = -2.0 * 3.14159265358979323846 * (double)i / (double)T_SZ;
            g_tw[i] = make_float2((float)cos(ang), (float)sin(ang));
        }
    } else {
        #pragma unroll
        for (int v = 0; v < 2; v++) {
            int idx = (blk - 16) * 512 + v * 256 + tid;
            int r = idx >> 7, f = idx & 127;
            float acc = 0.f;
            #pragma unroll 8
            for (int e = 0; e < 64; e++) acc += EE[r * 64 + e] * w1[e * 128 + f];
            g_F1[idx] = acc;
        }
    }
}

// ---------------- FFT (pair-packed real channels), radix-16 trips ---------------
__global__ __launch_bounds__(512) void fft_hilbert_kernel(const float* __restrict__ x) {
    extern __shared__ float2 s[];   // 64 KB
    const int blk = blockIdx.x;
    const int b = blk >> 5, cp = blk & 31;
    const float* __restrict__ xa = x + ((size_t)b * C_SZ + 2 * cp) * T_SZ;
    const float* __restrict__ xb = xa + T_SZ;
    const int q = threadIdx.x;

    float2 u[16];

    #pragma unroll
    for (int k = 0; k < 16; k++)
        u[k] = make_float2(xa[q + 512 * k], xb[q + 512 * k]);
    fft16_fwd_regs(u, g_tw[q], g_tw[2 * q], g_tw[4 * q], g_tw[8 * q]);
    #pragma unroll
    for (int k = 0; k < 16; k++) s[SW(q + 512 * k)] = u[k];
    __syncthreads();

    {
        const int j0 = q & 31, i = ((q >> 5) << 9) + j0;
        #pragma unroll
        for (int k = 0; k < 16; k++) u[k] = s[SW(i + 32 * k)];
        fft16_fwd_regs(u, g_tw[j0 << 4], g_tw[j0 << 5], g_tw[j0 << 6], g_tw[j0 << 7]);
        __syncthreads();
        #pragma unroll
        for (int k = 0; k < 16; k++) s[SW(i + 32 * k)] = u[k];
    }
    __syncthreads();

    {
        const int j0 = q & 1, i = ((q >> 1) << 5) + j0;
        #pragma unroll
        for (int k = 0; k < 16; k++) u[k] = s[SW(i + 2 * k)];
        fft16_fwd_regs(u, g_tw[j0 << 8], g_tw[j0 << 9], g_tw[j0 << 10], g_tw[j0 << 11]);
        __syncthreads();
        #pragma unroll
        for (int k = 0; k < 16; k++) s[SW(i + 2 * k)] = u[k];
    }
    __syncthreads();

    {
        const int i = q * 16;
        #pragma unroll
        for (int k2 = 0; k2 < 8; k2++) {
            int t = 8 * q + k2;
            float2 a = cadd(s[SW(i + 2 * k2)], s[SW(i + 2 * k2 + 1)]);
            float2 d = csub(s[SW(i + 2 * k2)], s[SW(i + 2 * k2 + 1)]);
            if (t == 0) { u[0] = a; u[1] = d; }
            else {
                u[2 * k2]     = make_float2(2.f * a.x, 2.f * a.y);
                u[2 * k2 + 1] = make_float2(0.f, 0.f);
            }
        }
        const float2 one = make_float2(1.f, 0.f);
        fft16_inv_regs(u, one, one, one, one);
        __syncthreads();
        #pragma unroll
        for (int k = 0; k < 16; k++) s[SW(i + k)] = u[k];
    }
    __syncthreads();

    {
        const int j0 = q & 15, i = ((q >> 4) << 8) + j0;
        #pragma unroll
        for (int k = 0; k < 16; k++) u[k] = s[SW(i + 16 * k)];
        float2 c1 = g_tw[j0 << 8], c2 = g_tw[j0 << 7];
        float2 c4 = g_tw[j0 << 6], c8 = g_tw[j0 << 5];
        fft16_inv_regs(u, make_float2(c1.x, -c1.y), make_float2(c2.x, -c2.y),
                          make_float2(c4.x, -c4.y), make_float2(c8.x, -c8.y));
        __syncthreads();
        #pragma unroll
        for (int k = 0; k < 16; k++) s[SW(i + 16 * k)] = u[k];
    }
    __syncthreads();

    {
        const int j0 = q & 255, i = ((q >> 8) << 12) + j0;
        #pragma unroll
        for (int k = 0; k < 16; k++) u[k] = s[SW(i + 256 * k)];
        float2 c1 = g_tw[j0 << 4], c2 = g_tw[j0 << 3];
        float2 c4 = g_tw[j0 << 2], c8 = g_tw[j0 << 1];
        fft16_inv_regs(u, make_float2(c1.x, -c1.y), make_float2(c2.x, -c2.y),
                          make_float2(c4.x, -c4.y), make_float2(c8.x, -c8.y));
        __syncthreads();
        #pragma unroll
        for (int k = 0; k < 16; k++) s[SW(i + 256 * k)] = u[k];
    }
    __syncthreads();

    const size_t pbase0 = ((size_t)(b * C_SZ + 2 * cp)) * 16384;
    const size_t pbase1 = pbase0 + 16384;
    const float invN = 1.0f / 8192.0f;
    #pragma unroll
    for (int rr = 0; rr < 8; rr++) {
        int t = q + rr * 512;
        float2 tm = g_tw[t];
        float2 w = make_float2(tm.x, -tm.y);
        float2 uu = s[SW(t)];
        float2 v = cmul(s[SW(t + 4096)], w);
        float2 Wv[2] = { cadd(uu, v), csub(uu, v) };
        int ti[2] = { t, t + 4096 };
        #pragma unroll
        for (int e = 0; e < 2; e++) {
            int idx = ti[e];
            float Wr = Wv[e].x * invN, Wi = Wv[e].y * invN;
            float av = xa[idx], bv = xb[idx];
            float zr[2] = { av, bv };
            float zi[2] = { Wi - bv, av - Wr };
            size_t pb[2] = { pbase0, pbase1 };
            #pragma unroll
            for (int ch = 0; ch < 2; ch++) {
                float inv = rsqrtf(zr[ch] * zr[ch] + zi[ch] * zi[ch]);
                float r = zr[ch] * inv, i2 = zi[ch] * inv;
                __nv_bfloat16 rh = __float2bfloat16(r);
                __nv_bfloat16 ih = __float2bfloat16(i2);
                __nv_bfloat16 rl = __float2bfloat16(r - __bfloat162float(rh));
                __nv_bfloat16 il = __float2bfloat16(i2 - __bfloat162float(ih));
                g_Zhi[pb[ch] + idx]        = rh;
                g_Zhi[pb[ch] + 8192 + idx] = ih;
                g_Zlo[pb[ch] + idx]        = rl;
                g_Zlo[pb[ch] + 8192 + idx] = il;
            }
        }
    }
}

// ---------------- gram via HMMA, 7 exact passes (unchanged, verified) ------------
__global__ __launch_bounds__(256) void gram_mma_kernel() {
    extern __shared__ __align__(1024) char gsm[];
    const unsigned sbase = smem_u32(gsm);
    const int split = blockIdx.x, b = blockIdx.y;
    const int tid = threadIdx.x, lane = tid & 31, w = tid >> 5;
    const int mrow = 16 * (w & 3);
    const bool isIm = (w >= 4);

    const char* hi0 = (const char*)g_Zhi + (size_t)b * 64 * 32768 + (size_t)split * 2048;
    const char* lo0 = (const char*)g_Zlo + (size_t)b * 64 * 32768 + (size_t)split * 2048;

    unsigned swo[2]; size_t gofs[2];
    #pragma unroll
    for (int v = 0; v < 2; v++) {
        int u = v * 256 + tid;
        int rw = u >> 3, seg = u & 7;
        unsigned off = rw * 128 + seg * 16;
        swo[v] = off ^ ((off >> 3) & 0x70);
        gofs[v] = (size_t)rw * 32768 + (seg & 3) * 16 + ((seg >= 4) ? 16384 : 0);
    }

    const int lr = lane & 15, lcb = lane >> 4;
    unsigned a_off0 = (mrow + lr) * 128 + lcb * 16;
    unsigned aX = ((a_off0 >> 3) & 0x70);
    unsigned b_off0[4], bX[4];
    #pragma unroll
    for (int q = 0; q < 4; q++) {
        b_off0[q] = (16 * q + lr) * 128 + lcb * 16;
        bX[q] = ((b_off0[q] >> 3) & 0x70);
    }

    float c1[8][4] = {};
    float c2[8][4] = {};

    #pragma unroll
    for (int j = 0; j < 3; j++) {
        unsigned st = sbase + j * STG_B;
        #pragma unroll
        for (int v = 0; v < 2; v++) {
            cpasync16(st + swo[v],        hi0 + gofs[v] + j * 64);
            cpasync16(st + 8192 + swo[v], lo0 + gofs[v] + j * 64);
        }
        asm volatile("cp.async.commit_group;" ::: "memory");
    }

    for (int i = 0; i < NCH; i++) {
        int jn = i + 3;
        if (jn < NCH) {
            unsigned st = sbase + (jn % NSTG) * STG_B;
            #pragma unroll
            for (int v = 0; v < 2; v++) {
                cpasync16(st + swo[v],        hi0 + gofs[v] + (size_t)jn * 64);
                cpasync16(st + 8192 + swo[v], lo0 + gofs[v] + (size_t)jn * 64);
            }
            asm volatile("cp.async.commit_group;" ::: "memory");
            asm volatile("cp.async.wait_group 3;" ::: "memory");
        } else {
            asm volatile("cp.async.wait_group 0;" ::: "memory");
        }
        __syncthreads();

        const unsigned sb = sbase + (i % NSTG) * STG_B;
        if (!isIm) {
            #pragma unroll
            for (int ks = 0; ks < 2; ks++) {
                unsigned ar0, ar1, ar2, ar3, ai0, ai1, ai2, ai3;
                ldsm4(ar0, ar1, ar2, ar3, sb + ((a_off0 + ks * 32) ^ aX));
                ldsm4(ai0, ai1, ai2, ai3, sb + ((a_off0 + 64 + ks * 32) ^ aX));
                #pragma unroll
                for (int q = 0; q < 4; q++) {
                    unsigned rh0, rh1, rh2, rh3, ih0, ih1, ih2, ih3;
                    unsigned rl0, rl1, rl2, rl3, il0, il1, il2, il3;
                    unsigned bar = sb + ((b_off0[q] + ks * 32) ^ bX[q]);
                    unsigned bai = sb + ((b_off0[q] + 64 + ks * 32) ^ bX[q]);
                    ldsm4(rh0, rh1, rh2, rh3, bar);
                    ldsm4(ih0, ih1, ih2, ih3, bai);
                    ldsm4(rl0, rl1, rl2, rl3, bar + 8192);
                    ldsm4(il0, il1, il2, il3, bai + 8192);
                    mma16816(c1[2 * q],     ar0, ar1, ar2, ar3, rh0, rh2);
                    mma16816(c1[2 * q + 1], ar0, ar1, ar2, ar3, rh1, rh3);
                    mma16816(c1[2 * q],     ai0, ai1, ai2, ai3, ih0, ih2);
                    mma16816(c1[2 * q + 1], ai0, ai1, ai2, ai3, ih1, ih3);
                    mma16816(c2[2 * q],     ar0, ar1, ar2, ar3, rl0, rl2);
                    mma16816(c2[2 * q + 1], ar0, ar1, ar2, ar3, rl1, rl3);
                    mma16816(c2[2 * q],     ai0, ai1, ai2, ai3, il0, il2);
                    mma16816(c2[2 * q + 1], ai0, ai1, ai2, ai3, il1, il3);
                }
            }
        } else {
            #pragma unroll
            for (int ks = 0; ks < 2; ks++) {
                unsigned ah0, ah1, ah2, ah3, al0, al1, al2, al3;
                unsigned aai = sb + ((a_off0 + 64 + ks * 32) ^ aX);
                ldsm4(ah0, ah1, ah2, ah3, aai);
                ldsm4(al0, al1, al2, al3, aai + 8192);
                #pragma unroll
                for (int q = 0; q < 4; q++) {
                    unsigned rh0, rh1, rh2, rh3, rl0, rl1, rl2, rl3;
                    unsigned bar = sb + ((b_off0[q] + ks * 32) ^ bX[q]);
                    ldsm4(rh0, rh1, rh2, rh3, bar);
                    ldsm4(rl0, rl1, rl2, rl3, bar + 8192);
                    mma16816(c1[2 * q],     ah0, ah1, ah2, ah3, rh0, rh2);
                    mma16816(c1[2 * q + 1], ah0, ah1, ah2, ah3, rh1, rh3);
                    mma16816(c1[2 * q],     ah0, ah1, ah2, ah3, rl0, rl2);
                    mma16816(c1[2 * q + 1], ah0, ah1, ah2, ah3, rl1, rl3);
                    mma16816(c1[2 * q],     al0, al1, al2, al3, rh0, rh2);
                    mma16816(c1[2 * q + 1], al0, al1, al2, al3, rh1, rh3);
                }
            }
        }
        __syncthreads();
    }

    float* G = g_G2 + ((size_t)(split * B_SZ + b)) * 12288;
    int rr0 = mrow + (lane >> 2);
    if (!isIm) {
        #pragma unroll
        for (int j = 0; j < 8; j++) {
            int col = 8 * j + 2 * (lane & 3);
            G[rr0 * 64 + col]              = c1[j][0];
            G[rr0 * 64 + col + 1]          = c1[j][1];
            G[(rr0 + 8) * 64 + col]        = c1[j][2];
            G[(rr0 + 8) * 64 + col + 1]    = c1[j][3];
            G[(64 + rr0) * 64 + col]       = c2[j][0];
            G[(64 + rr0) * 64 + col + 1]   = c2[j][1];
            G[(64 + rr0 + 8) * 64 + col]   = c2[j][2];
            G[(64 + rr0 + 8) * 64 + col + 1] = c2[j][3];
        }
    } else {
        #pragma unroll
        for (int j = 0; j < 8; j++) {
            int col = 8 * j + 2 * (lane & 3);
            G[(128 + rr0) * 64 + col]         = c1[j][0];
            G[(128 + rr0) * 64 + col + 1]     = c1[j][1];
            G[(128 + rr0 + 8) * 64 + col]     = c1[j][2];
            G[(128 + rr0 + 8) * 64 + col + 1] = c1[j][3];
        }
    }
}

// ================= tail, split 3 ways: grid (4, B) x 256 threads =================
// T1: conn (direct + gathered-transpose partial reads) -> h1 -> t2.
#define T1_F1 1040                 // s_conn [16][65]
#define T1_W2 (T1_F1 + 8448)       // s_F1 [64][132]
#define T1_H1 (T1_W2 + 8192)       // s_w2
#define T1_FLOATS (T1_H1 + 2112)   // s_h1 [16][132]

__global__ __launch_bounds__(256) void tail1_kernel(
    const float* __restrict__ b1, const float* __restrict__ w2, float* __restrict__ out)
{
    extern __shared__ float sm[];
    float* s_conn = sm;
    float* s_F1 = sm + T1_F1;
    float* s_w2 = sm + T1_W2;
    float* s_h1 = sm + T1_H1;
    const int g = blockIdx.x, b = blockIdx.y, tid = threadIdx.x;
    const int r0 = g * 16;

    // prefetch F1 ([64][132] padded) + w2
    {
        unsigned dF = smem_u32(sm + T1_F1), dW = smem_u32(sm + T1_W2);
        const uint4* sF = (const uint4*)g_F1;
        const uint4* s2 = (const uint4*)w2;
        #pragma unroll
        for (int v = 0; v < 8; v++) {
            int u = tid + v * 256;
            int r = u >> 5, f4 = u & 31;
            cpasync16(dF + (r * 132 + f4 * 4) * 4, sF + u);
            cpasync16(dW + u * 16, s2 + u);
        }
        asm volatile("cp.async.commit_group;" ::: "memory");
    }

    // conn: elem block (lr, 4c4..4c4+3). Re = hh+hl+hl^T, Im = R - R^T.
    {
        int lr = tid >> 4, c4 = tid & 15;
        int r = r0 + lr;
        float4 hh = make_float4(0.f, 0.f, 0.f, 0.f);
        float4 hl = make_float4(0.f, 0.f, 0.f, 0.f);
        float4 rs = make_float4(0.f, 0.f, 0.f, 0.f);
        float hlT[4] = {}, rsT[4] = {};
        #pragma unroll
        for (int sp = 0; sp < KSPLIT; sp++) {
            const float* G = g_G2 + ((size_t)(sp * B_SZ + b)) * 12288;
            float4 a = *(const float4*)&G[r * 64 + 4 * c4];
            float4 bb = *(const float4*)&G[(64 + r) * 64 + 4 * c4];
            float4 cc = *(const float4*)&G[(128 + r) * 64 + 4 * c4];
            hh.x += a.x; hh.y += a.y; hh.z += a.z; hh.w += a.w;
            hl.x += bb.x; hl.y += bb.y; hl.z += bb.z; hl.w += bb.w;
            rs.x += cc.x; rs.y += cc.y; rs.z += cc.z; rs.w += cc.w;
            #pragma unroll
            for (int j = 0; j < 4; j++) {
                int col = 4 * c4 + j;
                hlT[j] += G[(64 + col) * 64 + r];
                rsT[j] += G[(128 + col) * 64 + r];
            }
        }
        float hhv[4] = { hh.x, hh.y, hh.z, hh.w };
        float hlv[4] = { hl.x, hl.y, hl.z, hl.w };
        float rsv[4] = { rs.x, rs.y, rs.z, rs.w };
        float4 val;
        float* vp = (float*)&val;
        #pragma unroll
        for (int j = 0; j < 4; j++) {
            int col = 4 * c4 + j;
            float re = hhv[j] + hlv[j] + hlT[j];
            float im = rsv[j] - rsT[j];
            float v = (r == col) ? 0.f : sqrtf(re * re + im * im) * (1.f / (float)T_SZ);
            vp[j] = v;
            s_conn[lr * 65 + col] = v;
        }
        *(float4*)&out[(size_t)b * 4096 + r * 64 + 4 * c4] = val;
        *(float4*)&g_conn[(size_t)b * 4096 + r * 64 + 4 * c4] = val;
    }
    asm volatile("cp.async.wait_group 0;" ::: "memory");
    __syncthreads();

    // h1 = relu(conn @ F1 + b1): 512 slots, 2/thread
    {
        const float4* b1v = (const float4*)b1;
        #pragma unroll
        for (int it = 0; it < 2; it++) {
            int slot = tid + it * 256;
            int lr = slot >> 5, f4 = slot & 31;
            float4 acc = b1v[f4];
            #pragma unroll 8
            for (int j = 0; j < 64; j++) {
                float4 w = ((const float4*)&s_F1[j * 132])[f4];
                float cn = s_conn[lr * 65 + j];
                acc.x += cn * w.x; acc.y += cn * w.y; acc.z += cn * w.z; acc.w += cn * w.w;
            }
            acc.x = fmaxf(acc.x, 0.f); acc.y = fmaxf(acc.y, 0.f);
            acc.z = fmaxf(acc.z, 0.f); acc.w = fmaxf(acc.w, 0.f);
            ((float4*)&s_h1[lr * 132])[f4] = acc;
        }
    }
    __syncthreads();

    // t2 = h1 @ w2: 256 slots
    {
        int lr = tid >> 4, e4 = tid & 15;
        float4 acc = make_float4(0.f, 0.f, 0.f, 0.f);
        #pragma unroll 8
        for (int f = 0; f < 128; f++) {
            float4 w = ((const float4*)s_w2)[f * 16 + e4];
            float h = s_h1[lr * 132 + f];
            acc.x += h * w.x; acc.y += h * w.y; acc.z += h * w.z; acc.w += h * w.w;
        }
        *(float4*)&g_t2s[(size_t)b * 4096 + (r0 + lr) * 64 + 4 * e4] = acc;
    }
}

// T2: h2 = conn @ t2 + b2 (out#3) -> qkv = h2 @ Wip^T + bip -> q/k/v scratch.
#define T2_WIP 1088                 // s_conn [16][68]
#define T2_T2  (T2_WIP + 12288)     // wip raw
#define T2_H2  (T2_T2 + 4352)       // s_t2 [64][68]
#define T2_WT  (T2_H2 + 1040)       // s_h2 [16][65]
#define T2_FLOATS (T2_WT + 12544)   // WT [64][196] -> 31312 floats = 125 KB

__global__ __launch_bounds__(256) void tail2_kernel(
    const float* __restrict__ b2, const float* __restrict__ Wip,
    const float* __restrict__ bip, float* __restrict__ out)
{
    extern __shared__ float sm[];
    float* s_conn = sm;                // [16][68]
    float* s_wip  = sm + T2_WIP;
    float* s_t2   = sm + T2_T2;        // [64][68]
    float* s_h2   = sm + T2_H2;        // [16][65]
    float* s_WT   = sm + T2_WT;        // [64][196]
    const int g = blockIdx.x, b = blockIdx.y, tid = threadIdx.x;
    const int r0 = g * 16;

    // prefetch: conn rows (256 u4), t2 full (1024 u4), Wip (3072 u4)
    {
        unsigned dC = smem_u32(sm), dT = smem_u32(sm + T2_T2), dW = smem_u32(sm + T2_WIP);
        const uint4* sC = (const uint4*)(g_conn + (size_t)b * 4096 + r0 * 64);
        const uint4* sT = (const uint4*)(g_t2s + (size_t)b * 4096);
        const uint4* sW = (const uint4*)Wip;
        {
            int u = tid;                          // 0..255
            int lr = u >> 4, c4 = u & 15;
            cpasync16(dC + (lr * 68 + 4 * c4) * 4, sC + u);
        }
        #pragma unroll
        for (int v = 0; v < 4; v++) {
            int u = tid + v * 256;                // 0..1023
            int j = u >> 4, c4 = u & 15;
            cpasync16(dT + (j * 68 + 4 * c4) * 4, sT + u);
        }
        #pragma unroll
        for (int v = 0; v < 12; v++) {
            int u = tid + v * 256;                // 0..3071
            cpasync16(dW + u * 16, sW + u);
        }
        asm volatile("cp.async.commit_group;" ::: "memory");
        asm volatile("cp.async.wait_group 0;" ::: "memory");
    }
    __syncthreads();

    // h2 = conn @ t2 + b2 ; out#3
    {
        const float4* b2v = (const float4*)b2;
        int lr = tid >> 4, e4 = tid & 15;
        float4 acc = b2v[e4];
        #pragma unroll 8
        for (int j = 0; j < 64; j++) {
            float4 t4 = *(const float4*)&s_t2[j * 68 + 4 * e4];
            float cn = s_conn[lr * 68 + j];
            acc.x += cn * t4.x; acc.y += cn * t4.y; acc.z += cn * t4.z; acc.w += cn * t4.w;
        }
        s_h2[lr * 65 + 4 * e4]     = acc.x;
        s_h2[lr * 65 + 4 * e4 + 1] = acc.y;
        s_h2[lr * 65 + 4 * e4 + 2] = acc.z;
        s_h2[lr * 65 + 4 * e4 + 3] = acc.w;
        *(float4*)&out[(size_t)(2 * B_SZ * 4096) + (size_t)b * 4096 + (r0 + lr) * 64 + 4 * e4] = acc;
    }
    __syncthreads();

    // transpose Wip -> WT[e][196]
    #pragma unroll
    for (int it = 0; it < 48; it++) {
        int idx = tid + it * 256;
        int e = idx & 63, m = idx >> 6;
        s_WT[e * 196 + m] = s_wip[m * 64 + e];
    }
    __syncthreads();

    // qkv: 768 slots (16 rows x 48 m4), 3/thread
    {
        const float4* bipv = (const float4*)bip;
        #pragma unroll
        for (int it = 0; it < 3; it++) {
            int slot = tid + it * 256;
            int nl = slot & 15, m4 = slot >> 4;     // m4 0..47
            float4 acc = bipv[m4];
            #pragma unroll 8
            for (int e = 0; e < 64; e++) {
                float4 w = *(const float4*)&s_WT[e * 196 + 4 * m4];
                float h = s_h2[nl * 65 + e];
                acc.x += h * w.x; acc.y += h * w.y; acc.z += h * w.z; acc.w += h * w.w;
            }
            float* dst = (m4 < 16) ? g_qs : (m4 < 32 ? g_ks : g_vs);
            int c4 = m4 & 15;
            *(float4*)&dst[(size_t)b * 4096 + (r0 + nl) * 64 + 4 * c4] = acc;
        }
    }
}

// T3: attention (full k/v in smem) + out_proj (out#2).
#define T3_V   4352                  // s_k [64][68]
#define T3_Q   (T3_V + 4352)         // s_v [64][68]
#define T3_AO  (T3_Q + 1088)         // s_q [16][68]
#define T3_WOP (T3_AO + 1040)        // s_ao [16][65]
#define T3_FLOATS (T3_WOP + 4096)    // wop raw -> 14928 floats = 60 KB

__global__ __launch_bounds__(256) void tail3_kernel(
    const float* __restrict__ Wop, const float* __restrict__ bop, float* __restrict__ out)
{
    extern __shared__ float sm[];
    float* s_k  = sm;
    float* s_v  = sm + T3_V;
    float* s_q  = sm + T3_Q;
    float* s_ao = sm + T3_AO;
    float* s_wop = sm + T3_WOP;
    const int g = blockIdx.x, b = blockIdx.y, tid = threadIdx.x;
    const int r0 = g * 16;

    // prefetch: k, v (1024 u4 each), q rows (256 u4), wop (1024 u4)
    {
        unsigned dK = smem_u32(sm), dV = smem_u32(sm + T3_V);
        unsigned dQ = smem_u32(sm + T3_Q), dW = smem_u32(sm + T3_WOP);
        const uint4* sK = (const uint4*)(g_ks + (size_t)b * 4096);
        const uint4* sV = (const uint4*)(g_vs + (size_t)b * 4096);
        const uint4* sQ = (const uint4*)(g_qs + (size_t)b * 4096 + r0 * 64);
        const uint4* sW = (const uint4*)Wop;
        #pragma unroll
        for (int v = 0; v < 4; v++) {
            int u = tid + v * 256;
            int j = u >> 4, c4 = u & 15;
            cpasync16(dK + (j * 68 + 4 * c4) * 4, sK + u);
            cpasync16(dV + (j * 68 + 4 * c4) * 4, sV + u);
            cpasync16(dW + u * 16, sW + u);
        }
        {
            int u = tid;
            int lr = u >> 4, c4 = u & 15;
            cpasync16(dQ + (lr * 68 + 4 * c4) * 4, sQ + u);
        }
        asm volatile("cp.async.commit_group;" ::: "memory");
        asm volatile("cp.async.wait_group 0;" ::: "memory");
    }
    __syncthreads();

    // attention: 128 tasks (h, qi_local)
    if (tid < 128) {
        int h = tid >> 4, ql = tid & 15;
        const float inv_sqrt_d = 0.35355339059327373f;
        float4 q0 = *(const float4*)&s_q[ql * 68 + h * 8];
        float4 q1 = *(const float4*)&s_q[ql * 68 + h * 8 + 4];
        float mx = -1e30f;
        for (int k = 0; k < 64; k++) {
            float4 k0 = *(const float4*)&s_k[k * 68 + h * 8];
            float4 k1 = *(const float4*)&s_k[k * 68 + h * 8 + 4];
            float sc = q0.x * k0.x + q0.y * k0.y + q0.z * k0.z + q0.w * k0.w
                     + q1.x * k1.x + q1.y * k1.y + q1.z * k1.z + q1.w * k1.w;
            mx = fmaxf(mx, sc * inv_sqrt_d);
        }
        float denom = 0.f;
        float4 ac0 = make_float4(0.f, 0.f, 0.f, 0.f);
        float4 ac1 = make_float4(0.f, 0.f, 0.f, 0.f);
        for (int k = 0; k < 64; k++) {
            float4 k0 = *(const float4*)&s_k[k * 68 + h * 8];
            float4 k1 = *(const float4*)&s_k[k * 68 + h * 8 + 4];
            float sc = q0.x * k0.x + q0.y * k0.y + q0.z * k0.z + q0.w * k0.w
                     + q1.x * k1.x + q1.y * k1.y + q1.z * k1.z + q1.w * k1.w;
            float p = __expf(sc * inv_sqrt_d - mx);
            denom += p;
            float4 v0 = *(const float4*)&s_v[k * 68 + h * 8];
            float4 v1 = *(const float4*)&s_v[k * 68 + h * 8 + 4];
            ac0.x += p * v0.x; ac0.y += p * v0.y; ac0.z += p * v0.z; ac0.w += p * v0.w;
            ac1.x += p * v1.x; ac1.y += p * v1.y; ac1.z += p * v1.z; ac1.w += p * v1.w;
        }
        float rinv = 1.f / denom;
        s_ao[ql * 65 + h * 8 + 0] = ac0.x * rinv;
        s_ao[ql * 65 + h * 8 + 1] = ac0.y * rinv;
        s_ao[ql * 65 + h * 8 + 2] = ac0.z * rinv;
        s_ao[ql * 65 + h * 8 + 3] = ac0.w * rinv;
        s_ao[ql * 65 + h * 8 + 4] = ac1.x * rinv;
        s_ao[ql * 65 + h * 8 + 5] = ac1.y * rinv;
        s_ao[ql * 65 + h * 8 + 6] = ac1.z * rinv;
        s_ao[ql * 65 + h * 8 + 7] = ac1.w * rinv;
    }
    __syncthreads();

    // out#2 = ao @ Wop^T + bop: 256 slots
    {
        const float4* bopv = (const float4*)bop;
        int nl = tid >> 4, e4 = tid & 15;
        float4 acc = bopv[e4];
        #pragma unroll 8
        for (int f = 0; f < 64; f++) {
            float av = s_ao[nl * 65 + f];
            acc.x += av * s_wop[(4 * e4 + 0) * 64 + f];
            acc.y += av * s_wop[(4 * e4 + 1) * 64 + f];
            acc.z += av * s_wop[(4 * e4 + 2) * 64 + f];
            acc.w += av * s_wop[(4 * e4 + 3) * 64 + f];
        }
        *(float4*)&out[(size_t)(B_SZ * 4096) + (size_t)b * 4096 + (r0 + nl) * 64 + 4 * e4] = acc;
    }
}

// ---------------- launch ----------------
extern "C" void kernel_launch(void* const* d_in, const int* in_sizes, int n_in,
                              void* d_out, int out_size) {
    const float* x   = (const float*)d_in[0];
    const float* EE  = (const float*)d_in[1];
    const float* w1  = (const float*)d_in[2];
    const float* b1  = (const float*)d_in[3];
    const float* w2  = (const float*)d_in[4];
    const float* b2  = (const float*)d_in[5];
    const float* Wip = (const float*)d_in[6];
    const float* bip = (const float*)d_in[7];
    const float* Wop = (const float*)d_in[8];
    const float* bop = (const float*)d_in[9];
    float* out = (float*)d_out;

    cudaFuncSetAttribute(fft_hilbert_kernel,
                         cudaFuncAttributeMaxDynamicSharedMemorySize, 65536);
    cudaFuncSetAttribute(gram_mma_kernel,
                         cudaFuncAttributeMaxDynamicSharedMemorySize, GRAM_SMEM);
    cudaFuncSetAttribute(tail1_kernel,
                         cudaFuncAttributeMaxDynamicSharedMemorySize, T1_FLOATS * 4);
    cudaFuncSetAttribute(tail2_kernel,
                         cudaFuncAttributeMaxDynamicSharedMemorySize, T2_FLOATS * 4);
    cudaFuncSetAttribute(tail3_kernel,
                         cudaFuncAttributeMaxDynamicSharedMemorySize, T3_FLOATS * 4);

    init_kernel<<<32, 256>>>(EE, w1);
    fft_hilbert_kernel<<<B_SZ * C_SZ / 2, 512, 65536>>>(x);
    gram_mma_kernel<<<dim3(KSPLIT, B_SZ), 256, GRAM_SMEM>>>();
    tail1_kernel<<<dim3(4, B_SZ), 256, T1_FLOATS * 4>>>(b1, w2, out);
    tail2_kernel<<<dim3(4, B_SZ), 256, T2_FLOATS * 4>>>(b2, Wip, bip, out);
    tail3_kernel<<<dim3(4, B_SZ), 256, T3_FLOATS * 4>>>(Wop, bop, out);
}

// round 14
// speedup vs baseline: 2.9522x; 1.0492x over previous
#include <cuda_runtime.h>
#include <cuda_bf16.h>
#include <math.h>

#define B_SZ 32
#define C_SZ 64
#define T_SZ 8192
#define KSPLIT 8
#define NCH 32               // 32-sample k-chunks per CTA (8192/8 splits/32)
#define NSTG 4
#define STG_B 16384          // per stage: hi tile 8KB + lo tile 8KB
#define GRAM_SMEM (NSTG * STG_B)

// ---------------- scratch (static device globals; no allocation) ----------------
__device__ __nv_bfloat16 g_Zhi[(size_t)B_SZ * 64 * 2 * 8192];   // 67 MB
__device__ __nv_bfloat16 g_Zlo[(size_t)B_SZ * 64 * 2 * 8192];   // 67 MB
// partials per (split,b): rows 0-63 hh, 64-127 hl, 128-191 hl^T, 192-255 R, 256-319 R^T
__device__ float  g_G2[(size_t)KSPLIT * B_SZ * 320 * 64];       // 21 MB
__device__ float2 g_tw[T_SZ / 2];
__device__ float  g_F1[64 * 128];                               // EE @ w1 (batch-invariant)
// tail inter-kernel scratch
__device__ float  g_conn[(size_t)B_SZ * 4096];
__device__ float  g_t2s [(size_t)B_SZ * 4096];
__device__ float  g_qs  [(size_t)B_SZ * 4096];
__device__ float  g_ks  [(size_t)B_SZ * 4096];
__device__ float  g_vs  [(size_t)B_SZ * 4096];

__device__ __forceinline__ float2 cmul(float2 a, float2 b) {
    return make_float2(a.x * b.x - a.y * b.y, a.x * b.y + a.y * b.x);
}
__device__ __forceinline__ float2 cadd(float2 a, float2 b) { return make_float2(a.x + b.x, a.y + b.y); }
__device__ __forceinline__ float2 csub(float2 a, float2 b) { return make_float2(a.x - b.x, a.y - b.y); }
__device__ __forceinline__ float2 cmulc(float2 v, float cx, float cy) {
    return make_float2(v.x * cx - v.y * cy, v.x * cy + v.y * cx);
}
__device__ __forceinline__ int SW(int i) { return i ^ ((i >> 5) & 31); }

__device__ __forceinline__ unsigned smem_u32(const void* p) {
    unsigned a;
    asm("{ .reg .u64 t; cvta.to.shared.u64 t, %1; cvt.u32.u64 %0, t; }" : "=r"(a) : "l"(p));
    return a;
}
__device__ __forceinline__ void cpasync16(unsigned dst, const void* src) {
    asm volatile("cp.async.cg.shared.global [%0], [%1], 16;" :: "r"(dst), "l"(src) : "memory");
}
__device__ __forceinline__ void ldsm4(unsigned& r0, unsigned& r1, unsigned& r2, unsigned& r3,
                                      unsigned addr) {
    asm volatile("ldmatrix.sync.aligned.m8n8.x4.shared.b16 {%0,%1,%2,%3}, [%4];"
                 : "=r"(r0), "=r"(r1), "=r"(r2), "=r"(r3) : "r"(addr));
}
__device__ __forceinline__ void mma16816(float* c, unsigned a0, unsigned a1, unsigned a2,
                                         unsigned a3, unsigned b0, unsigned b1) {
    asm volatile("mma.sync.aligned.m16n8k16.row.col.f32.bf16.bf16.f32 "
                 "{%0,%1,%2,%3}, {%4,%5,%6,%7}, {%8,%9}, {%0,%1,%2,%3};"
                 : "+f"(c[0]), "+f"(c[1]), "+f"(c[2]), "+f"(c[3])
                 : "r"(a0), "r"(a1), "r"(a2), "r"(a3), "r"(b0), "r"(b1));
}

#define RC8 0.70710678118654752f
#define C16 0.92387953251128676f
#define S16 0.38268343236508977f

// ---- radix-16 forward butterfly in registers (DIF stages st..st+3) ----
__device__ __forceinline__ void fft16_fwd_regs(float2* u, float2 W1, float2 W2,
                                               float2 W4, float2 W8) {
    float2 W1k[8];
    W1k[0] = W1;
    W1k[1] = cmulc(W1,  C16, -S16);
    W1k[2] = cmulc(W1,  RC8, -RC8);
    W1k[3] = cmulc(W1,  S16, -C16);
    W1k[4] = make_float2(W1.y, -W1.x);
    W1k[5] = cmulc(W1, -S16, -C16);
    W1k[6] = cmulc(W1, -RC8, -RC8);
    W1k[7] = cmulc(W1, -C16, -S16);
    #pragma unroll
    for (int k = 0; k < 8; k++) {
        float2 sum = cadd(u[k], u[k + 8]);
        float2 dif = csub(u[k], u[k + 8]);
        u[k] = sum;
        u[k + 8] = cmul(dif, W1k[k]);
    }
    float2 W2k[4];
    W2k[0] = W2;
    W2k[1] = cmulc(W2,  RC8, -RC8);
    W2k[2] = make_float2(W2.y, -W2.x);
    W2k[3] = cmulc(W2, -RC8, -RC8);
    #pragma unroll
    for (int g = 0; g < 16; g += 8)
        #pragma unroll
        for (int k = 0; k < 4; k++) {
            float2 sum = cadd(u[g + k], u[g + k + 4]);
            float2 dif = csub(u[g + k], u[g + k + 4]);
            u[g + k] = sum;
            u[g + k + 4] = cmul(dif, W2k[k]);
        }
    float2 W4k[2] = { W4, make_float2(W4.y, -W4.x) };
    #pragma unroll
    for (int g = 0; g < 16; g += 4)
        #pragma unroll
        for (int k = 0; k < 2; k++) {
            float2 sum = cadd(u[g + k], u[g + k + 2]);
            float2 dif = csub(u[g + k], u[g + k + 2]);
            u[g + k] = sum;
            u[g + k + 2] = cmul(dif, W4k[k]);
        }
    #pragma unroll
    for (int g = 0; g < 16; g += 2) {
        float2 sum = cadd(u[g], u[g + 1]);
        float2 dif = csub(u[g], u[g + 1]);
        u[g] = sum;
        u[g + 1] = cmul(dif, W8);
    }
}

// ---- radix-16 inverse butterfly in registers (DIT stages st..st+3) ----
__device__ __forceinline__ void fft16_inv_regs(float2* u, float2 W1, float2 W2,
                                               float2 W4, float2 W8) {
    #pragma unroll
    for (int g = 0; g < 16; g += 2) {
        float2 v = cmul(u[g + 1], W1);
        float2 t = u[g];
        u[g]     = cadd(t, v);
        u[g + 1] = csub(t, v);
    }
    float2 W2k[2] = { W2, make_float2(-W2.y, W2.x) };
    #pragma unroll
    for (int g = 0; g < 16; g += 4)
        #pragma unroll
        for (int k = 0; k < 2; k++) {
            float2 v = cmul(u[g + k + 2], W2k[k]);
            float2 t = u[g + k];
            u[g + k]     = cadd(t, v);
            u[g + k + 2] = csub(t, v);
        }
    float2 W4k[4];
    W4k[0] = W4;
    W4k[1] = cmulc(W4,  RC8, RC8);
    W4k[2] = make_float2(-W4.y, W4.x);
    W4k[3] = cmulc(W4, -RC8, RC8);
    #pragma unroll
    for (int g = 0; g < 16; g += 8)
        #pragma unroll
        for (int k = 0; k < 4; k++) {
            float2 v = cmul(u[g + k + 4], W4k[k]);
            float2 t = u[g + k];
            u[g + k]     = cadd(t, v);
            u[g + k + 4] = csub(t, v);
        }
    float2 W8k[8];
    W8k[0] = W8;
    W8k[1] = cmulc(W8,  C16, S16);
    W8k[2] = cmulc(W8,  RC8, RC8);
    W8k[3] = cmulc(W8,  S16, C16);
    W8k[4] = make_float2(-W8.y, W8.x);
    W8k[5] = cmulc(W8, -S16, C16);
    W8k[6] = cmulc(W8, -RC8, RC8);
    W8k[7] = cmulc(W8, -C16, S16);
    #pragma unroll
    for (int k = 0; k < 8; k++) {
        float2 v = cmul(u[k + 8], W8k[k]);
        float2 t = u[k];
        u[k]     = cadd(t, v);
        u[k + 8] = csub(t, v);
    }
}

// ---------------- init: twiddles (blocks 0-15) + F1 = EE @ w1 (blocks 16-31) ----
__global__ void init_kernel(const float* __restrict__ EE, const float* __restrict__ w1) {
    const int blk = blockIdx.x, tid = threadIdx.x;
    if (blk < 16) {
        int i = blk * 256 + tid;
        if (i < T_SZ / 2) {
            double ang = -2.0 * 3.14159265358979323846 * (double)i / (double)T_SZ;
            g_tw[i] = make_float2((float)cos(ang), (float)sin(ang));
        }
    } else {
        #pragma unroll
        for (int v = 0; v < 2; v++) {
            int idx = (blk - 16) * 512 + v * 256 + tid;
            int r = idx >> 7, f = idx & 127;
            float acc = 0.f;
            #pragma unroll 8
            for (int e = 0; e < 64; e++) acc += EE[r * 64 + e] * w1[e * 128 + f];
            g_F1[idx] = acc;
        }
    }
}

// ---------------- FFT (pair-packed real channels), radix-16 trips ---------------
__global__ __launch_bounds__(512, 2) void fft_hilbert_kernel(const float* __restrict__ x) {
    extern __shared__ float2 s[];   // 64 KB
    const int blk = blockIdx.x;
    const int b = blk >> 5, cp = blk & 31;
    const float* __restrict__ xa = x + ((size_t)b * C_SZ + 2 * cp) * T_SZ;
    const float* __restrict__ xb = xa + T_SZ;
    const int q = threadIdx.x;

    float2 u[16];

    #pragma unroll
    for (int k = 0; k < 16; k++)
        u[k] = make_float2(xa[q + 512 * k], xb[q + 512 * k]);
    fft16_fwd_regs(u, g_tw[q], g_tw[2 * q], g_tw[4 * q], g_tw[8 * q]);
    #pragma unroll
    for (int k = 0; k < 16; k++) s[SW(q + 512 * k)] = u[k];
    __syncthreads();

    {
        const int j0 = q & 31, i = ((q >> 5) << 9) + j0;
        #pragma unroll
        for (int k = 0; k < 16; k++) u[k] = s[SW(i + 32 * k)];
        fft16_fwd_regs(u, g_tw[j0 << 4], g_tw[j0 << 5], g_tw[j0 << 6], g_tw[j0 << 7]);
        __syncthreads();
        #pragma unroll
        for (int k = 0; k < 16; k++) s[SW(i + 32 * k)] = u[k];
    }
    __syncthreads();

    {
        const int j0 = q & 1, i = ((q >> 1) << 5) + j0;
        #pragma unroll
        for (int k = 0; k < 16; k++) u[k] = s[SW(i + 2 * k)];
        fft16_fwd_regs(u, g_tw[j0 << 8], g_tw[j0 << 9], g_tw[j0 << 10], g_tw[j0 << 11]);
        __syncthreads();
        #pragma unroll
        for (int k = 0; k < 16; k++) s[SW(i + 2 * k)] = u[k];
    }
    __syncthreads();

    {
        const int i = q * 16;
        #pragma unroll
        for (int k2 = 0; k2 < 8; k2++) {
            int t = 8 * q + k2;
            float2 a = cadd(s[SW(i + 2 * k2)], s[SW(i + 2 * k2 + 1)]);
            float2 d = csub(s[SW(i + 2 * k2)], s[SW(i + 2 * k2 + 1)]);
            if (t == 0) { u[0] = a; u[1] = d; }
            else {
                u[2 * k2]     = make_float2(2.f * a.x, 2.f * a.y);
                u[2 * k2 + 1] = make_float2(0.f, 0.f);
            }
        }
        const float2 one = make_float2(1.f, 0.f);
        fft16_inv_regs(u, one, one, one, one);
        __syncthreads();
        #pragma unroll
        for (int k = 0; k < 16; k++) s[SW(i + k)] = u[k];
    }
    __syncthreads();

    {
        const int j0 = q & 15, i = ((q >> 4) << 8) + j0;
        #pragma unroll
        for (int k = 0; k < 16; k++) u[k] = s[SW(i + 16 * k)];
        float2 c1 = g_tw[j0 << 8], c2 = g_tw[j0 << 7];
        float2 c4 = g_tw[j0 << 6], c8 = g_tw[j0 << 5];
        fft16_inv_regs(u, make_float2(c1.x, -c1.y), make_float2(c2.x, -c2.y),
                          make_float2(c4.x, -c4.y), make_float2(c8.x, -c8.y));
        __syncthreads();
        #pragma unroll
        for (int k = 0; k < 16; k++) s[SW(i + 16 * k)] = u[k];
    }
    __syncthreads();

    {
        const int j0 = q & 255, i = ((q >> 8) << 12) + j0;
        #pragma unroll
        for (int k = 0; k < 16; k++) u[k] = s[SW(i + 256 * k)];
        float2 c1 = g_tw[j0 << 4], c2 = g_tw[j0 << 3];
        float2 c4 = g_tw[j0 << 2], c8 = g_tw[j0 << 1];
        fft16_inv_regs(u, make_float2(c1.x, -c1.y), make_float2(c2.x, -c2.y),
                          make_float2(c4.x, -c4.y), make_float2(c8.x, -c8.y));
        __syncthreads();
        #pragma unroll
        for (int k = 0; k < 16; k++) s[SW(i + 256 * k)] = u[k];
    }
    __syncthreads();

    const size_t pbase0 = ((size_t)(b * C_SZ + 2 * cp)) * 16384;
    const size_t pbase1 = pbase0 + 16384;
    const float invN = 1.0f / 8192.0f;
    #pragma unroll
    for (int rr = 0; rr < 8; rr++) {
        int t = q + rr * 512;
        float2 tm = g_tw[t];
        float2 w = make_float2(tm.x, -tm.y);
        float2 uu = s[SW(t)];
        float2 v = cmul(s[SW(t + 4096)], w);
        float2 Wv[2] = { cadd(uu, v), csub(uu, v) };
        int ti[2] = { t, t + 4096 };
        #pragma unroll
        for (int e = 0; e < 2; e++) {
            int idx = ti[e];
            float Wr = Wv[e].x * invN, Wi = Wv[e].y * invN;
            float av = xa[idx], bv = xb[idx];
            float zr[2] = { av, bv };
            float zi[2] = { Wi - bv, av - Wr };
            size_t pb[2] = { pbase0, pbase1 };
            #pragma unroll
            for (int ch = 0; ch < 2; ch++) {
                float inv = rsqrtf(zr[ch] * zr[ch] + zi[ch] * zi[ch]);
                float r = zr[ch] * inv, i2 = zi[ch] * inv;
                __nv_bfloat16 rh = __float2bfloat16(r);
                __nv_bfloat16 ih = __float2bfloat16(i2);
                __nv_bfloat16 rl = __float2bfloat16(r - __bfloat162float(rh));
                __nv_bfloat16 il = __float2bfloat16(i2 - __bfloat162float(ih));
                g_Zhi[pb[ch] + idx]        = rh;
                g_Zhi[pb[ch] + 8192 + idx] = ih;
                g_Zlo[pb[ch] + idx]        = rl;
                g_Zlo[pb[ch] + 8192 + idx] = il;
            }
        }
    }
}

// ---------------- gram via HMMA, 7 exact passes; epilogue writes transposes -----
__global__ __launch_bounds__(256) void gram_mma_kernel() {
    extern __shared__ __align__(1024) char gsm[];
    const unsigned sbase = smem_u32(gsm);
    const int split = blockIdx.x, b = blockIdx.y;
    const int tid = threadIdx.x, lane = tid & 31, w = tid >> 5;
    const int mrow = 16 * (w & 3);
    const bool isIm = (w >= 4);

    const char* hi0 = (const char*)g_Zhi + (size_t)b * 64 * 32768 + (size_t)split * 2048;
    const char* lo0 = (const char*)g_Zlo + (size_t)b * 64 * 32768 + (size_t)split * 2048;

    unsigned swo[2]; size_t gofs[2];
    #pragma unroll
    for (int v = 0; v < 2; v++) {
        int u = v * 256 + tid;
        int rw = u >> 3, seg = u & 7;
        unsigned off = rw * 128 + seg * 16;
        swo[v] = off ^ ((off >> 3) & 0x70);
        gofs[v] = (size_t)rw * 32768 + (seg & 3) * 16 + ((seg >= 4) ? 16384 : 0);
    }

    const int lr = lane & 15, lcb = lane >> 4;
    unsigned a_off0 = (mrow + lr) * 128 + lcb * 16;
    unsigned aX = ((a_off0 >> 3) & 0x70);
    unsigned b_off0[4], bX[4];
    #pragma unroll
    for (int q = 0; q < 4; q++) {
        b_off0[q] = (16 * q + lr) * 128 + lcb * 16;
        bX[q] = ((b_off0[q] >> 3) & 0x70);
    }

    float c1[8][4] = {};
    float c2[8][4] = {};

    #pragma unroll
    for (int j = 0; j < 3; j++) {
        unsigned st = sbase + j * STG_B;
        #pragma unroll
        for (int v = 0; v < 2; v++) {
            cpasync16(st + swo[v],        hi0 + gofs[v] + j * 64);
            cpasync16(st + 8192 + swo[v], lo0 + gofs[v] + j * 64);
        }
        asm volatile("cp.async.commit_group;" ::: "memory");
    }

    for (int i = 0; i < NCH; i++) {
        int jn = i + 3;
        if (jn < NCH) {
            unsigned st = sbase + (jn % NSTG) * STG_B;
            #pragma unroll
            for (int v = 0; v < 2; v++) {
                cpasync16(st + swo[v],        hi0 + gofs[v] + (size_t)jn * 64);
                cpasync16(st + 8192 + swo[v], lo0 + gofs[v] + (size_t)jn * 64);
            }
            asm volatile("cp.async.commit_group;" ::: "memory");
            asm volatile("cp.async.wait_group 3;" ::: "memory");
        } else {
            asm volatile("cp.async.wait_group 0;" ::: "memory");
        }
        __syncthreads();

        const unsigned sb = sbase + (i % NSTG) * STG_B;
        if (!isIm) {
            #pragma unroll
            for (int ks = 0; ks < 2; ks++) {
                unsigned ar0, ar1, ar2, ar3, ai0, ai1, ai2, ai3;
                ldsm4(ar0, ar1, ar2, ar3, sb + ((a_off0 + ks * 32) ^ aX));
                ldsm4(ai0, ai1, ai2, ai3, sb + ((a_off0 + 64 + ks * 32) ^ aX));
                #pragma unroll
                for (int q = 0; q < 4; q++) {
                    unsigned rh0, rh1, rh2, rh3, ih0, ih1, ih2, ih3;
                    unsigned rl0, rl1, rl2, rl3, il0, il1, il2, il3;
                    unsigned bar = sb + ((b_off0[q] + ks * 32) ^ bX[q]);
                    unsigned bai = sb + ((b_off0[q] + 64 + ks * 32) ^ bX[q]);
                    ldsm4(rh0, rh1, rh2, rh3, bar);
                    ldsm4(ih0, ih1, ih2, ih3, bai);
                    ldsm4(rl0, rl1, rl2, rl3, bar + 8192);
                    ldsm4(il0, il1, il2, il3, bai + 8192);
                    mma16816(c1[2 * q],     ar0, ar1, ar2, ar3, rh0, rh2);
                    mma16816(c1[2 * q + 1], ar0, ar1, ar2, ar3, rh1, rh3);
                    mma16816(c1[2 * q],     ai0, ai1, ai2, ai3, ih0, ih2);
                    mma16816(c1[2 * q + 1], ai0, ai1, ai2, ai3, ih1, ih3);
                    mma16816(c2[2 * q],     ar0, ar1, ar2, ar3, rl0, rl2);
                    mma16816(c2[2 * q + 1], ar0, ar1, ar2, ar3, rl1, rl3);
                    mma16816(c2[2 * q],     ai0, ai1, ai2, ai3, il0, il2);
                    mma16816(c2[2 * q + 1], ai0, ai1, ai2, ai3, il1, il3);
                }
            }
        } else {
            #pragma unroll
            for (int ks = 0; ks < 2; ks++) {
                unsigned ah0, ah1, ah2, ah3, al0, al1, al2, al3;
                unsigned aai = sb + ((a_off0 + 64 + ks * 32) ^ aX);
                ldsm4(ah0, ah1, ah2, ah3, aai);
                ldsm4(al0, al1, al2, al3, aai + 8192);
                #pragma unroll
                for (int q = 0; q < 4; q++) {
                    unsigned rh0, rh1, rh2, rh3, rl0, rl1, rl2, rl3;
                    unsigned bar = sb + ((b_off0[q] + ks * 32) ^ bX[q]);
                    ldsm4(rh0, rh1, rh2, rh3, bar);
                    ldsm4(rl0, rl1, rl2, rl3, bar + 8192);
                    mma16816(c1[2 * q],     ah0, ah1, ah2, ah3, rh0, rh2);
                    mma16816(c1[2 * q + 1], ah0, ah1, ah2, ah3, rh1, rh3);
                    mma16816(c1[2 * q],     ah0, ah1, ah2, ah3, rl0, rl2);
                    mma16816(c1[2 * q + 1], ah0, ah1, ah2, ah3, rl1, rl3);
                    mma16816(c1[2 * q],     al0, al1, al2, al3, rh0, rh2);
                    mma16816(c1[2 * q + 1], al0, al1, al2, al3, rh1, rh3);
                }
            }
        }
        __syncthreads();
    }

    float* G = g_G2 + ((size_t)(split * B_SZ + b)) * 20480;
    int rr0 = mrow + (lane >> 2);
    if (!isIm) {
        #pragma unroll
        for (int j = 0; j < 8; j++) {
            int col = 8 * j + 2 * (lane & 3);
            // hh direct
            G[rr0 * 64 + col]              = c1[j][0];
            G[rr0 * 64 + col + 1]          = c1[j][1];
            G[(rr0 + 8) * 64 + col]        = c1[j][2];
            G[(rr0 + 8) * 64 + col + 1]    = c1[j][3];
            // hl direct
            G[(64 + rr0) * 64 + col]         = c2[j][0];
            G[(64 + rr0) * 64 + col + 1]     = c2[j][1];
            G[(64 + rr0 + 8) * 64 + col]     = c2[j][2];
            G[(64 + rr0 + 8) * 64 + col + 1] = c2[j][3];
            // hl transposed
            G[(128 + col) * 64 + rr0]         = c2[j][0];
            G[(128 + col + 1) * 64 + rr0]     = c2[j][1];
            G[(128 + col) * 64 + rr0 + 8]     = c2[j][2];
            G[(128 + col + 1) * 64 + rr0 + 8] = c2[j][3];
        }
    } else {
        #pragma unroll
        for (int j = 0; j < 8; j++) {
            int col = 8 * j + 2 * (lane & 3);
            // R direct
            G[(192 + rr0) * 64 + col]         = c1[j][0];
            G[(192 + rr0) * 64 + col + 1]     = c1[j][1];
            G[(192 + rr0 + 8) * 64 + col]     = c1[j][2];
            G[(192 + rr0 + 8) * 64 + col + 1] = c1[j][3];
            // R transposed
            G[(256 + col) * 64 + rr0]         = c1[j][0];
            G[(256 + col + 1) * 64 + rr0]     = c1[j][1];
            G[(256 + col) * 64 + rr0 + 8]     = c1[j][2];
            G[(256 + col + 1) * 64 + rr0 + 8] = c1[j][3];
        }
    }
}

// ================= tail, split 3 ways: grid (4, B) x 256 threads =================
// T1: conn (all-coalesced partial reads) -> h1 -> t2.
#define T1_F1 1040                 // s_conn [16][65]
#define T1_W2 (T1_F1 + 8448)       // s_F1 [64][132]
#define T1_H1 (T1_W2 + 8192)       // s_w2
#define T1_FLOATS (T1_H1 + 2112)   // s_h1 [16][132]

__global__ __launch_bounds__(256) void tail1_kernel(
    const float* __restrict__ b1, const float* __restrict__ w2, float* __restrict__ out)
{
    extern __shared__ float sm[];
    float* s_conn = sm;
    float* s_F1 = sm + T1_F1;
    float* s_w2 = sm + T1_W2;
    float* s_h1 = sm + T1_H1;
    const int g = blockIdx.x, b = blockIdx.y, tid = threadIdx.x;
    const int r0 = g * 16;

    // prefetch F1 ([64][132] padded) + w2
    {
        unsigned dF = smem_u32(sm + T1_F1), dW = smem_u32(sm + T1_W2);
        const uint4* sF = (const uint4*)g_F1;
        const uint4* s2 = (const uint4*)w2;
        #pragma unroll
        for (int v = 0; v < 8; v++) {
            int u = tid + v * 256;
            int r = u >> 5, f4 = u & 31;
            cpasync16(dF + (r * 132 + f4 * 4) * 4, sF + u);
            cpasync16(dW + u * 16, s2 + u);
        }
        asm volatile("cp.async.commit_group;" ::: "memory");
    }

    // conn: Re = hh + hl + hl^T, Im = R - R^T. All rows coalesced from g_G2.
    {
        int lr = tid >> 4, c4 = tid & 15;
        int r = r0 + lr;
        float re4[4] = {}, im4[4] = {};
        #pragma unroll
        for (int sp = 0; sp < KSPLIT; sp++) {
            const float* G = g_G2 + ((size_t)(sp * B_SZ + b)) * 20480;
            float4 a  = *(const float4*)&G[r * 64 + 4 * c4];
            float4 bb = *(const float4*)&G[(64 + r) * 64 + 4 * c4];
            float4 tt = *(const float4*)&G[(128 + r) * 64 + 4 * c4];
            float4 rs = *(const float4*)&G[(192 + r) * 64 + 4 * c4];
            float4 rt = *(const float4*)&G[(256 + r) * 64 + 4 * c4];
            re4[0] += a.x + bb.x + tt.x;  im4[0] += rs.x - rt.x;
            re4[1] += a.y + bb.y + tt.y;  im4[1] += rs.y - rt.y;
            re4[2] += a.z + bb.z + tt.z;  im4[2] += rs.z - rt.z;
            re4[3] += a.w + bb.w + tt.w;  im4[3] += rs.w - rt.w;
        }
        float4 val;
        float* vp = (float*)&val;
        #pragma unroll
        for (int j = 0; j < 4; j++) {
            int col = 4 * c4 + j;
            float v = (r == col) ? 0.f
                    : sqrtf(re4[j] * re4[j] + im4[j] * im4[j]) * (1.f / (float)T_SZ);
            vp[j] = v;
            s_conn[lr * 65 + col] = v;
        }
        *(float4*)&out[(size_t)b * 4096 + r * 64 + 4 * c4] = val;
        *(float4*)&g_conn[(size_t)b * 4096 + r * 64 + 4 * c4] = val;
    }
    asm volatile("cp.async.wait_group 0;" ::: "memory");
    __syncthreads();

    // h1 = relu(conn @ F1 + b1): 512 slots, 2/thread
    {
        const float4* b1v = (const float4*)b1;
        #pragma unroll
        for (int it = 0; it < 2; it++) {
            int slot = tid + it * 256;
            int lr = slot >> 5, f4 = slot & 31;
            float4 acc = b1v[f4];
            #pragma unroll 8
            for (int j = 0; j < 64; j++) {
                float4 w = ((const float4*)&s_F1[j * 132])[f4];
                float cn = s_conn[lr * 65 + j];
                acc.x += cn * w.x; acc.y += cn * w.y; acc.z += cn * w.z; acc.w += cn * w.w;
            }
            acc.x = fmaxf(acc.x, 0.f); acc.y = fmaxf(acc.y, 0.f);
            acc.z = fmaxf(acc.z, 0.f); acc.w = fmaxf(acc.w, 0.f);
            ((float4*)&s_h1[lr * 132])[f4] = acc;
        }
    }
    __syncthreads();

    // t2 = h1 @ w2: 256 slots
    {
        int lr = tid >> 4, e4 = tid & 15;
        float4 acc = make_float4(0.f, 0.f, 0.f, 0.f);
        #pragma unroll 8
        for (int f = 0; f < 128; f++) {
            float4 w = ((const float4*)s_w2)[f * 16 + e4];
            float h = s_h1[lr * 132 + f];
            acc.x += h * w.x; acc.y += h * w.y; acc.z += h * w.z; acc.w += h * w.w;
        }
        *(float4*)&g_t2s[(size_t)b * 4096 + (r0 + lr) * 64 + 4 * e4] = acc;
    }
}

// T2: h2 = conn @ t2 + b2 (out#3) -> qkv = h2 @ Wip^T + bip -> q/k/v scratch.
#define T2_WIP 1088                 // s_conn [16][68]
#define T2_T2  (T2_WIP + 12288)     // wip raw
#define T2_H2  (T2_T2 + 4352)       // s_t2 [64][68]
#define T2_WT  (T2_H2 + 1040)       // s_h2 [16][65]
#define T2_FLOATS (T2_WT + 12544)   // WT [64][196]

__global__ __launch_bounds__(256) void tail2_kernel(
    const float* __restrict__ b2, const float* __restrict__ Wip,
    const float* __restrict__ bip, float* __restrict__ out)
{
    extern __shared__ float sm[];
    float* s_conn = sm;                // [16][68]
    float* s_wip  = sm + T2_WIP;
    float* s_t2   = sm + T2_T2;        // [64][68]
    float* s_h2   = sm + T2_H2;        // [16][65]
    float* s_WT   = sm + T2_WT;        // [64][196]
    const int g = blockIdx.x, b = blockIdx.y, tid = threadIdx.x;
    const int r0 = g * 16;

    {
        unsigned dC = smem_u32(sm), dT = smem_u32(sm + T2_T2), dW = smem_u32(sm + T2_WIP);
        const uint4* sC = (const uint4*)(g_conn + (size_t)b * 4096 + r0 * 64);
        const uint4* sT = (const uint4*)(g_t2s + (size_t)b * 4096);
        const uint4* sW = (const uint4*)Wip;
        {
            int u = tid;
            int lr = u >> 4, c4 = u & 15;
            cpasync16(dC + (lr * 68 + 4 * c4) * 4, sC + u);
        }
        #pragma unroll
        for (int v = 0; v < 4; v++) {
            int u = tid + v * 256;
            int j = u >> 4, c4 = u & 15;
            cpasync16(dT + (j * 68 + 4 * c4) * 4, sT + u);
        }
        #pragma unroll
        for (int v = 0; v < 12; v++) {
            int u = tid + v * 256;
            cpasync16(dW + u * 16, sW + u);
        }
        asm volatile("cp.async.commit_group;" ::: "memory");
        asm volatile("cp.async.wait_group 0;" ::: "memory");
    }
    __syncthreads();

    // h2 = conn @ t2 + b2 ; out#3
    {
        const float4* b2v = (const float4*)b2;
        int lr = tid >> 4, e4 = tid & 15;
        float4 acc = b2v[e4];
        #pragma unroll 8
        for (int j = 0; j < 64; j++) {
            float4 t4 = *(const float4*)&s_t2[j * 68 + 4 * e4];
            float cn = s_conn[lr * 68 + j];
            acc.x += cn * t4.x; acc.y += cn * t4.y; acc.z += cn * t4.z; acc.w += cn * t4.w;
        }
        s_h2[lr * 65 + 4 * e4]     = acc.x;
        s_h2[lr * 65 + 4 * e4 + 1] = acc.y;
        s_h2[lr * 65 + 4 * e4 + 2] = acc.z;
        s_h2[lr * 65 + 4 * e4 + 3] = acc.w;
        *(float4*)&out[(size_t)(2 * B_SZ * 4096) + (size_t)b * 4096 + (r0 + lr) * 64 + 4 * e4] = acc;
    }
    __syncthreads();

    // transpose Wip -> WT[e][196]
    #pragma unroll
    for (int it = 0; it < 48; it++) {
        int idx = tid + it * 256;
        int e = idx & 63, m = idx >> 6;
        s_WT[e * 196 + m] = s_wip[m * 64 + e];
    }
    __syncthreads();

    // qkv: 768 slots (16 rows x 48 m4), 3/thread
    {
        const float4* bipv = (const float4*)bip;
        #pragma unroll
        for (int it = 0; it < 3; it++) {
            int slot = tid + it * 256;
            int nl = slot & 15, m4 = slot >> 4;
            float4 acc = bipv[m4];
            #pragma unroll 8
            for (int e = 0; e < 64; e++) {
                float4 w = *(const float4*)&s_WT[e * 196 + 4 * m4];
                float h = s_h2[nl * 65 + e];
                acc.x += h * w.x; acc.y += h * w.y; acc.z += h * w.z; acc.w += h * w.w;
            }
            float* dst = (m4 < 16) ? g_qs : (m4 < 32 ? g_ks : g_vs);
            int c4 = m4 & 15;
            *(float4*)&dst[(size_t)b * 4096 + (r0 + nl) * 64 + 4 * c4] = acc;
        }
    }
}

// T3: attention (full k/v in smem) + out_proj (out#2).
#define T3_V   4352                  // s_k [64][68]
#define T3_Q   (T3_V + 4352)         // s_v [64][68]
#define T3_AO  (T3_Q + 1088)         // s_q [16][68]
#define T3_WOP (T3_AO + 1040)        // s_ao [16][65]
#define T3_FLOATS (T3_WOP + 4096)

__global__ __launch_bounds__(256) void tail3_kernel(
    const float* __restrict__ Wop, const float* __restrict__ bop, float* __restrict__ out)
{
    extern __shared__ float sm[];
    float* s_k  = sm;
    float* s_v  = sm + T3_V;
    float* s_q  = sm + T3_Q;
    float* s_ao = sm + T3_AO;
    float* s_wop = sm + T3_WOP;
    const int g = blockIdx.x, b = blockIdx.y, tid = threadIdx.x;
    const int r0 = g * 16;

    {
        unsigned dK = smem_u32(sm), dV = smem_u32(sm + T3_V);
        unsigned dQ = smem_u32(sm + T3_Q), dW = smem_u32(sm + T3_WOP);
        const uint4* sK = (const uint4*)(g_ks + (size_t)b * 4096);
        const uint4* sV = (const uint4*)(g_vs + (size_t)b * 4096);
        const uint4* sQ = (const uint4*)(g_qs + (size_t)b * 4096 + r0 * 64);
        const uint4* sW = (const uint4*)Wop;
        #pragma unroll
        for (int v = 0; v < 4; v++) {
            int u = tid + v * 256;
            int j = u >> 4, c4 = u & 15;
            cpasync16(dK + (j * 68 + 4 * c4) * 4, sK + u);
            cpasync16(dV + (j * 68 + 4 * c4) * 4, sV + u);
            cpasync16(dW + u * 16, sW + u);
        }
        {
            int u = tid;
            int lr = u >> 4, c4 = u & 15;
            cpasync16(dQ + (lr * 68 + 4 * c4) * 4, sQ + u);
        }
        asm volatile("cp.async.commit_group;" ::: "memory");
        asm volatile("cp.async.wait_group 0;" ::: "memory");
    }
    __syncthreads();

    if (tid < 128) {
        int h = tid >> 4, ql = tid & 15;
        const float inv_sqrt_d = 0.35355339059327373f;
        float4 q0 = *(const float4*)&s_q[ql * 68 + h * 8];
        float4 q1 = *(const float4*)&s_q[ql * 68 + h * 8 + 4];
        float mx = -1e30f;
        for (int k = 0; k < 64; k++) {
            float4 k0 = *(const float4*)&s_k[k * 68 + h * 8];
            float4 k1 = *(const float4*)&s_k[k * 68 + h * 8 + 4];
            float sc = q0.x * k0.x + q0.y * k0.y + q0.z * k0.z + q0.w * k0.w
                     + q1.x * k1.x + q1.y * k1.y + q1.z * k1.z + q1.w * k1.w;
            mx = fmaxf(mx, sc * inv_sqrt_d);
        }
        float denom = 0.f;
        float4 ac0 = make_float4(0.f, 0.f, 0.f, 0.f);
        float4 ac1 = make_float4(0.f, 0.f, 0.f, 0.f);
        for (int k = 0; k < 64; k++) {
            float4 k0 = *(const float4*)&s_k[k * 68 + h * 8];
            float4 k1 = *(const float4*)&s_k[k * 68 + h * 8 + 4];
            float sc = q0.x * k0.x + q0.y * k0.y + q0.z * k0.z + q0.w * k0.w
                     + q1.x * k1.x + q1.y * k1.y + q1.z * k1.z + q1.w * k1.w;
            float p = __expf(sc * inv_sqrt_d - mx);
            denom += p;
            float4 v0 = *(const float4*)&s_v[k * 68 + h * 8];
            float4 v1 = *(const float4*)&s_v[k * 68 + h * 8 + 4];
            ac0.x += p * v0.x; ac0.y += p * v0.y; ac0.z += p * v0.z; ac0.w += p * v0.w;
            ac1.x += p * v1.x; ac1.y += p * v1.y; ac1.z += p * v1.z; ac1.w += p * v1.w;
        }
        float rinv = 1.f / denom;
        s_ao[ql * 65 + h * 8 + 0] = ac0.x * rinv;
        s_ao[ql * 65 + h * 8 + 1] = ac0.y * rinv;
        s_ao[ql * 65 + h * 8 + 2] = ac0.z * rinv;
        s_ao[ql * 65 + h * 8 + 3] = ac0.w * rinv;
        s_ao[ql * 65 + h * 8 + 4] = ac1.x * rinv;
        s_ao[ql * 65 + h * 8 + 5] = ac1.y * rinv;
        s_ao[ql * 65 + h * 8 + 6] = ac1.z * rinv;
        s_ao[ql * 65 + h * 8 + 7] = ac1.w * rinv;
    }
    __syncthreads();

    {
        const float4* bopv = (const float4*)bop;
        int nl = tid >> 4, e4 = tid & 15;
        float4 acc = bopv[e4];
        #pragma unroll 8
        for (int f = 0; f < 64; f++) {
            float av = s_ao[nl * 65 + f];
            acc.x += av * s_wop[(4 * e4 + 0) * 64 + f];
            acc.y += av * s_wop[(4 * e4 + 1) * 64 + f];
            acc.z += av * s_wop[(4 * e4 + 2) * 64 + f];
            acc.w += av * s_wop[(4 * e4 + 3) * 64 + f];
        }
        *(float4*)&out[(size_t)(B_SZ * 4096) + (size_t)b * 4096 + (r0 + nl) * 64 + 4 * e4] = acc;
    }
}

// ---------------- launch ----------------
extern "C" void kernel_launch(void* const* d_in, const int* in_sizes, int n_in,
                              void* d_out, int out_size) {
    const float* x   = (const float*)d_in[0];
    const float* EE  = (const float*)d_in[1];
    const float* w1  = (const float*)d_in[2];
    const float* b1  = (const float*)d_in[3];
    const float* w2  = (const float*)d_in[4];
    const float* b2  = (const float*)d_in[5];
    const float* Wip = (const float*)d_in[6];
    const float* bip = (const float*)d_in[7];
    const float* Wop = (const float*)d_in[8];
    const float* bop = (const float*)d_in[9];
    float* out = (float*)d_out;

    cudaFuncSetAttribute(fft_hilbert_kernel,
                         cudaFuncAttributeMaxDynamicSharedMemorySize, 65536);
    cudaFuncSetAttribute(gram_mma_kernel,
                         cudaFuncAttributeMaxDynamicSharedMemorySize, GRAM_SMEM);
    cudaFuncSetAttribute(tail1_kernel,
                         cudaFuncAttributeMaxDynamicSharedMemorySize, T1_FLOATS * 4);
    cudaFuncSetAttribute(tail2_kernel,
                         cudaFuncAttributeMaxDynamicSharedMemorySize, T2_FLOATS * 4);
    cudaFuncSetAttribute(tail3_kernel,
                         cudaFuncAttributeMaxDynamicSharedMemorySize, T3_FLOATS * 4);

    init_kernel<<<32, 256>>>(EE, w1);
    fft_hilbert_kernel<<<B_SZ * C_SZ / 2, 512, 65536>>>(x);
    gram_mma_kernel<<<dim3(KSPLIT, B_SZ), 256, GRAM_SMEM>>>();
    tail1_kernel<<<dim3(4, B_SZ), 256, T1_FLOATS * 4>>>(b1, w2, out);
    tail2_kernel<<<dim3(4, B_SZ), 256, T2_FLOATS * 4>>>(b2, Wip, bip, out);
    tail3_kernel<<<dim3(4, B_SZ), 256, T3_FLOATS * 4>>>(Wop, bop, out);
}